// round 10
// baseline (speedup 1.0000x reference)
#include <cuda_runtime.h>
#include <stdint.h>
#include <math.h>

#define BB 4
#define NN 32768
#define HH 256
#define SS 64

#define XP 268   // xs row pad (floats)
#define WP 268   // sq_w row pad
#define LP 72    // logits/W tile row pad
#define SP 268   // st2 row pad (KC)
#define AP 68    // W tile row pad (KC)
#define MP 268   // middle-gemm row pad

// ---------------- scratch (static device allocations only) ----------------
__device__ float g_W[(size_t)BB * NN * SS];          // 32 MB soft-assignment weights
__device__ float g_part[(size_t)256 * 16384];        // 16.8MB pooling partials
__device__ float g_st[BB * SS * HH];
__device__ float g_stg[BB * SS * HH];                // gated st
__device__ float g_qkv[BB * SS * 3 * HH];
__device__ float g_ao[BB * SS * HH];
__device__ float g_pro[BB * SS * HH];                // attn out-proj (pre-LN)
__device__ float g_st1[BB * SS * HH];
__device__ float g_h[BB * SS * 4 * HH];
__device__ float g_f2p[4][BB * SS * HH];             // ffn2 k-split partials
__device__ float g_st2[BB * SS * HH];

// ---- m16n8k8 tf32 mma helper --------------------------------------------
__device__ __forceinline__ void mma_tf32(float c[4], uint32_t a0, uint32_t a1,
                                         uint32_t a2, uint32_t a3, uint32_t b0,
                                         uint32_t b1) {
  asm volatile(
      "mma.sync.aligned.m16n8k8.row.col.f32.tf32.tf32.f32 "
      "{%0,%1,%2,%3}, {%4,%5,%6,%7}, {%8,%9}, {%0,%1,%2,%3};\n"
      : "+f"(c[0]), "+f"(c[1]), "+f"(c[2]), "+f"(c[3])
      : "r"(a0), "r"(a1), "r"(a2), "r"(a3), "r"(b0), "r"(b1));
}
#define F2U __float_as_uint

// ===========================================================================
// KA: fused logits + softmax + pooling. 512 threads, grid (64, B).
// 512 tokens per block in 8 tiles of 64. x staging double-buffered via regs.
// ===========================================================================
__global__ __launch_bounds__(512, 1) void k_assign_pool(
    const float* __restrict__ x, const float* __restrict__ sq_w,
    const float* __restrict__ sq_b) {
  extern __shared__ float sm[];
  float* xs = sm;                 // [64][XP]
  float* ws = sm + 64 * XP;       // [64][WP]
  float* lg = ws + 64 * WP;       // [64][LP]
  float* sb = lg + 64 * LP;       // [64]

  const int tid = threadIdx.x;
  const int b = blockIdx.y;
  const size_t tok0 = (size_t)blockIdx.x * 512;
  const float* xb = x + (size_t)b * NN * HH;

  for (int i = tid * 4; i < 16384; i += 2048) {
    float4 v = *(const float4*)(sq_w + i);
    *(float4*)(ws + (i >> 8) * WP + (i & 255)) = v;
  }
  if (tid < 64) sb[tid] = sq_b[tid];

  const int wid = tid >> 5, lane = tid & 31;
  const int r = lane >> 2, q = lane & 3;
  const int mA = (wid & 3) * 16;   // phase-A m-tile
  const int wn = wid >> 2;         // phase-A n-quarter (0..3)
  const int hb = wid * 16;         // pooling h tile

  float stacc[8][4];
#pragma unroll
  for (int j = 0; j < 8; j++)
#pragma unroll
    for (int k = 0; k < 4; k++) stacc[j][k] = 0.f;

  // prefetch tile 0 into registers
  float4 pf[8];
  {
    const float* xsrc = xb + tok0 * 256;
#pragma unroll
    for (int it = 0; it < 8; it++)
      pf[it] = *(const float4*)(xsrc + tid * 4 + it * 2048);
  }

  for (int tile = 0; tile < 8; tile++) {
    __syncthreads();  // previous tile's xs/lg consumers done
#pragma unroll
    for (int it = 0; it < 8; it++) {
      const int i = tid * 4 + it * 2048;
      *(float4*)(xs + (i >> 8) * XP + (i & 255)) = pf[it];
    }
    __syncthreads();
    if (tile < 7) {  // issue next tile's loads; overlap with compute below
      const float* xsrc = xb + (tok0 + (tile + 1) * 64) * 256;
#pragma unroll
      for (int it = 0; it < 8; it++)
        pf[it] = *(const float4*)(xsrc + tid * 4 + it * 2048);
    }

    // ---- phase A: logits, full K=256, 2 n-tiles per warp ----
    float lacc[2][4];
#pragma unroll
    for (int j = 0; j < 2; j++)
#pragma unroll
      for (int k = 0; k < 4; k++) lacc[j][k] = 0.f;

    for (int ks = 0; ks < 32; ks++) {
      const int k0 = ks * 8;
      uint32_t a0 = F2U(xs[(mA + r) * XP + k0 + q]);
      uint32_t a1 = F2U(xs[(mA + r + 8) * XP + k0 + q]);
      uint32_t a2 = F2U(xs[(mA + r) * XP + k0 + q + 4]);
      uint32_t a3 = F2U(xs[(mA + r + 8) * XP + k0 + q + 4]);
#pragma unroll
      for (int j = 0; j < 2; j++) {
        const int nt = wn * 2 + j;
        uint32_t b0 = F2U(ws[(nt * 8 + r) * WP + k0 + q]);
        uint32_t b1 = F2U(ws[(nt * 8 + r) * WP + k0 + q + 4]);
        mma_tf32(lacc[j], a0, a1, a2, a3, b0, b1);
      }
    }
#pragma unroll
    for (int j = 0; j < 2; j++) {
      const int nt = wn * 2 + j;
      lg[(mA + r) * LP + nt * 8 + 2 * q] = lacc[j][0];
      lg[(mA + r) * LP + nt * 8 + 2 * q + 1] = lacc[j][1];
      lg[(mA + r + 8) * LP + nt * 8 + 2 * q] = lacc[j][2];
      lg[(mA + r + 8) * LP + nt * 8 + 2 * q + 1] = lacc[j][3];
    }
    __syncthreads();

    // ---- softmax: 8 threads per row ----
    {
      const int t = tid >> 3, qq = tid & 7;
      float v[8];
      float mx = -1e30f;
#pragma unroll
      for (int i = 0; i < 8; i++) {
        v[i] = lg[t * LP + qq * 8 + i] + sb[qq * 8 + i];
        mx = fmaxf(mx, v[i]);
      }
      mx = fmaxf(mx, __shfl_xor_sync(0xffffffffu, mx, 1));
      mx = fmaxf(mx, __shfl_xor_sync(0xffffffffu, mx, 2));
      mx = fmaxf(mx, __shfl_xor_sync(0xffffffffu, mx, 4));
      float s = 0.f;
#pragma unroll
      for (int i = 0; i < 8; i++) {
        v[i] = __expf(v[i] - mx);
        s += v[i];
      }
      s += __shfl_xor_sync(0xffffffffu, s, 1);
      s += __shfl_xor_sync(0xffffffffu, s, 2);
      s += __shfl_xor_sync(0xffffffffu, s, 4);
      const float inv = 1.f / s;
      const size_t wrow =
          ((size_t)b * NN + tok0 + tile * 64 + t) * 64 + qq * 8;
#pragma unroll
      for (int i = 0; i < 8; i++) {
        float w = v[i] * inv;
        lg[t * LP + qq * 8 + i] = w;
        g_W[wrow + i] = w;
      }
    }
    __syncthreads();

    // ---- pooling: st^T[h][s] += x^T @ Wtile, warp = 16 h rows ----
    for (int ks = 0; ks < 8; ks++) {
      const int k0 = ks * 8;
      uint32_t a0 = F2U(xs[(k0 + q) * XP + hb + r]);
      uint32_t a1 = F2U(xs[(k0 + q) * XP + hb + r + 8]);
      uint32_t a2 = F2U(xs[(k0 + q + 4) * XP + hb + r]);
      uint32_t a3 = F2U(xs[(k0 + q + 4) * XP + hb + r + 8]);
#pragma unroll
      for (int nt = 0; nt < 8; nt++) {
        uint32_t b0 = F2U(lg[(k0 + q) * LP + nt * 8 + r]);
        uint32_t b1 = F2U(lg[(k0 + q + 4) * LP + nt * 8 + r]);
        mma_tf32(stacc[nt], a0, a1, a2, a3, b0, b1);
      }
    }
  }

  float* pp = g_part + (size_t)(b * 64 + blockIdx.x) * 16384;
#pragma unroll
  for (int nt = 0; nt < 8; nt++) {
    const int h0 = hb + r;
    const int s0 = nt * 8 + 2 * q;
    *(float2*)(pp + h0 * 64 + s0) = make_float2(stacc[nt][0], stacc[nt][1]);
    *(float2*)(pp + (h0 + 8) * 64 + s0) = make_float2(stacc[nt][2], stacc[nt][3]);
  }
}

// ===========================================================================
// reduce pooling partials (64 per batch) -> g_st
// ===========================================================================
__global__ __launch_bounds__(256) void k_reduce_st() {
  const int gt = blockIdx.x * 256 + threadIdx.x;  // 0..16383
  const int bb = gt >> 12;
  const int p4 = (gt & 4095) * 4;
  const float* p = g_part + (size_t)bb * 64 * 16384 + p4;
  float4 acc = make_float4(0.f, 0.f, 0.f, 0.f);
#pragma unroll 8
  for (int j = 0; j < 64; j++) {
    float4 v = *(const float4*)(p + (size_t)j * 16384);
    acc.x += v.x; acc.y += v.y; acc.z += v.z; acc.w += v.w;
  }
  const int h = p4 >> 6, s0 = p4 & 63;
  float* dst = g_st + bb * 16384 + h;
  dst[(s0 + 0) * 256] = acc.x;
  dst[(s0 + 1) * 256] = acc.y;
  dst[(s0 + 2) * 256] = acc.z;
  dst[(s0 + 3) * 256] = acc.w;
}

// ===========================================================================
// Middle GEMM via tf32 mma. 256 threads (8 warps = 4 m-tiles x 2 n-tiles),
// 16 output cols per block -> many small blocks, 2 blocks/SM co-residency.
// smem: As[64][MP] + ws[16][MP] = 85.8KB.
// ===========================================================================
#define MIDQ_SMEM ((64 * MP + 16 * MP) * 4)

__device__ __forceinline__ void stage_mid(float* As, float* ws,
                                          const float* asrc, int lds,
                                          const float* w, int ldw, int c0,
                                          int koff, int tid) {
  for (int i = tid * 4; i < 16384; i += 1024) {
    float4 v = *(const float4*)(asrc + (i >> 8) * lds + (i & 255));
    *(float4*)(As + (i >> 8) * MP + (i & 255)) = v;
  }
  for (int i = tid * 4; i < 4096; i += 1024) {
    int cl = i >> 8, k = i & 255;
    float4 v = *(const float4*)(w + (size_t)(c0 + cl) * ldw + koff + k);
    *(float4*)(ws + cl * MP + k) = v;
  }
}

__device__ __forceinline__ void mid_mma(const float* __restrict__ As,
                                        const float* __restrict__ ws,
                                        float c[4], int mA, int nq, int r,
                                        int q) {
#pragma unroll 4
  for (int ks = 0; ks < 32; ks++) {
    const int k0 = ks * 8;
    uint32_t a0 = F2U(As[(mA + r) * MP + k0 + q]);
    uint32_t a1 = F2U(As[(mA + r + 8) * MP + k0 + q]);
    uint32_t a2 = F2U(As[(mA + r) * MP + k0 + q + 4]);
    uint32_t a3 = F2U(As[(mA + r + 8) * MP + k0 + q + 4]);
    uint32_t b0 = F2U(ws[(nq * 8 + r) * MP + k0 + q]);
    uint32_t b1 = F2U(ws[(nq * 8 + r) * MP + k0 + q + 4]);
    mma_tf32(c, a0, a1, a2, a3, b0, b1);
  }
}

// thread->output mapping shared by all middle kernels (16 cols per block)
#define MID_PROLOG                                     \
  const int tid = threadIdx.x;                         \
  const int b = blockIdx.y;                            \
  const int c0 = blockIdx.x * 16;                      \
  const int wid = tid >> 5, lane = tid & 31;           \
  const int r = lane >> 2, q = lane & 3;               \
  const int mA = (wid & 3) * 16, nq = wid >> 2;        \
  const int cg = c0 + nq * 8 + 2 * q;                  \
  const int row0 = mA + r, row1 = mA + r + 8;

// gate: st_gated = st + sigmoid(st @ gw^T + gb) * estate
__global__ __launch_bounds__(256) void k_gate(
    const float* __restrict__ gw, const float* __restrict__ gb,
    const float* __restrict__ estate) {
  extern __shared__ float smm[];
  float* As = smm;
  float* ws = smm + 64 * MP;
  MID_PROLOG
  stage_mid(As, ws, g_st + b * 16384, 256, gw, 256, c0, 0, tid);
  float b0v = gb[cg], b1v = gb[cg + 1];
  float c[4] = {b0v, b1v, b0v, b1v};
  __syncthreads();
  mid_mma(As, ws, c, mA, nq, r, q);
  float s0 = 1.f / (1.f + __expf(-c[0]));
  float s1 = 1.f / (1.f + __expf(-c[1]));
  float s2 = 1.f / (1.f + __expf(-c[2]));
  float s3 = 1.f / (1.f + __expf(-c[3]));
  g_stg[b * 16384 + row0 * 256 + cg] = As[row0 * MP + cg] + s0 * estate[row0 * 256 + cg];
  g_stg[b * 16384 + row0 * 256 + cg + 1] = As[row0 * MP + cg + 1] + s1 * estate[row0 * 256 + cg + 1];
  g_stg[b * 16384 + row1 * 256 + cg] = As[row1 * MP + cg] + s2 * estate[row1 * 256 + cg];
  g_stg[b * 16384 + row1 * 256 + cg + 1] = As[row1 * MP + cg + 1] + s3 * estate[row1 * 256 + cg + 1];
}

__global__ __launch_bounds__(256) void k_qkv(
    const float* __restrict__ in_w, const float* __restrict__ in_b) {
  extern __shared__ float smm[];
  float* As = smm;
  float* ws = smm + 64 * MP;
  MID_PROLOG
  stage_mid(As, ws, g_stg + b * 16384, 256, in_w, 256, c0, 0, tid);
  float b0v = in_b[cg], b1v = in_b[cg + 1];
  float c[4] = {b0v, b1v, b0v, b1v};
  __syncthreads();
  mid_mma(As, ws, c, mA, nq, r, q);
  g_qkv[(b * 64 + row0) * 768 + cg] = c[0];
  g_qkv[(b * 64 + row0) * 768 + cg + 1] = c[1];
  g_qkv[(b * 64 + row1) * 768 + cg] = c[2];
  g_qkv[(b * 64 + row1) * 768 + cg + 1] = c[3];
}

// attention per (b, head): 32 blocks, 1024 threads
__global__ __launch_bounds__(1024) void k_attn() {
  int b = blockIdx.x >> 3, hh = blockIdx.x & 7;
  __shared__ float q[64][32], kk[64][33], vv[64][32], p[64][65];
  int tid = threadIdx.x;
  for (int i = tid; i < 2048; i += 1024) {
    int s = i >> 5, d = i & 31;
    int base = (b * 64 + s) * 768 + hh * 32 + d;
    q[s][d] = g_qkv[base];
    kk[s][d] = g_qkv[base + 256];
    vv[s][d] = g_qkv[base + 512];
  }
  __syncthreads();
  for (int idx = tid; idx < 4096; idx += 1024) {
    int qi = idx >> 6, ki = idx & 63;
    float a = 0.f;
#pragma unroll
    for (int d = 0; d < 32; d++) a += q[qi][d] * kk[ki][d];
    p[qi][ki] = a * 0.17677669529663687f;
  }
  __syncthreads();
  if (tid < 512) {
    const int row = tid >> 3, qq = tid & 7;
    float v[8], mx = -1e30f;
#pragma unroll
    for (int i = 0; i < 8; i++) {
      v[i] = p[row][qq * 8 + i];
      mx = fmaxf(mx, v[i]);
    }
    mx = fmaxf(mx, __shfl_xor_sync(0xffffffffu, mx, 1));
    mx = fmaxf(mx, __shfl_xor_sync(0xffffffffu, mx, 2));
    mx = fmaxf(mx, __shfl_xor_sync(0xffffffffu, mx, 4));
    float s = 0.f;
#pragma unroll
    for (int i = 0; i < 8; i++) { v[i] = __expf(v[i] - mx); s += v[i]; }
    s += __shfl_xor_sync(0xffffffffu, s, 1);
    s += __shfl_xor_sync(0xffffffffu, s, 2);
    s += __shfl_xor_sync(0xffffffffu, s, 4);
    const float inv = 1.f / s;
#pragma unroll
    for (int i = 0; i < 8; i++) p[row][qq * 8 + i] = v[i] * inv;
  }
  __syncthreads();
  for (int idx = tid; idx < 2048; idx += 1024) {
    int qi = idx >> 5, d = idx & 31;
    float a = 0.f;
#pragma unroll
    for (int j = 0; j < 64; j++) a += p[qi][j] * vv[j][d];
    g_ao[(b * 64 + qi) * 256 + hh * 32 + d] = a;
  }
}

__global__ __launch_bounds__(256) void k_proj(
    const float* __restrict__ out_w, const float* __restrict__ out_b) {
  extern __shared__ float smm[];
  float* As = smm;
  float* ws = smm + 64 * MP;
  MID_PROLOG
  stage_mid(As, ws, g_ao + b * 16384, 256, out_w, 256, c0, 0, tid);
  float b0v = out_b[cg], b1v = out_b[cg + 1];
  float c[4] = {b0v, b1v, b0v, b1v};
  __syncthreads();
  mid_mma(As, ws, c, mA, nq, r, q);
  g_pro[(b * 64 + row0) * 256 + cg] = c[0];
  g_pro[(b * 64 + row0) * 256 + cg + 1] = c[1];
  g_pro[(b * 64 + row1) * 256 + cg] = c[2];
  g_pro[(b * 64 + row1) * 256 + cg + 1] = c[3];
}

// LN kernel (used for LN2): out = LN(a + sum of np partials)
__device__ __forceinline__ void ln4_reduce(float yv[4], float mu[4], float var[4],
                                           float wsum[4][8], float wsq[4][8],
                                           int tid) {
  float s1[4], s2[4];
#pragma unroll
  for (int r = 0; r < 4; r++) { s1[r] = yv[r]; s2[r] = yv[r] * yv[r]; }
#pragma unroll
  for (int off = 16; off; off >>= 1)
#pragma unroll
    for (int r = 0; r < 4; r++) {
      s1[r] += __shfl_xor_sync(0xffffffffu, s1[r], off);
      s2[r] += __shfl_xor_sync(0xffffffffu, s2[r], off);
    }
  int w = tid >> 5, lane = tid & 31;
  if (lane == 0)
#pragma unroll
    for (int r = 0; r < 4; r++) { wsum[r][w] = s1[r]; wsq[r][w] = s2[r]; }
  __syncthreads();
#pragma unroll
  for (int r = 0; r < 4; r++) {
    float a = 0.f, bq = 0.f;
#pragma unroll
    for (int ww = 0; ww < 8; ww++) { a += wsum[r][ww]; bq += wsq[r][ww]; }
    mu[r] = a * (1.f / 256.f);
    var[r] = bq * (1.f / 256.f) - mu[r] * mu[r];
  }
}

__global__ __launch_bounds__(256) void k_ln(
    const float* __restrict__ a, const float* __restrict__ parts, int np,
    const float* __restrict__ g, const float* __restrict__ bb,
    float* __restrict__ out) {
  int bs0 = blockIdx.x * 4;
  __shared__ float wsum[4][8], wsq[4][8];
  int tid = threadIdx.x;
  float yv[4];
#pragma unroll
  for (int r = 0; r < 4; r++) {
    int idx = (bs0 + r) * 256 + tid;
    float v = a[idx];
    for (int pz = 0; pz < np; pz++) v += parts[pz * (BB * SS * HH) + idx];
    yv[r] = v;
  }
  float mu[4], var[4];
  ln4_reduce(yv, mu, var, wsum, wsq, tid);
#pragma unroll
  for (int r = 0; r < 4; r++)
    out[(bs0 + r) * 256 + tid] =
        (yv[r] - mu[r]) * rsqrtf(var[r] + 1e-5f) * g[tid] + bb[tid];
}

// ffn1 with fused LN1: y = stg + pro; st1 = LN(y); h = GELU(st1 @ f1_w^T + b)
// block x==0 also materializes st1 for the LN2 residual.
__global__ __launch_bounds__(256) void k_ffn1(
    const float* __restrict__ f1_w, const float* __restrict__ f1_b,
    const float* __restrict__ n1g, const float* __restrict__ n1b) {
  extern __shared__ float smm[];
  float* As = smm;
  float* ws = smm + 64 * MP;
  __shared__ float sg[256], sbv[256];
  MID_PROLOG
  // stage y = stg + pro
  for (int i = tid * 4; i < 16384; i += 1024) {
    float4 a = *(const float4*)(g_stg + b * 16384 + i);
    float4 p = *(const float4*)(g_pro + b * 16384 + i);
    a.x += p.x; a.y += p.y; a.z += p.z; a.w += p.w;
    *(float4*)(As + (i >> 8) * MP + (i & 255)) = a;
  }
  for (int i = tid * 4; i < 4096; i += 1024) {
    int cl = i >> 8, k = i & 255;
    float4 v = *(const float4*)(f1_w + (size_t)(c0 + cl) * 256 + k);
    *(float4*)(ws + cl * MP + k) = v;
  }
  sg[tid] = n1g[tid];
  sbv[tid] = n1b[tid];
  __syncthreads();
  // LN in-block: 8 warps x 8 rows, each lane 8 cols
  {
    const int cbase = lane * 8;
    for (int rr = wid * 8; rr < wid * 8 + 8; rr++) {
      float4 v1 = *(const float4*)(As + rr * MP + cbase);
      float4 v2 = *(const float4*)(As + rr * MP + cbase + 4);
      float s1 = v1.x + v1.y + v1.z + v1.w + v2.x + v2.y + v2.z + v2.w;
      float s2 = v1.x * v1.x + v1.y * v1.y + v1.z * v1.z + v1.w * v1.w +
                 v2.x * v2.x + v2.y * v2.y + v2.z * v2.z + v2.w * v2.w;
#pragma unroll
      for (int off = 16; off; off >>= 1) {
        s1 += __shfl_xor_sync(0xffffffffu, s1, off);
        s2 += __shfl_xor_sync(0xffffffffu, s2, off);
      }
      float mu = s1 * (1.f / 256.f);
      float var = s2 * (1.f / 256.f) - mu * mu;
      float rs = rsqrtf(var + 1e-5f);
      v1.x = (v1.x - mu) * rs * sg[cbase + 0] + sbv[cbase + 0];
      v1.y = (v1.y - mu) * rs * sg[cbase + 1] + sbv[cbase + 1];
      v1.z = (v1.z - mu) * rs * sg[cbase + 2] + sbv[cbase + 2];
      v1.w = (v1.w - mu) * rs * sg[cbase + 3] + sbv[cbase + 3];
      v2.x = (v2.x - mu) * rs * sg[cbase + 4] + sbv[cbase + 4];
      v2.y = (v2.y - mu) * rs * sg[cbase + 5] + sbv[cbase + 5];
      v2.z = (v2.z - mu) * rs * sg[cbase + 6] + sbv[cbase + 6];
      v2.w = (v2.w - mu) * rs * sg[cbase + 7] + sbv[cbase + 7];
      *(float4*)(As + rr * MP + cbase) = v1;
      *(float4*)(As + rr * MP + cbase + 4) = v2;
    }
  }
  __syncthreads();
  // materialize st1 once per batch (block x==0)
  if (blockIdx.x == 0) {
    for (int i = tid * 4; i < 16384; i += 1024)
      *(float4*)(g_st1 + b * 16384 + i) =
          *(const float4*)(As + (i >> 8) * MP + (i & 255));
  }
  float b0v = f1_b[cg], b1v = f1_b[cg + 1];
  float c[4] = {b0v, b1v, b0v, b1v};
  mid_mma(As, ws, c, mA, nq, r, q);
#pragma unroll
  for (int j = 0; j < 4; j++) {
    float v = c[j];
    c[j] = 0.5f * v * (1.f + erff(v * 0.7071067811865475f));
  }
  g_h[(b * 64 + row0) * 1024 + cg] = c[0];
  g_h[(b * 64 + row0) * 1024 + cg + 1] = c[1];
  g_h[(b * 64 + row1) * 1024 + cg] = c[2];
  g_h[(b * 64 + row1) * 1024 + cg + 1] = c[3];
}

// ffn2: K=1024 with 4-way k-split (blockIdx.z)
__global__ __launch_bounds__(256) void k_ffn2(
    const float* __restrict__ f2_w, const float* __restrict__ f2_b) {
  extern __shared__ float smm[];
  float* As = smm;
  float* ws = smm + 64 * MP;
  const int z = blockIdx.z;
  MID_PROLOG
  stage_mid(As, ws, g_h + b * 65536 + z * 256, 1024, f2_w, 1024, c0, z * 256,
            tid);
  float b0v = (z == 0) ? f2_b[cg] : 0.f;
  float b1v = (z == 0) ? f2_b[cg + 1] : 0.f;
  float c[4] = {b0v, b1v, b0v, b1v};
  __syncthreads();
  mid_mma(As, ws, c, mA, nq, r, q);
  g_f2p[z][(b * 64 + row0) * 256 + cg] = c[0];
  g_f2p[z][(b * 64 + row0) * 256 + cg + 1] = c[1];
  g_f2p[z][(b * 64 + row1) * 256 + cg] = c[2];
  g_f2p[z][(b * 64 + row1) * 256 + cg + 1] = c[3];
}

// ===========================================================================
// KC: decode out = W @ st2 + x via tf32 mma. 256 threads, 128 tokens/block,
// 103KB smem -> 2 blocks/SM. grid (256, B).
// ===========================================================================
__global__ __launch_bounds__(256, 2) void k_decode(const float* __restrict__ x,
                                                   float* __restrict__ out) {
  extern __shared__ float sm[];
  float* st2s = sm;              // [64][SP]
  float* Ws = sm + 64 * SP;      // [128][AP]
  const int tid = threadIdx.x;
  const int b = blockIdx.y;
  const int n0 = blockIdx.x * 128;

  for (int i = tid * 4; i < 16384; i += 1024)
    *(float4*)(st2s + (i >> 8) * SP + (i & 255)) =
        *(const float4*)(g_st2 + b * 16384 + i);
  for (int i = tid * 4; i < 8192; i += 1024)
    *(float4*)(Ws + (i >> 6) * AP + (i & 63)) =
        *(const float4*)(g_W + ((size_t)b * NN + n0 + (i >> 6)) * 64 + (i & 63));
  __syncthreads();

  const int wid = tid >> 5, lane = tid & 31;
  const int r = lane >> 2, q = lane & 3;
  const int m0 = wid * 16;

  for (int nh = 0; nh < 2; nh++) {
    float acc[16][4];
#pragma unroll
    for (int i = 0; i < 16; i++)
#pragma unroll
      for (int j = 0; j < 4; j++) acc[i][j] = 0.f;

    for (int ks = 0; ks < 8; ks++) {
      const int k0 = ks * 8;
      uint32_t a0 = F2U(Ws[(m0 + r) * AP + k0 + q]);
      uint32_t a1 = F2U(Ws[(m0 + r + 8) * AP + k0 + q]);
      uint32_t a2 = F2U(Ws[(m0 + r) * AP + k0 + q + 4]);
      uint32_t a3 = F2U(Ws[(m0 + r + 8) * AP + k0 + q + 4]);
#pragma unroll
      for (int nt = 0; nt < 16; nt++) {
        const int n = nh * 128 + nt * 8;
        uint32_t b0 = F2U(st2s[(k0 + q) * SP + n + r]);
        uint32_t b1 = F2U(st2s[(k0 + q + 4) * SP + n + r]);
        mma_tf32(acc[nt], a0, a1, a2, a3, b0, b1);
      }
    }
#pragma unroll
    for (int nt = 0; nt < 16; nt++) {
      const int n = nh * 128 + nt * 8 + 2 * q;
      const size_t base0 = ((size_t)b * NN + n0 + m0 + r) * 256 + n;
      const size_t base1 = base0 + 8 * 256;
      float2 xv0 = *(const float2*)(x + base0);
      float2 xv1 = *(const float2*)(x + base1);
      *(float2*)(out + base0) = make_float2(acc[nt][0] + xv0.x, acc[nt][1] + xv0.y);
      *(float2*)(out + base1) = make_float2(acc[nt][2] + xv1.x, acc[nt][3] + xv1.y);
    }
  }
}

// ===========================================================================
extern "C" void kernel_launch(void* const* d_in, const int* in_sizes, int n_in,
                              void* d_out, int out_size) {
  const float* x = (const float*)d_in[0];
  const float* sq_w = (const float*)d_in[1];
  const float* sq_b = (const float*)d_in[2];
  const float* eid_state = (const float*)d_in[3];
  const float* eid_gw = (const float*)d_in[4];
  const float* eid_gb = (const float*)d_in[5];
  const float* in_w = (const float*)d_in[6];
  const float* in_b = (const float*)d_in[7];
  const float* out_w = (const float*)d_in[8];
  const float* out_b = (const float*)d_in[9];
  const float* n1_g = (const float*)d_in[10];
  const float* n1_b = (const float*)d_in[11];
  const float* n2_g = (const float*)d_in[12];
  const float* n2_b = (const float*)d_in[13];
  const float* f1_w = (const float*)d_in[14];
  const float* f1_b = (const float*)d_in[15];
  const float* f2_w = (const float*)d_in[16];
  const float* f2_b = (const float*)d_in[17];
  float* out = (float*)d_out;

  const int smem_ka = (64 * XP + 64 * WP + 64 * LP + 64) * 4;
  const int smem_kc = (64 * SP + 128 * AP) * 4;
  cudaFuncSetAttribute(k_assign_pool, cudaFuncAttributeMaxDynamicSharedMemorySize, smem_ka);
  cudaFuncSetAttribute(k_decode, cudaFuncAttributeMaxDynamicSharedMemorySize, smem_kc);
  cudaFuncSetAttribute(k_gate, cudaFuncAttributeMaxDynamicSharedMemorySize, MIDQ_SMEM);
  cudaFuncSetAttribute(k_qkv, cudaFuncAttributeMaxDynamicSharedMemorySize, MIDQ_SMEM);
  cudaFuncSetAttribute(k_proj, cudaFuncAttributeMaxDynamicSharedMemorySize, MIDQ_SMEM);
  cudaFuncSetAttribute(k_ffn1, cudaFuncAttributeMaxDynamicSharedMemorySize, MIDQ_SMEM);
  cudaFuncSetAttribute(k_ffn2, cudaFuncAttributeMaxDynamicSharedMemorySize, MIDQ_SMEM);

  float *p_st1, *p_f2p, *p_st2;
  cudaGetSymbolAddress((void**)&p_st1, g_st1);
  cudaGetSymbolAddress((void**)&p_f2p, g_f2p);
  cudaGetSymbolAddress((void**)&p_st2, g_st2);

  k_assign_pool<<<dim3(64, BB), 512, smem_ka>>>(x, sq_w, sq_b);
  k_reduce_st<<<64, 256>>>();
  k_gate<<<dim3(16, BB), 256, MIDQ_SMEM>>>(eid_gw, eid_gb, eid_state);
  k_qkv<<<dim3(48, BB), 256, MIDQ_SMEM>>>(in_w, in_b);
  k_attn<<<32, 1024>>>();
  k_proj<<<dim3(16, BB), 256, MIDQ_SMEM>>>(out_w, out_b);
  k_ffn1<<<dim3(64, BB), 256, MIDQ_SMEM>>>(f1_w, f1_b, n1_g, n1_b);
  k_ffn2<<<dim3(16, BB, 4), 256, MIDQ_SMEM>>>(f2_w, f2_b);
  k_ln<<<64, 256>>>(p_st1, p_f2p, 4, n2_g, n2_b, p_st2);
  k_decode<<<dim3(256, BB), 256, smem_kc>>>(x, out);
}

// round 12
// speedup vs baseline: 1.0386x; 1.0386x over previous
#include <cuda_runtime.h>
#include <stdint.h>
#include <math.h>

#define BB 4
#define NN 32768
#define HH 256
#define SS 64

#define XP 268   // xs row pad (floats)
#define WP 268   // sq_w row pad
#define LP 72    // logits/W tile row pad
#define SP 268   // st2 row pad (KC)
#define AP 68    // W tile row pad (KC)
#define MP 268   // middle-gemm row pad

// ---------------- scratch (static device allocations only) ----------------
__device__ float g_W[(size_t)BB * NN * SS];          // 32 MB soft-assignment weights
__device__ float g_part[(size_t)256 * 16384];        // 16.8MB pooling partials
__device__ float g_st[BB * SS * HH];
__device__ float g_stg[BB * SS * HH];                // gated st
__device__ float g_qkv[BB * SS * 3 * HH];
__device__ float g_ao[BB * SS * HH];
__device__ float g_pro[BB * SS * HH];                // attn out-proj (pre-LN)
__device__ float g_st1[BB * SS * HH];
__device__ float g_h[BB * SS * 4 * HH];
__device__ float g_f2p[4][BB * SS * HH];             // ffn2 k-split partials
__device__ float g_st2[BB * SS * HH];

// ---- m16n8k8 tf32 mma helper --------------------------------------------
__device__ __forceinline__ void mma_tf32(float c[4], uint32_t a0, uint32_t a1,
                                         uint32_t a2, uint32_t a3, uint32_t b0,
                                         uint32_t b1) {
  asm volatile(
      "mma.sync.aligned.m16n8k8.row.col.f32.tf32.tf32.f32 "
      "{%0,%1,%2,%3}, {%4,%5,%6,%7}, {%8,%9}, {%0,%1,%2,%3};\n"
      : "+f"(c[0]), "+f"(c[1]), "+f"(c[2]), "+f"(c[3])
      : "r"(a0), "r"(a1), "r"(a2), "r"(a3), "r"(b0), "r"(b1));
}
#define F2U __float_as_uint

// ===========================================================================
// KA: fused logits + softmax + pooling. 512 threads, grid (64, B).
// 512 tokens per block in 8 tiles of 64. x staging double-buffered via regs.
// Phase A: split-K2, warp = m16 x n32 (amortizes A-fragment LDS over 4 nt).
// ===========================================================================
__global__ __launch_bounds__(512, 1) void k_assign_pool(
    const float* __restrict__ x, const float* __restrict__ sq_w,
    const float* __restrict__ sq_b) {
  extern __shared__ float sm[];
  float* xs = sm;                 // [64][XP]
  float* ws = sm + 64 * XP;       // [64][WP]
  float* lg = ws + 64 * WP;       // [64][LP]
  float* sb = lg + 64 * LP;       // [64]

  const int tid = threadIdx.x;
  const int b = blockIdx.y;
  const size_t tok0 = (size_t)blockIdx.x * 512;
  const float* xb = x + (size_t)b * NN * HH;

  for (int i = tid * 4; i < 16384; i += 2048) {
    float4 v = *(const float4*)(sq_w + i);
    *(float4*)(ws + (i >> 8) * WP + (i & 255)) = v;
  }
  if (tid < 64) sb[tid] = sq_b[tid];

  const int wid = tid >> 5, lane = tid & 31;
  const int r = lane >> 2, q = lane & 3;
  const int mA = (wid & 3) * 16;        // phase-A m-tile (4)
  const int nh = ((wid >> 2) & 1) * 4;  // phase-A nt base (2 halves of 4 nt)
  const int kh = (wid >> 3) * 128;      // phase-A k half (2)
  const int hb = wid * 16;              // pooling h tile

  float stacc[8][4];
#pragma unroll
  for (int j = 0; j < 8; j++)
#pragma unroll
    for (int k = 0; k < 4; k++) stacc[j][k] = 0.f;

  // prefetch tile 0 into registers
  float4 pf[8];
  {
    const float* xsrc = xb + tok0 * 256;
#pragma unroll
    for (int it = 0; it < 8; it++)
      pf[it] = *(const float4*)(xsrc + tid * 4 + it * 2048);
  }

  for (int tile = 0; tile < 8; tile++) {
    __syncthreads();  // previous tile's xs/lg consumers done
#pragma unroll
    for (int it = 0; it < 8; it++) {
      const int i = tid * 4 + it * 2048;
      *(float4*)(xs + (i >> 8) * XP + (i & 255)) = pf[it];
    }
    __syncthreads();
    if (tile < 7) {  // issue next tile's loads; overlap with compute below
      const float* xsrc = xb + (tok0 + (tile + 1) * 64) * 256;
#pragma unroll
      for (int it = 0; it < 8; it++)
        pf[it] = *(const float4*)(xsrc + tid * 4 + it * 2048);
    }

    // ---- phase A: logits, warp = m16 x (4 nt), K half = 128 ----
    float lacc[4][4];
#pragma unroll
    for (int j = 0; j < 4; j++)
#pragma unroll
      for (int k = 0; k < 4; k++) lacc[j][k] = 0.f;

    for (int ks = 0; ks < 16; ks++) {
      const int k0 = kh + ks * 8;
      uint32_t a0 = F2U(xs[(mA + r) * XP + k0 + q]);
      uint32_t a1 = F2U(xs[(mA + r + 8) * XP + k0 + q]);
      uint32_t a2 = F2U(xs[(mA + r) * XP + k0 + q + 4]);
      uint32_t a3 = F2U(xs[(mA + r + 8) * XP + k0 + q + 4]);
#pragma unroll
      for (int j = 0; j < 4; j++) {
        const int nt = nh + j;
        uint32_t b0 = F2U(ws[(nt * 8 + r) * WP + k0 + q]);
        uint32_t b1 = F2U(ws[(nt * 8 + r) * WP + k0 + q + 4]);
        mma_tf32(lacc[j], a0, a1, a2, a3, b0, b1);
      }
    }
    // reduce the two k-halves into lg
    if (kh == 0) {
#pragma unroll
      for (int j = 0; j < 4; j++) {
        const int nt = nh + j;
        lg[(mA + r) * LP + nt * 8 + 2 * q] = lacc[j][0];
        lg[(mA + r) * LP + nt * 8 + 2 * q + 1] = lacc[j][1];
        lg[(mA + r + 8) * LP + nt * 8 + 2 * q] = lacc[j][2];
        lg[(mA + r + 8) * LP + nt * 8 + 2 * q + 1] = lacc[j][3];
      }
    }
    __syncthreads();
    if (kh != 0) {
#pragma unroll
      for (int j = 0; j < 4; j++) {
        const int nt = nh + j;
        lg[(mA + r) * LP + nt * 8 + 2 * q] += lacc[j][0];
        lg[(mA + r) * LP + nt * 8 + 2 * q + 1] += lacc[j][1];
        lg[(mA + r + 8) * LP + nt * 8 + 2 * q] += lacc[j][2];
        lg[(mA + r + 8) * LP + nt * 8 + 2 * q + 1] += lacc[j][3];
      }
    }
    __syncthreads();

    // ---- softmax: 8 threads per row ----
    {
      const int t = tid >> 3, qq = tid & 7;
      float v[8];
      float mx = -1e30f;
#pragma unroll
      for (int i = 0; i < 8; i++) {
        v[i] = lg[t * LP + qq * 8 + i] + sb[qq * 8 + i];
        mx = fmaxf(mx, v[i]);
      }
      mx = fmaxf(mx, __shfl_xor_sync(0xffffffffu, mx, 1));
      mx = fmaxf(mx, __shfl_xor_sync(0xffffffffu, mx, 2));
      mx = fmaxf(mx, __shfl_xor_sync(0xffffffffu, mx, 4));
      float s = 0.f;
#pragma unroll
      for (int i = 0; i < 8; i++) {
        v[i] = __expf(v[i] - mx);
        s += v[i];
      }
      s += __shfl_xor_sync(0xffffffffu, s, 1);
      s += __shfl_xor_sync(0xffffffffu, s, 2);
      s += __shfl_xor_sync(0xffffffffu, s, 4);
      const float inv = 1.f / s;
      const size_t wrow =
          ((size_t)b * NN + tok0 + tile * 64 + t) * 64 + qq * 8;
#pragma unroll
      for (int i = 0; i < 8; i++) {
        float w = v[i] * inv;
        lg[t * LP + qq * 8 + i] = w;
        g_W[wrow + i] = w;
      }
    }
    __syncthreads();

    // ---- pooling: st^T[h][s] += x^T @ Wtile, warp = 16 h rows ----
    for (int ks = 0; ks < 8; ks++) {
      const int k0 = ks * 8;
      uint32_t a0 = F2U(xs[(k0 + q) * XP + hb + r]);
      uint32_t a1 = F2U(xs[(k0 + q) * XP + hb + r + 8]);
      uint32_t a2 = F2U(xs[(k0 + q + 4) * XP + hb + r]);
      uint32_t a3 = F2U(xs[(k0 + q + 4) * XP + hb + r + 8]);
#pragma unroll
      for (int nt = 0; nt < 8; nt++) {
        uint32_t b0 = F2U(lg[(k0 + q) * LP + nt * 8 + r]);
        uint32_t b1 = F2U(lg[(k0 + q + 4) * LP + nt * 8 + r]);
        mma_tf32(stacc[nt], a0, a1, a2, a3, b0, b1);
      }
    }
  }

  float* pp = g_part + (size_t)(b * 64 + blockIdx.x) * 16384;
#pragma unroll
  for (int nt = 0; nt < 8; nt++) {
    const int h0 = hb + r;
    const int s0 = nt * 8 + 2 * q;
    *(float2*)(pp + h0 * 64 + s0) = make_float2(stacc[nt][0], stacc[nt][1]);
    *(float2*)(pp + (h0 + 8) * 64 + s0) = make_float2(stacc[nt][2], stacc[nt][3]);
  }
}

// ===========================================================================
// reduce pooling partials (64 per batch) -> g_st
// ===========================================================================
__global__ __launch_bounds__(256) void k_reduce_st() {
  const int gt = blockIdx.x * 256 + threadIdx.x;  // 0..16383
  const int bb = gt >> 12;
  const int p4 = (gt & 4095) * 4;
  const float* p = g_part + (size_t)bb * 64 * 16384 + p4;
  float4 acc = make_float4(0.f, 0.f, 0.f, 0.f);
#pragma unroll 8
  for (int j = 0; j < 64; j++) {
    float4 v = *(const float4*)(p + (size_t)j * 16384);
    acc.x += v.x; acc.y += v.y; acc.z += v.z; acc.w += v.w;
  }
  const int h = p4 >> 6, s0 = p4 & 63;
  float* dst = g_st + bb * 16384 + h;
  dst[(s0 + 0) * 256] = acc.x;
  dst[(s0 + 1) * 256] = acc.y;
  dst[(s0 + 2) * 256] = acc.z;
  dst[(s0 + 3) * 256] = acc.w;
}

// ===========================================================================
// Middle GEMM via tf32 mma. 512 threads (16 warps = 4 m-tiles x 4 n-tiles),
// 32 output cols per block (R9 proven geometry).
// smem: As[64][MP] + ws[32][MP] = 102.9KB.
// ===========================================================================
#define MIDQ_SMEM ((64 * MP + 32 * MP) * 4)

__device__ __forceinline__ void stage_mid(float* As, float* ws,
                                          const float* asrc, int lds,
                                          const float* w, int ldw, int c0,
                                          int koff, int tid) {
  for (int i = tid * 4; i < 16384; i += 2048) {
    float4 v = *(const float4*)(asrc + (i >> 8) * lds + (i & 255));
    *(float4*)(As + (i >> 8) * MP + (i & 255)) = v;
  }
  for (int i = tid * 4; i < 8192; i += 2048) {
    int cl = i >> 8, k = i & 255;
    float4 v = *(const float4*)(w + (size_t)(c0 + cl) * ldw + koff + k);
    *(float4*)(ws + cl * MP + k) = v;
  }
}

__device__ __forceinline__ void mid_mma(const float* __restrict__ As,
                                        const float* __restrict__ ws,
                                        float c[4], int mA, int nq, int r,
                                        int q) {
#pragma unroll 4
  for (int ks = 0; ks < 32; ks++) {
    const int k0 = ks * 8;
    uint32_t a0 = F2U(As[(mA + r) * MP + k0 + q]);
    uint32_t a1 = F2U(As[(mA + r + 8) * MP + k0 + q]);
    uint32_t a2 = F2U(As[(mA + r) * MP + k0 + q + 4]);
    uint32_t a3 = F2U(As[(mA + r + 8) * MP + k0 + q + 4]);
    uint32_t b0 = F2U(ws[(nq * 8 + r) * MP + k0 + q]);
    uint32_t b1 = F2U(ws[(nq * 8 + r) * MP + k0 + q + 4]);
    mma_tf32(c, a0, a1, a2, a3, b0, b1);
  }
}

// thread->output mapping shared by all middle kernels (32 cols, 512 thr)
#define MID_PROLOG                                     \
  const int tid = threadIdx.x;                         \
  const int b = blockIdx.y;                            \
  const int c0 = blockIdx.x * 32;                      \
  const int wid = tid >> 5, lane = tid & 31;           \
  const int r = lane >> 2, q = lane & 3;               \
  const int mA = (wid & 3) * 16, nq = wid >> 2;        \
  const int cg = c0 + nq * 8 + 2 * q;                  \
  const int row0 = mA + r, row1 = mA + r + 8;

// gate: st_gated = st + sigmoid(st @ gw^T + gb) * estate
__global__ __launch_bounds__(512) void k_gate(
    const float* __restrict__ gw, const float* __restrict__ gb,
    const float* __restrict__ estate) {
  extern __shared__ float smm[];
  float* As = smm;
  float* ws = smm + 64 * MP;
  MID_PROLOG
  stage_mid(As, ws, g_st + b * 16384, 256, gw, 256, c0, 0, tid);
  float b0v = gb[cg], b1v = gb[cg + 1];
  float c[4] = {b0v, b1v, b0v, b1v};
  __syncthreads();
  mid_mma(As, ws, c, mA, nq, r, q);
  float s0 = 1.f / (1.f + __expf(-c[0]));
  float s1 = 1.f / (1.f + __expf(-c[1]));
  float s2 = 1.f / (1.f + __expf(-c[2]));
  float s3 = 1.f / (1.f + __expf(-c[3]));
  g_stg[b * 16384 + row0 * 256 + cg] = As[row0 * MP + cg] + s0 * estate[row0 * 256 + cg];
  g_stg[b * 16384 + row0 * 256 + cg + 1] = As[row0 * MP + cg + 1] + s1 * estate[row0 * 256 + cg + 1];
  g_stg[b * 16384 + row1 * 256 + cg] = As[row1 * MP + cg] + s2 * estate[row1 * 256 + cg];
  g_stg[b * 16384 + row1 * 256 + cg + 1] = As[row1 * MP + cg + 1] + s3 * estate[row1 * 256 + cg + 1];
}

__global__ __launch_bounds__(512) void k_qkv(
    const float* __restrict__ in_w, const float* __restrict__ in_b) {
  extern __shared__ float smm[];
  float* As = smm;
  float* ws = smm + 64 * MP;
  MID_PROLOG
  stage_mid(As, ws, g_stg + b * 16384, 256, in_w, 256, c0, 0, tid);
  float b0v = in_b[cg], b1v = in_b[cg + 1];
  float c[4] = {b0v, b1v, b0v, b1v};
  __syncthreads();
  mid_mma(As, ws, c, mA, nq, r, q);
  g_qkv[(b * 64 + row0) * 768 + cg] = c[0];
  g_qkv[(b * 64 + row0) * 768 + cg + 1] = c[1];
  g_qkv[(b * 64 + row1) * 768 + cg] = c[2];
  g_qkv[(b * 64 + row1) * 768 + cg + 1] = c[3];
}

// attention per (b, head): 32 blocks, 1024 threads
__global__ __launch_bounds__(1024) void k_attn() {
  int b = blockIdx.x >> 3, hh = blockIdx.x & 7;
  __shared__ float q[64][32], kk[64][33], vv[64][32], p[64][65];
  int tid = threadIdx.x;
  for (int i = tid; i < 2048; i += 1024) {
    int s = i >> 5, d = i & 31;
    int base = (b * 64 + s) * 768 + hh * 32 + d;
    q[s][d] = g_qkv[base];
    kk[s][d] = g_qkv[base + 256];
    vv[s][d] = g_qkv[base + 512];
  }
  __syncthreads();
  for (int idx = tid; idx < 4096; idx += 1024) {
    int qi = idx >> 6, ki = idx & 63;
    float a = 0.f;
#pragma unroll
    for (int d = 0; d < 32; d++) a += q[qi][d] * kk[ki][d];
    p[qi][ki] = a * 0.17677669529663687f;
  }
  __syncthreads();
  if (tid < 512) {
    const int row = tid >> 3, qq = tid & 7;
    float v[8], mx = -1e30f;
#pragma unroll
    for (int i = 0; i < 8; i++) {
      v[i] = p[row][qq * 8 + i];
      mx = fmaxf(mx, v[i]);
    }
    mx = fmaxf(mx, __shfl_xor_sync(0xffffffffu, mx, 1));
    mx = fmaxf(mx, __shfl_xor_sync(0xffffffffu, mx, 2));
    mx = fmaxf(mx, __shfl_xor_sync(0xffffffffu, mx, 4));
    float s = 0.f;
#pragma unroll
    for (int i = 0; i < 8; i++) { v[i] = __expf(v[i] - mx); s += v[i]; }
    s += __shfl_xor_sync(0xffffffffu, s, 1);
    s += __shfl_xor_sync(0xffffffffu, s, 2);
    s += __shfl_xor_sync(0xffffffffu, s, 4);
    const float inv = 1.f / s;
#pragma unroll
    for (int i = 0; i < 8; i++) p[row][qq * 8 + i] = v[i] * inv;
  }
  __syncthreads();
  for (int idx = tid; idx < 2048; idx += 1024) {
    int qi = idx >> 5, d = idx & 31;
    float a = 0.f;
#pragma unroll
    for (int j = 0; j < 64; j++) a += p[qi][j] * vv[j][d];
    g_ao[(b * 64 + qi) * 256 + hh * 32 + d] = a;
  }
}

__global__ __launch_bounds__(512) void k_proj(
    const float* __restrict__ out_w, const float* __restrict__ out_b) {
  extern __shared__ float smm[];
  float* As = smm;
  float* ws = smm + 64 * MP;
  MID_PROLOG
  stage_mid(As, ws, g_ao + b * 16384, 256, out_w, 256, c0, 0, tid);
  float b0v = out_b[cg], b1v = out_b[cg + 1];
  float c[4] = {b0v, b1v, b0v, b1v};
  __syncthreads();
  mid_mma(As, ws, c, mA, nq, r, q);
  g_pro[(b * 64 + row0) * 256 + cg] = c[0];
  g_pro[(b * 64 + row0) * 256 + cg + 1] = c[1];
  g_pro[(b * 64 + row1) * 256 + cg] = c[2];
  g_pro[(b * 64 + row1) * 256 + cg + 1] = c[3];
}

// LN kernel (used for LN2): out = LN(a + sum of np partials)
__device__ __forceinline__ void ln4_reduce(float yv[4], float mu[4], float var[4],
                                           float wsum[4][8], float wsq[4][8],
                                           int tid) {
  float s1[4], s2[4];
#pragma unroll
  for (int r = 0; r < 4; r++) { s1[r] = yv[r]; s2[r] = yv[r] * yv[r]; }
#pragma unroll
  for (int off = 16; off; off >>= 1)
#pragma unroll
    for (int r = 0; r < 4; r++) {
      s1[r] += __shfl_xor_sync(0xffffffffu, s1[r], off);
      s2[r] += __shfl_xor_sync(0xffffffffu, s2[r], off);
    }
  int w = tid >> 5, lane = tid & 31;
  if (lane == 0)
#pragma unroll
    for (int r = 0; r < 4; r++) { wsum[r][w] = s1[r]; wsq[r][w] = s2[r]; }
  __syncthreads();
#pragma unroll
  for (int r = 0; r < 4; r++) {
    float a = 0.f, bq = 0.f;
#pragma unroll
    for (int ww = 0; ww < 8; ww++) { a += wsum[r][ww]; bq += wsq[r][ww]; }
    mu[r] = a * (1.f / 256.f);
    var[r] = bq * (1.f / 256.f) - mu[r] * mu[r];
  }
}

__global__ __launch_bounds__(256) void k_ln(
    const float* __restrict__ a, const float* __restrict__ parts, int np,
    const float* __restrict__ g, const float* __restrict__ bb,
    float* __restrict__ out) {
  int bs0 = blockIdx.x * 4;
  __shared__ float wsum[4][8], wsq[4][8];
  int tid = threadIdx.x;
  float yv[4];
#pragma unroll
  for (int r = 0; r < 4; r++) {
    int idx = (bs0 + r) * 256 + tid;
    float v = a[idx];
    for (int pz = 0; pz < np; pz++) v += parts[pz * (BB * SS * HH) + idx];
    yv[r] = v;
  }
  float mu[4], var[4];
  ln4_reduce(yv, mu, var, wsum, wsq, tid);
#pragma unroll
  for (int r = 0; r < 4; r++)
    out[(bs0 + r) * 256 + tid] =
        (yv[r] - mu[r]) * rsqrtf(var[r] + 1e-5f) * g[tid] + bb[tid];
}

// ffn1 with fused LN1: y = stg + pro; st1 = LN(y); h = GELU(st1 @ f1_w^T + b)
// block x==0 also materializes st1 for the LN2 residual. 512 threads.
__global__ __launch_bounds__(512) void k_ffn1(
    const float* __restrict__ f1_w, const float* __restrict__ f1_b,
    const float* __restrict__ n1g, const float* __restrict__ n1b) {
  extern __shared__ float smm[];
  float* As = smm;
  float* ws = smm + 64 * MP;
  __shared__ float sg[256], sbv[256];
  MID_PROLOG
  // stage y = stg + pro
  for (int i = tid * 4; i < 16384; i += 2048) {
    float4 a = *(const float4*)(g_stg + b * 16384 + i);
    float4 p = *(const float4*)(g_pro + b * 16384 + i);
    a.x += p.x; a.y += p.y; a.z += p.z; a.w += p.w;
    *(float4*)(As + (i >> 8) * MP + (i & 255)) = a;
  }
  for (int i = tid * 4; i < 8192; i += 2048) {
    int cl = i >> 8, k = i & 255;
    float4 v = *(const float4*)(f1_w + (size_t)(c0 + cl) * 256 + k);
    *(float4*)(ws + cl * MP + k) = v;
  }
  if (tid < 256) {
    sg[tid] = n1g[tid];
    sbv[tid] = n1b[tid];
  }
  __syncthreads();
  // LN in-block: 16 warps x 4 rows, each lane 8 cols
  {
    const int cbase = lane * 8;
    for (int rr = wid * 4; rr < wid * 4 + 4; rr++) {
      float4 v1 = *(const float4*)(As + rr * MP + cbase);
      float4 v2 = *(const float4*)(As + rr * MP + cbase + 4);
      float s1 = v1.x + v1.y + v1.z + v1.w + v2.x + v2.y + v2.z + v2.w;
      float s2 = v1.x * v1.x + v1.y * v1.y + v1.z * v1.z + v1.w * v1.w +
                 v2.x * v2.x + v2.y * v2.y + v2.z * v2.z + v2.w * v2.w;
#pragma unroll
      for (int off = 16; off; off >>= 1) {
        s1 += __shfl_xor_sync(0xffffffffu, s1, off);
        s2 += __shfl_xor_sync(0xffffffffu, s2, off);
      }
      float mu = s1 * (1.f / 256.f);
      float var = s2 * (1.f / 256.f) - mu * mu;
      float rs = rsqrtf(var + 1e-5f);
      v1.x = (v1.x - mu) * rs * sg[cbase + 0] + sbv[cbase + 0];
      v1.y = (v1.y - mu) * rs * sg[cbase + 1] + sbv[cbase + 1];
      v1.z = (v1.z - mu) * rs * sg[cbase + 2] + sbv[cbase + 2];
      v1.w = (v1.w - mu) * rs * sg[cbase + 3] + sbv[cbase + 3];
      v2.x = (v2.x - mu) * rs * sg[cbase + 4] + sbv[cbase + 4];
      v2.y = (v2.y - mu) * rs * sg[cbase + 5] + sbv[cbase + 5];
      v2.z = (v2.z - mu) * rs * sg[cbase + 6] + sbv[cbase + 6];
      v2.w = (v2.w - mu) * rs * sg[cbase + 7] + sbv[cbase + 7];
      *(float4*)(As + rr * MP + cbase) = v1;
      *(float4*)(As + rr * MP + cbase + 4) = v2;
    }
  }
  __syncthreads();
  // materialize st1 once per batch (block x==0)
  if (blockIdx.x == 0) {
    for (int i = tid * 4; i < 16384; i += 2048)
      *(float4*)(g_st1 + b * 16384 + i) =
          *(const float4*)(As + (i >> 8) * MP + (i & 255));
  }
  float b0v = f1_b[cg], b1v = f1_b[cg + 1];
  float c[4] = {b0v, b1v, b0v, b1v};
  mid_mma(As, ws, c, mA, nq, r, q);
#pragma unroll
  for (int j = 0; j < 4; j++) {
    float v = c[j];
    c[j] = 0.5f * v * (1.f + erff(v * 0.7071067811865475f));
  }
  g_h[(b * 64 + row0) * 1024 + cg] = c[0];
  g_h[(b * 64 + row0) * 1024 + cg + 1] = c[1];
  g_h[(b * 64 + row1) * 1024 + cg] = c[2];
  g_h[(b * 64 + row1) * 1024 + cg + 1] = c[3];
}

// ffn2: K=1024 with 4-way k-split (blockIdx.z)
__global__ __launch_bounds__(512) void k_ffn2(
    const float* __restrict__ f2_w, const float* __restrict__ f2_b) {
  extern __shared__ float smm[];
  float* As = smm;
  float* ws = smm + 64 * MP;
  const int z = blockIdx.z;
  MID_PROLOG
  stage_mid(As, ws, g_h + b * 65536 + z * 256, 1024, f2_w, 1024, c0, z * 256,
            tid);
  float b0v = (z == 0) ? f2_b[cg] : 0.f;
  float b1v = (z == 0) ? f2_b[cg + 1] : 0.f;
  float c[4] = {b0v, b1v, b0v, b1v};
  __syncthreads();
  mid_mma(As, ws, c, mA, nq, r, q);
  g_f2p[z][(b * 64 + row0) * 256 + cg] = c[0];
  g_f2p[z][(b * 64 + row0) * 256 + cg + 1] = c[1];
  g_f2p[z][(b * 64 + row1) * 256 + cg] = c[2];
  g_f2p[z][(b * 64 + row1) * 256 + cg + 1] = c[3];
}

// ===========================================================================
// KC: decode out = W @ st2 + x via tf32 mma. 256 threads, 128 tokens/block,
// 103KB smem -> 2 blocks/SM. grid (256, B).
// ===========================================================================
__global__ __launch_bounds__(256, 2) void k_decode(const float* __restrict__ x,
                                                   float* __restrict__ out) {
  extern __shared__ float sm[];
  float* st2s = sm;              // [64][SP]
  float* Ws = sm + 64 * SP;      // [128][AP]
  const int tid = threadIdx.x;
  const int b = blockIdx.y;
  const int n0 = blockIdx.x * 128;

  for (int i = tid * 4; i < 16384; i += 1024)
    *(float4*)(st2s + (i >> 8) * SP + (i & 255)) =
        *(const float4*)(g_st2 + b * 16384 + i);
  for (int i = tid * 4; i < 8192; i += 1024)
    *(float4*)(Ws + (i >> 6) * AP + (i & 63)) =
        *(const float4*)(g_W + ((size_t)b * NN + n0 + (i >> 6)) * 64 + (i & 63));
  __syncthreads();

  const int wid = tid >> 5, lane = tid & 31;
  const int r = lane >> 2, q = lane & 3;
  const int m0 = wid * 16;

  for (int nh = 0; nh < 2; nh++) {
    float acc[16][4];
#pragma unroll
    for (int i = 0; i < 16; i++)
#pragma unroll
      for (int j = 0; j < 4; j++) acc[i][j] = 0.f;

    for (int ks = 0; ks < 8; ks++) {
      const int k0 = ks * 8;
      uint32_t a0 = F2U(Ws[(m0 + r) * AP + k0 + q]);
      uint32_t a1 = F2U(Ws[(m0 + r + 8) * AP + k0 + q]);
      uint32_t a2 = F2U(Ws[(m0 + r) * AP + k0 + q + 4]);
      uint32_t a3 = F2U(Ws[(m0 + r + 8) * AP + k0 + q + 4]);
#pragma unroll
      for (int nt = 0; nt < 16; nt++) {
        const int n = nh * 128 + nt * 8;
        uint32_t b0 = F2U(st2s[(k0 + q) * SP + n + r]);
        uint32_t b1 = F2U(st2s[(k0 + q + 4) * SP + n + r]);
        mma_tf32(acc[nt], a0, a1, a2, a3, b0, b1);
      }
    }
#pragma unroll
    for (int nt = 0; nt < 16; nt++) {
      const int n = nh * 128 + nt * 8 + 2 * q;
      const size_t base0 = ((size_t)b * NN + n0 + m0 + r) * 256 + n;
      const size_t base1 = base0 + 8 * 256;
      float2 xv0 = *(const float2*)(x + base0);
      float2 xv1 = *(const float2*)(x + base1);
      *(float2*)(out + base0) = make_float2(acc[nt][0] + xv0.x, acc[nt][1] + xv0.y);
      *(float2*)(out + base1) = make_float2(acc[nt][2] + xv1.x, acc[nt][3] + xv1.y);
    }
  }
}

// ===========================================================================
extern "C" void kernel_launch(void* const* d_in, const int* in_sizes, int n_in,
                              void* d_out, int out_size) {
  const float* x = (const float*)d_in[0];
  const float* sq_w = (const float*)d_in[1];
  const float* sq_b = (const float*)d_in[2];
  const float* eid_state = (const float*)d_in[3];
  const float* eid_gw = (const float*)d_in[4];
  const float* eid_gb = (const float*)d_in[5];
  const float* in_w = (const float*)d_in[6];
  const float* in_b = (const float*)d_in[7];
  const float* out_w = (const float*)d_in[8];
  const float* out_b = (const float*)d_in[9];
  const float* n1_g = (const float*)d_in[10];
  const float* n1_b = (const float*)d_in[11];
  const float* n2_g = (const float*)d_in[12];
  const float* n2_b = (const float*)d_in[13];
  const float* f1_w = (const float*)d_in[14];
  const float* f1_b = (const float*)d_in[15];
  const float* f2_w = (const float*)d_in[16];
  const float* f2_b = (const float*)d_in[17];
  float* out = (float*)d_out;

  const int smem_ka = (64 * XP + 64 * WP + 64 * LP + 64) * 4;
  const int smem_kc = (64 * SP + 128 * AP) * 4;
  cudaFuncSetAttribute(k_assign_pool, cudaFuncAttributeMaxDynamicSharedMemorySize, smem_ka);
  cudaFuncSetAttribute(k_decode, cudaFuncAttributeMaxDynamicSharedMemorySize, smem_kc);
  cudaFuncSetAttribute(k_gate, cudaFuncAttributeMaxDynamicSharedMemorySize, MIDQ_SMEM);
  cudaFuncSetAttribute(k_qkv, cudaFuncAttributeMaxDynamicSharedMemorySize, MIDQ_SMEM);
  cudaFuncSetAttribute(k_proj, cudaFuncAttributeMaxDynamicSharedMemorySize, MIDQ_SMEM);
  cudaFuncSetAttribute(k_ffn1, cudaFuncAttributeMaxDynamicSharedMemorySize, MIDQ_SMEM);
  cudaFuncSetAttribute(k_ffn2, cudaFuncAttributeMaxDynamicSharedMemorySize, MIDQ_SMEM);

  float *p_st1, *p_f2p, *p_st2;
  cudaGetSymbolAddress((void**)&p_st1, g_st1);
  cudaGetSymbolAddress((void**)&p_f2p, g_f2p);
  cudaGetSymbolAddress((void**)&p_st2, g_st2);

  k_assign_pool<<<dim3(64, BB), 512, smem_ka>>>(x, sq_w, sq_b);
  k_reduce_st<<<64, 256>>>();
  k_gate<<<dim3(8, BB), 512, MIDQ_SMEM>>>(eid_gw, eid_gb, eid_state);
  k_qkv<<<dim3(24, BB), 512, MIDQ_SMEM>>>(in_w, in_b);
  k_attn<<<32, 1024>>>();
  k_proj<<<dim3(8, BB), 512, MIDQ_SMEM>>>(out_w, out_b);
  k_ffn1<<<dim3(32, BB), 512, MIDQ_SMEM>>>(f1_w, f1_b, n1_g, n1_b);
  k_ffn2<<<dim3(8, BB, 4), 512, MIDQ_SMEM>>>(f2_w, f2_b);
  k_ln<<<64, 256>>>(p_st1, p_f2p, 4, n2_g, n2_b, p_st2);
  k_decode<<<dim3(256, BB), 256, smem_kc>>>(x, out);
}

// round 13
// speedup vs baseline: 1.3401x; 1.2903x over previous
#include <cuda_runtime.h>
#include <cuda_bf16.h>
#include <stdint.h>
#include <math.h>

#define BB 4
#define NN 32768
#define HH 256
#define SS 64

#define XP 268   // xs row pad (floats)
#define WP 268   // sq_w row pad
#define LP 72    // logits/W tile row pad
#define MP 268   // middle-gemm row pad
#define KCP 36   // KC packed row pad (uint32)

// ---------------- scratch (static device allocations only) ----------------
__device__ uint32_t g_Wp[(size_t)BB * NN * 32];      // 16MB packed-bf16 weights
__device__ float g_part[(size_t)256 * 16384];        // 16.8MB pooling partials
__device__ float g_st[BB * SS * HH];
__device__ float g_stg[BB * SS * HH];                // gated st
__device__ float g_qkv[BB * SS * 3 * HH];
__device__ float g_ao[BB * SS * HH];
__device__ float g_pro[BB * SS * HH];                // attn out-proj (pre-LN)
__device__ float g_st1[BB * SS * HH];
__device__ float g_h[BB * SS * 4 * HH];
__device__ float g_f2p[4][BB * SS * HH];             // ffn2 k-split partials
__device__ float g_st2[BB * SS * HH];

// ---- mma helpers ---------------------------------------------------------
__device__ __forceinline__ void mma_tf32(float c[4], uint32_t a0, uint32_t a1,
                                         uint32_t a2, uint32_t a3, uint32_t b0,
                                         uint32_t b1) {
  asm volatile(
      "mma.sync.aligned.m16n8k8.row.col.f32.tf32.tf32.f32 "
      "{%0,%1,%2,%3}, {%4,%5,%6,%7}, {%8,%9}, {%0,%1,%2,%3};\n"
      : "+f"(c[0]), "+f"(c[1]), "+f"(c[2]), "+f"(c[3])
      : "r"(a0), "r"(a1), "r"(a2), "r"(a3), "r"(b0), "r"(b1));
}
__device__ __forceinline__ void mma_bf16(float c[4], uint32_t a0, uint32_t a1,
                                         uint32_t a2, uint32_t a3, uint32_t b0,
                                         uint32_t b1) {
  asm volatile(
      "mma.sync.aligned.m16n8k16.row.col.f32.bf16.bf16.f32 "
      "{%0,%1,%2,%3}, {%4,%5,%6,%7}, {%8,%9}, {%0,%1,%2,%3};\n"
      : "+f"(c[0]), "+f"(c[1]), "+f"(c[2]), "+f"(c[3])
      : "r"(a0), "r"(a1), "r"(a2), "r"(a3), "r"(b0), "r"(b1));
}
#define F2U __float_as_uint

// ===========================================================================
// KA: fused logits + softmax + pooling. 512 threads, grid (64, B).
// 512 tokens per block in 8 tiles of 64. x staging double-buffered via regs.
// Phase A: split-K2 into two logit buffers (no RMW reduce pass).
// Softmax writes W as packed bf16 to g_Wp, fp32 to lg for pooling.
// ===========================================================================
__global__ __launch_bounds__(512, 1) void k_assign_pool(
    const float* __restrict__ x, const float* __restrict__ sq_w,
    const float* __restrict__ sq_b) {
  extern __shared__ float sm[];
  float* xs = sm;                       // [64][XP]
  float* ws = sm + 64 * XP;             // [64][WP]
  float* lg = ws + 64 * WP;             // [64][LP]  (k-half 0 / W)
  float* lg2 = lg + 64 * LP;            // [64][LP]  (k-half 1)
  float* sb = lg2 + 64 * LP;            // [64]

  const int tid = threadIdx.x;
  const int b = blockIdx.y;
  const size_t tok0 = (size_t)blockIdx.x * 512;
  const float* xb = x + (size_t)b * NN * HH;

  for (int i = tid * 4; i < 16384; i += 2048) {
    float4 v = *(const float4*)(sq_w + i);
    *(float4*)(ws + (i >> 8) * WP + (i & 255)) = v;
  }
  if (tid < 64) sb[tid] = sq_b[tid];

  const int wid = tid >> 5, lane = tid & 31;
  const int r = lane >> 2, q = lane & 3;
  const int mA = (wid & 3) * 16;        // phase-A m-tile (4)
  const int nh = ((wid >> 2) & 1) * 4;  // phase-A nt base (2 halves of 4 nt)
  const int kh = (wid >> 3) * 128;      // phase-A k half (2)
  const int hb = wid * 16;              // pooling h tile

  float stacc[8][4];
#pragma unroll
  for (int j = 0; j < 8; j++)
#pragma unroll
    for (int k = 0; k < 4; k++) stacc[j][k] = 0.f;

  // prefetch tile 0 into registers
  float4 pf[8];
  {
    const float* xsrc = xb + tok0 * 256;
#pragma unroll
    for (int it = 0; it < 8; it++)
      pf[it] = *(const float4*)(xsrc + tid * 4 + it * 2048);
  }

  for (int tile = 0; tile < 8; tile++) {
    __syncthreads();  // previous tile's xs/lg consumers done
#pragma unroll
    for (int it = 0; it < 8; it++) {
      const int i = tid * 4 + it * 2048;
      *(float4*)(xs + (i >> 8) * XP + (i & 255)) = pf[it];
    }
    __syncthreads();
    if (tile < 7) {  // issue next tile's loads; overlap with compute below
      const float* xsrc = xb + (tok0 + (tile + 1) * 64) * 256;
#pragma unroll
      for (int it = 0; it < 8; it++)
        pf[it] = *(const float4*)(xsrc + tid * 4 + it * 2048);
    }

    // ---- phase A: logits, warp = m16 x (4 nt), K half = 128 ----
    float lacc[4][4];
#pragma unroll
    for (int j = 0; j < 4; j++)
#pragma unroll
      for (int k = 0; k < 4; k++) lacc[j][k] = 0.f;

    for (int ks = 0; ks < 16; ks++) {
      const int k0 = kh + ks * 8;
      uint32_t a0 = F2U(xs[(mA + r) * XP + k0 + q]);
      uint32_t a1 = F2U(xs[(mA + r + 8) * XP + k0 + q]);
      uint32_t a2 = F2U(xs[(mA + r) * XP + k0 + q + 4]);
      uint32_t a3 = F2U(xs[(mA + r + 8) * XP + k0 + q + 4]);
#pragma unroll
      for (int j = 0; j < 4; j++) {
        const int nt = nh + j;
        uint32_t b0 = F2U(ws[(nt * 8 + r) * WP + k0 + q]);
        uint32_t b1 = F2U(ws[(nt * 8 + r) * WP + k0 + q + 4]);
        mma_tf32(lacc[j], a0, a1, a2, a3, b0, b1);
      }
    }
    {
      float* lgw = (kh == 0) ? lg : lg2;
#pragma unroll
      for (int j = 0; j < 4; j++) {
        const int nt = nh + j;
        lgw[(mA + r) * LP + nt * 8 + 2 * q] = lacc[j][0];
        lgw[(mA + r) * LP + nt * 8 + 2 * q + 1] = lacc[j][1];
        lgw[(mA + r + 8) * LP + nt * 8 + 2 * q] = lacc[j][2];
        lgw[(mA + r + 8) * LP + nt * 8 + 2 * q + 1] = lacc[j][3];
      }
    }
    __syncthreads();

    // ---- softmax: 8 threads per row ----
    {
      const int t = tid >> 3, qq = tid & 7;
      float v[8];
      float mx = -1e30f;
#pragma unroll
      for (int i = 0; i < 8; i++) {
        v[i] = lg[t * LP + qq * 8 + i] + lg2[t * LP + qq * 8 + i] +
               sb[qq * 8 + i];
        mx = fmaxf(mx, v[i]);
      }
      mx = fmaxf(mx, __shfl_xor_sync(0xffffffffu, mx, 1));
      mx = fmaxf(mx, __shfl_xor_sync(0xffffffffu, mx, 2));
      mx = fmaxf(mx, __shfl_xor_sync(0xffffffffu, mx, 4));
      float s = 0.f;
#pragma unroll
      for (int i = 0; i < 8; i++) {
        v[i] = __expf(v[i] - mx);
        s += v[i];
      }
      s += __shfl_xor_sync(0xffffffffu, s, 1);
      s += __shfl_xor_sync(0xffffffffu, s, 2);
      s += __shfl_xor_sync(0xffffffffu, s, 4);
      const float inv = 1.f / s;
      uint32_t* wp =
          g_Wp + ((size_t)b * NN + tok0 + tile * 64 + t) * 32 + qq * 4;
#pragma unroll
      for (int i = 0; i < 8; i++) {
        float w = v[i] * inv;
        v[i] = w;
        lg[t * LP + qq * 8 + i] = w;
      }
#pragma unroll
      for (int i = 0; i < 4; i++) {
        __nv_bfloat162 pk = __floats2bfloat162_rn(v[2 * i], v[2 * i + 1]);
        wp[i] = *(uint32_t*)&pk;
      }
    }
    __syncthreads();

    // ---- pooling: st^T[h][s] += x^T @ Wtile, warp = 16 h rows ----
    for (int ks = 0; ks < 8; ks++) {
      const int k0 = ks * 8;
      uint32_t a0 = F2U(xs[(k0 + q) * XP + hb + r]);
      uint32_t a1 = F2U(xs[(k0 + q) * XP + hb + r + 8]);
      uint32_t a2 = F2U(xs[(k0 + q + 4) * XP + hb + r]);
      uint32_t a3 = F2U(xs[(k0 + q + 4) * XP + hb + r + 8]);
#pragma unroll
      for (int nt = 0; nt < 8; nt++) {
        uint32_t b0 = F2U(lg[(k0 + q) * LP + nt * 8 + r]);
        uint32_t b1 = F2U(lg[(k0 + q + 4) * LP + nt * 8 + r]);
        mma_tf32(stacc[nt], a0, a1, a2, a3, b0, b1);
      }
    }
  }

  float* pp = g_part + (size_t)(b * 64 + blockIdx.x) * 16384;
#pragma unroll
  for (int nt = 0; nt < 8; nt++) {
    const int h0 = hb + r;
    const int s0 = nt * 8 + 2 * q;
    *(float2*)(pp + h0 * 64 + s0) = make_float2(stacc[nt][0], stacc[nt][1]);
    *(float2*)(pp + (h0 + 8) * 64 + s0) = make_float2(stacc[nt][2], stacc[nt][3]);
  }
}

// ===========================================================================
// reduce pooling partials (64 per batch) -> g_st
// ===========================================================================
__global__ __launch_bounds__(256) void k_reduce_st() {
  const int gt = blockIdx.x * 256 + threadIdx.x;  // 0..16383
  const int bb = gt >> 12;
  const int p4 = (gt & 4095) * 4;
  const float* p = g_part + (size_t)bb * 64 * 16384 + p4;
  float4 acc = make_float4(0.f, 0.f, 0.f, 0.f);
#pragma unroll 8
  for (int j = 0; j < 64; j++) {
    float4 v = *(const float4*)(p + (size_t)j * 16384);
    acc.x += v.x; acc.y += v.y; acc.z += v.z; acc.w += v.w;
  }
  const int h = p4 >> 6, s0 = p4 & 63;
  float* dst = g_st + bb * 16384 + h;
  dst[(s0 + 0) * 256] = acc.x;
  dst[(s0 + 1) * 256] = acc.y;
  dst[(s0 + 2) * 256] = acc.z;
  dst[(s0 + 3) * 256] = acc.w;
}

// ===========================================================================
// Middle GEMM via tf32 mma. 512 threads (16 warps = 4 m-tiles x 4 n-tiles),
// 32 output cols per block. smem: As[64][MP] + ws[32][MP].
// ===========================================================================
#define MIDQ_SMEM ((64 * MP + 32 * MP) * 4)

__device__ __forceinline__ void stage_mid(float* As, float* ws,
                                          const float* asrc, int lds,
                                          const float* w, int ldw, int c0,
                                          int koff, int tid) {
  for (int i = tid * 4; i < 16384; i += 2048) {
    float4 v = *(const float4*)(asrc + (i >> 8) * lds + (i & 255));
    *(float4*)(As + (i >> 8) * MP + (i & 255)) = v;
  }
  for (int i = tid * 4; i < 8192; i += 2048) {
    int cl = i >> 8, k = i & 255;
    float4 v = *(const float4*)(w + (size_t)(c0 + cl) * ldw + koff + k);
    *(float4*)(ws + cl * MP + k) = v;
  }
}

__device__ __forceinline__ void mid_mma(const float* __restrict__ As,
                                        const float* __restrict__ ws,
                                        float c[4], int mA, int nq, int r,
                                        int q) {
#pragma unroll 4
  for (int ks = 0; ks < 32; ks++) {
    const int k0 = ks * 8;
    uint32_t a0 = F2U(As[(mA + r) * MP + k0 + q]);
    uint32_t a1 = F2U(As[(mA + r + 8) * MP + k0 + q]);
    uint32_t a2 = F2U(As[(mA + r) * MP + k0 + q + 4]);
    uint32_t a3 = F2U(As[(mA + r + 8) * MP + k0 + q + 4]);
    uint32_t b0 = F2U(ws[(nq * 8 + r) * MP + k0 + q]);
    uint32_t b1 = F2U(ws[(nq * 8 + r) * MP + k0 + q + 4]);
    mma_tf32(c, a0, a1, a2, a3, b0, b1);
  }
}

#define MID_PROLOG                                     \
  const int tid = threadIdx.x;                         \
  const int b = blockIdx.y;                            \
  const int c0 = blockIdx.x * 32;                      \
  const int wid = tid >> 5, lane = tid & 31;           \
  const int r = lane >> 2, q = lane & 3;               \
  const int mA = (wid & 3) * 16, nq = wid >> 2;        \
  const int cg = c0 + nq * 8 + 2 * q;                  \
  const int row0 = mA + r, row1 = mA + r + 8;

// gate: st_gated = st + sigmoid(st @ gw^T + gb) * estate
__global__ __launch_bounds__(512) void k_gate(
    const float* __restrict__ gw, const float* __restrict__ gb,
    const float* __restrict__ estate) {
  extern __shared__ float smm[];
  float* As = smm;
  float* ws = smm + 64 * MP;
  MID_PROLOG
  stage_mid(As, ws, g_st + b * 16384, 256, gw, 256, c0, 0, tid);
  float b0v = gb[cg], b1v = gb[cg + 1];
  float c[4] = {b0v, b1v, b0v, b1v};
  __syncthreads();
  mid_mma(As, ws, c, mA, nq, r, q);
  float s0 = 1.f / (1.f + __expf(-c[0]));
  float s1 = 1.f / (1.f + __expf(-c[1]));
  float s2 = 1.f / (1.f + __expf(-c[2]));
  float s3 = 1.f / (1.f + __expf(-c[3]));
  g_stg[b * 16384 + row0 * 256 + cg] = As[row0 * MP + cg] + s0 * estate[row0 * 256 + cg];
  g_stg[b * 16384 + row0 * 256 + cg + 1] = As[row0 * MP + cg + 1] + s1 * estate[row0 * 256 + cg + 1];
  g_stg[b * 16384 + row1 * 256 + cg] = As[row1 * MP + cg] + s2 * estate[row1 * 256 + cg];
  g_stg[b * 16384 + row1 * 256 + cg + 1] = As[row1 * MP + cg + 1] + s3 * estate[row1 * 256 + cg + 1];
}

__global__ __launch_bounds__(512) void k_qkv(
    const float* __restrict__ in_w, const float* __restrict__ in_b) {
  extern __shared__ float smm[];
  float* As = smm;
  float* ws = smm + 64 * MP;
  MID_PROLOG
  stage_mid(As, ws, g_stg + b * 16384, 256, in_w, 256, c0, 0, tid);
  float b0v = in_b[cg], b1v = in_b[cg + 1];
  float c[4] = {b0v, b1v, b0v, b1v};
  __syncthreads();
  mid_mma(As, ws, c, mA, nq, r, q);
  g_qkv[(b * 64 + row0) * 768 + cg] = c[0];
  g_qkv[(b * 64 + row0) * 768 + cg + 1] = c[1];
  g_qkv[(b * 64 + row1) * 768 + cg] = c[2];
  g_qkv[(b * 64 + row1) * 768 + cg + 1] = c[3];
}

// attention per (b, head): 32 blocks, 1024 threads
__global__ __launch_bounds__(1024) void k_attn() {
  int b = blockIdx.x >> 3, hh = blockIdx.x & 7;
  __shared__ float q[64][32], kk[64][33], vv[64][32], p[64][65];
  int tid = threadIdx.x;
  for (int i = tid; i < 2048; i += 1024) {
    int s = i >> 5, d = i & 31;
    int base = (b * 64 + s) * 768 + hh * 32 + d;
    q[s][d] = g_qkv[base];
    kk[s][d] = g_qkv[base + 256];
    vv[s][d] = g_qkv[base + 512];
  }
  __syncthreads();
  for (int idx = tid; idx < 4096; idx += 1024) {
    int qi = idx >> 6, ki = idx & 63;
    float a = 0.f;
#pragma unroll
    for (int d = 0; d < 32; d++) a += q[qi][d] * kk[ki][d];
    p[qi][ki] = a * 0.17677669529663687f;
  }
  __syncthreads();
  if (tid < 512) {
    const int row = tid >> 3, qq = tid & 7;
    float v[8], mx = -1e30f;
#pragma unroll
    for (int i = 0; i < 8; i++) {
      v[i] = p[row][qq * 8 + i];
      mx = fmaxf(mx, v[i]);
    }
    mx = fmaxf(mx, __shfl_xor_sync(0xffffffffu, mx, 1));
    mx = fmaxf(mx, __shfl_xor_sync(0xffffffffu, mx, 2));
    mx = fmaxf(mx, __shfl_xor_sync(0xffffffffu, mx, 4));
    float s = 0.f;
#pragma unroll
    for (int i = 0; i < 8; i++) { v[i] = __expf(v[i] - mx); s += v[i]; }
    s += __shfl_xor_sync(0xffffffffu, s, 1);
    s += __shfl_xor_sync(0xffffffffu, s, 2);
    s += __shfl_xor_sync(0xffffffffu, s, 4);
    const float inv = 1.f / s;
#pragma unroll
    for (int i = 0; i < 8; i++) p[row][qq * 8 + i] = v[i] * inv;
  }
  __syncthreads();
  for (int idx = tid; idx < 2048; idx += 1024) {
    int qi = idx >> 5, d = idx & 31;
    float a = 0.f;
#pragma unroll
    for (int j = 0; j < 64; j++) a += p[qi][j] * vv[j][d];
    g_ao[(b * 64 + qi) * 256 + hh * 32 + d] = a;
  }
}

__global__ __launch_bounds__(512) void k_proj(
    const float* __restrict__ out_w, const float* __restrict__ out_b) {
  extern __shared__ float smm[];
  float* As = smm;
  float* ws = smm + 64 * MP;
  MID_PROLOG
  stage_mid(As, ws, g_ao + b * 16384, 256, out_w, 256, c0, 0, tid);
  float b0v = out_b[cg], b1v = out_b[cg + 1];
  float c[4] = {b0v, b1v, b0v, b1v};
  __syncthreads();
  mid_mma(As, ws, c, mA, nq, r, q);
  g_pro[(b * 64 + row0) * 256 + cg] = c[0];
  g_pro[(b * 64 + row0) * 256 + cg + 1] = c[1];
  g_pro[(b * 64 + row1) * 256 + cg] = c[2];
  g_pro[(b * 64 + row1) * 256 + cg + 1] = c[3];
}

// LN kernel (used for LN2): out = LN(a + sum of np partials)
__device__ __forceinline__ void ln4_reduce(float yv[4], float mu[4], float var[4],
                                           float wsum[4][8], float wsq[4][8],
                                           int tid) {
  float s1[4], s2[4];
#pragma unroll
  for (int r = 0; r < 4; r++) { s1[r] = yv[r]; s2[r] = yv[r] * yv[r]; }
#pragma unroll
  for (int off = 16; off; off >>= 1)
#pragma unroll
    for (int r = 0; r < 4; r++) {
      s1[r] += __shfl_xor_sync(0xffffffffu, s1[r], off);
      s2[r] += __shfl_xor_sync(0xffffffffu, s2[r], off);
    }
  int w = tid >> 5, lane = tid & 31;
  if (lane == 0)
#pragma unroll
    for (int r = 0; r < 4; r++) { wsum[r][w] = s1[r]; wsq[r][w] = s2[r]; }
  __syncthreads();
#pragma unroll
  for (int r = 0; r < 4; r++) {
    float a = 0.f, bq = 0.f;
#pragma unroll
    for (int ww = 0; ww < 8; ww++) { a += wsum[r][ww]; bq += wsq[r][ww]; }
    mu[r] = a * (1.f / 256.f);
    var[r] = bq * (1.f / 256.f) - mu[r] * mu[r];
  }
}

__global__ __launch_bounds__(256) void k_ln(
    const float* __restrict__ a, const float* __restrict__ parts, int np,
    const float* __restrict__ g, const float* __restrict__ bb,
    float* __restrict__ out) {
  int bs0 = blockIdx.x * 4;
  __shared__ float wsum[4][8], wsq[4][8];
  int tid = threadIdx.x;
  float yv[4];
#pragma unroll
  for (int r = 0; r < 4; r++) {
    int idx = (bs0 + r) * 256 + tid;
    float v = a[idx];
    for (int pz = 0; pz < np; pz++) v += parts[pz * (BB * SS * HH) + idx];
    yv[r] = v;
  }
  float mu[4], var[4];
  ln4_reduce(yv, mu, var, wsum, wsq, tid);
#pragma unroll
  for (int r = 0; r < 4; r++)
    out[(bs0 + r) * 256 + tid] =
        (yv[r] - mu[r]) * rsqrtf(var[r] + 1e-5f) * g[tid] + bb[tid];
}

// ffn1 with fused LN1: y = stg + pro; st1 = LN(y); h = GELU(st1 @ f1_w^T + b)
__global__ __launch_bounds__(512) void k_ffn1(
    const float* __restrict__ f1_w, const float* __restrict__ f1_b,
    const float* __restrict__ n1g, const float* __restrict__ n1b) {
  extern __shared__ float smm[];
  float* As = smm;
  float* ws = smm + 64 * MP;
  __shared__ float sg[256], sbv[256];
  MID_PROLOG
  for (int i = tid * 4; i < 16384; i += 2048) {
    float4 a = *(const float4*)(g_stg + b * 16384 + i);
    float4 p = *(const float4*)(g_pro + b * 16384 + i);
    a.x += p.x; a.y += p.y; a.z += p.z; a.w += p.w;
    *(float4*)(As + (i >> 8) * MP + (i & 255)) = a;
  }
  for (int i = tid * 4; i < 8192; i += 2048) {
    int cl = i >> 8, k = i & 255;
    float4 v = *(const float4*)(f1_w + (size_t)(c0 + cl) * 256 + k);
    *(float4*)(ws + cl * MP + k) = v;
  }
  if (tid < 256) {
    sg[tid] = n1g[tid];
    sbv[tid] = n1b[tid];
  }
  __syncthreads();
  {
    const int cbase = lane * 8;
    for (int rr = wid * 4; rr < wid * 4 + 4; rr++) {
      float4 v1 = *(const float4*)(As + rr * MP + cbase);
      float4 v2 = *(const float4*)(As + rr * MP + cbase + 4);
      float s1 = v1.x + v1.y + v1.z + v1.w + v2.x + v2.y + v2.z + v2.w;
      float s2 = v1.x * v1.x + v1.y * v1.y + v1.z * v1.z + v1.w * v1.w +
                 v2.x * v2.x + v2.y * v2.y + v2.z * v2.z + v2.w * v2.w;
#pragma unroll
      for (int off = 16; off; off >>= 1) {
        s1 += __shfl_xor_sync(0xffffffffu, s1, off);
        s2 += __shfl_xor_sync(0xffffffffu, s2, off);
      }
      float mu = s1 * (1.f / 256.f);
      float var = s2 * (1.f / 256.f) - mu * mu;
      float rs = rsqrtf(var + 1e-5f);
      v1.x = (v1.x - mu) * rs * sg[cbase + 0] + sbv[cbase + 0];
      v1.y = (v1.y - mu) * rs * sg[cbase + 1] + sbv[cbase + 1];
      v1.z = (v1.z - mu) * rs * sg[cbase + 2] + sbv[cbase + 2];
      v1.w = (v1.w - mu) * rs * sg[cbase + 3] + sbv[cbase + 3];
      v2.x = (v2.x - mu) * rs * sg[cbase + 4] + sbv[cbase + 4];
      v2.y = (v2.y - mu) * rs * sg[cbase + 5] + sbv[cbase + 5];
      v2.z = (v2.z - mu) * rs * sg[cbase + 6] + sbv[cbase + 6];
      v2.w = (v2.w - mu) * rs * sg[cbase + 7] + sbv[cbase + 7];
      *(float4*)(As + rr * MP + cbase) = v1;
      *(float4*)(As + rr * MP + cbase + 4) = v2;
    }
  }
  __syncthreads();
  if (blockIdx.x == 0) {
    for (int i = tid * 4; i < 16384; i += 2048)
      *(float4*)(g_st1 + b * 16384 + i) =
          *(const float4*)(As + (i >> 8) * MP + (i & 255));
  }
  float b0v = f1_b[cg], b1v = f1_b[cg + 1];
  float c[4] = {b0v, b1v, b0v, b1v};
  mid_mma(As, ws, c, mA, nq, r, q);
#pragma unroll
  for (int j = 0; j < 4; j++) {
    float v = c[j];
    c[j] = 0.5f * v * (1.f + erff(v * 0.7071067811865475f));
  }
  g_h[(b * 64 + row0) * 1024 + cg] = c[0];
  g_h[(b * 64 + row0) * 1024 + cg + 1] = c[1];
  g_h[(b * 64 + row1) * 1024 + cg] = c[2];
  g_h[(b * 64 + row1) * 1024 + cg + 1] = c[3];
}

// ffn2: K=1024 with 4-way k-split (blockIdx.z)
__global__ __launch_bounds__(512) void k_ffn2(
    const float* __restrict__ f2_w, const float* __restrict__ f2_b) {
  extern __shared__ float smm[];
  float* As = smm;
  float* ws = smm + 64 * MP;
  const int z = blockIdx.z;
  MID_PROLOG
  stage_mid(As, ws, g_h + b * 65536 + z * 256, 1024, f2_w, 1024, c0, z * 256,
            tid);
  float b0v = (z == 0) ? f2_b[cg] : 0.f;
  float b1v = (z == 0) ? f2_b[cg + 1] : 0.f;
  float c[4] = {b0v, b1v, b0v, b1v};
  __syncthreads();
  mid_mma(As, ws, c, mA, nq, r, q);
  g_f2p[z][(b * 64 + row0) * 256 + cg] = c[0];
  g_f2p[z][(b * 64 + row0) * 256 + cg + 1] = c[1];
  g_f2p[z][(b * 64 + row1) * 256 + cg] = c[2];
  g_f2p[z][(b * 64 + row1) * 256 + cg + 1] = c[3];
}

// ===========================================================================
// KC: decode out = W @ st2 + x via bf16 mma m16n8k16. 256 threads,
// 128 tokens/block, 55KB smem -> 2 blocks/SM. grid (256, B).
// smem: st2p [256][KCP] uint32 (st2^T packed bf16 pairs along slots),
//       Wp [128][KCP] uint32 (W packed bf16 pairs along slots).
// ===========================================================================
__global__ __launch_bounds__(256, 2) void k_decode(const float* __restrict__ x,
                                                   float* __restrict__ out) {
  extern __shared__ float sm[];
  uint32_t* st2p = (uint32_t*)sm;             // [256][KCP]
  uint32_t* Wp = (uint32_t*)sm + 256 * KCP;   // [128][KCP]
  const int tid = threadIdx.x;
  const int b = blockIdx.y;
  const int n0 = blockIdx.x * 128;

  // stage st2 transposed + packed: st2p[h][s2] = {st2[2s2][h], st2[2s2+1][h]}
  for (int i = tid; i < 8192; i += 256) {
    int h = i & 255, s2 = i >> 8;
    float v0 = g_st2[b * 16384 + (2 * s2) * 256 + h];
    float v1 = g_st2[b * 16384 + (2 * s2 + 1) * 256 + h];
    __nv_bfloat162 pk = __floats2bfloat162_rn(v0, v1);
    st2p[h * KCP + s2] = *(uint32_t*)&pk;
  }
  // stage W packed rows (already bf16-packed in g_Wp)
  for (int i = tid * 4; i < 4096; i += 1024) {
    int t = i >> 5, s = i & 31;
    uint4 v = *(const uint4*)(g_Wp + ((size_t)b * NN + n0 + t) * 32 + s);
    *(uint4*)(Wp + t * KCP + s) = v;
  }
  __syncthreads();

  const int wid = tid >> 5, lane = tid & 31;
  const int r = lane >> 2, q = lane & 3;
  const int m0 = wid * 16;

  for (int nh = 0; nh < 2; nh++) {
    float acc[16][4];
#pragma unroll
    for (int i = 0; i < 16; i++)
#pragma unroll
      for (int j = 0; j < 4; j++) acc[i][j] = 0.f;

#pragma unroll
    for (int ks = 0; ks < 4; ks++) {
      const int kg = ks * 8;
      uint32_t a0 = Wp[(m0 + r) * KCP + kg + q];
      uint32_t a1 = Wp[(m0 + r + 8) * KCP + kg + q];
      uint32_t a2 = Wp[(m0 + r) * KCP + kg + q + 4];
      uint32_t a3 = Wp[(m0 + r + 8) * KCP + kg + q + 4];
#pragma unroll
      for (int nt = 0; nt < 16; nt++) {
        const int n = nh * 128 + nt * 8;
        uint32_t b0 = st2p[(n + r) * KCP + kg + q];
        uint32_t b1 = st2p[(n + r) * KCP + kg + q + 4];
        mma_bf16(acc[nt], a0, a1, a2, a3, b0, b1);
      }
    }
#pragma unroll
    for (int nt = 0; nt < 16; nt++) {
      const int n = nh * 128 + nt * 8 + 2 * q;
      const size_t base0 = ((size_t)b * NN + n0 + m0 + r) * 256 + n;
      const size_t base1 = base0 + 8 * 256;
      float2 xv0 = *(const float2*)(x + base0);
      float2 xv1 = *(const float2*)(x + base1);
      *(float2*)(out + base0) = make_float2(acc[nt][0] + xv0.x, acc[nt][1] + xv0.y);
      *(float2*)(out + base1) = make_float2(acc[nt][2] + xv1.x, acc[nt][3] + xv1.y);
    }
  }
}

// ===========================================================================
extern "C" void kernel_launch(void* const* d_in, const int* in_sizes, int n_in,
                              void* d_out, int out_size) {
  const float* x = (const float*)d_in[0];
  const float* sq_w = (const float*)d_in[1];
  const float* sq_b = (const float*)d_in[2];
  const float* eid_state = (const float*)d_in[3];
  const float* eid_gw = (const float*)d_in[4];
  const float* eid_gb = (const float*)d_in[5];
  const float* in_w = (const float*)d_in[6];
  const float* in_b = (const float*)d_in[7];
  const float* out_w = (const float*)d_in[8];
  const float* out_b = (const float*)d_in[9];
  const float* n1_g = (const float*)d_in[10];
  const float* n1_b = (const float*)d_in[11];
  const float* n2_g = (const float*)d_in[12];
  const float* n2_b = (const float*)d_in[13];
  const float* f1_w = (const float*)d_in[14];
  const float* f1_b = (const float*)d_in[15];
  const float* f2_w = (const float*)d_in[16];
  const float* f2_b = (const float*)d_in[17];
  float* out = (float*)d_out;

  const int smem_ka = (64 * XP + 64 * WP + 64 * LP * 2 + 64) * 4;
  const int smem_kc = (256 * KCP + 128 * KCP) * 4;
  cudaFuncSetAttribute(k_assign_pool, cudaFuncAttributeMaxDynamicSharedMemorySize, smem_ka);
  cudaFuncSetAttribute(k_decode, cudaFuncAttributeMaxDynamicSharedMemorySize, smem_kc);
  cudaFuncSetAttribute(k_gate, cudaFuncAttributeMaxDynamicSharedMemorySize, MIDQ_SMEM);
  cudaFuncSetAttribute(k_qkv, cudaFuncAttributeMaxDynamicSharedMemorySize, MIDQ_SMEM);
  cudaFuncSetAttribute(k_proj, cudaFuncAttributeMaxDynamicSharedMemorySize, MIDQ_SMEM);
  cudaFuncSetAttribute(k_ffn1, cudaFuncAttributeMaxDynamicSharedMemorySize, MIDQ_SMEM);
  cudaFuncSetAttribute(k_ffn2, cudaFuncAttributeMaxDynamicSharedMemorySize, MIDQ_SMEM);

  float *p_st1, *p_f2p, *p_st2;
  cudaGetSymbolAddress((void**)&p_st1, g_st1);
  cudaGetSymbolAddress((void**)&p_f2p, g_f2p);
  cudaGetSymbolAddress((void**)&p_st2, g_st2);

  k_assign_pool<<<dim3(64, BB), 512, smem_ka>>>(x, sq_w, sq_b);
  k_reduce_st<<<64, 256>>>();
  k_gate<<<dim3(8, BB), 512, MIDQ_SMEM>>>(eid_gw, eid_gb, eid_state);
  k_qkv<<<dim3(24, BB), 512, MIDQ_SMEM>>>(in_w, in_b);
  k_attn<<<32, 1024>>>();
  k_proj<<<dim3(8, BB), 512, MIDQ_SMEM>>>(out_w, out_b);
  k_ffn1<<<dim3(32, BB), 512, MIDQ_SMEM>>>(f1_w, f1_b, n1_g, n1_b);
  k_ffn2<<<dim3(8, BB, 4), 512, MIDQ_SMEM>>>(f2_w, f2_b);
  k_ln<<<64, 256>>>(p_st1, p_f2p, 4, n2_g, n2_b, p_st2);
  k_decode<<<dim3(256, BB), 256, smem_kc>>>(x, out);
}

// round 14
// speedup vs baseline: 1.4025x; 1.0465x over previous
#include <cuda_runtime.h>
#include <cuda_bf16.h>
#include <stdint.h>
#include <math.h>

#define BB 4
#define NN 32768
#define HH 256
#define SS 64

#define XP 268   // xs row pad (floats)
#define PXP 132  // packed bf16 row pad (uint32)
#define LP 72    // logits/W tile row pad
#define MP 268   // middle-gemm row pad
#define KCP 36   // KC packed row pad (uint32)

// ---------------- scratch (static device allocations only) ----------------
__device__ uint32_t g_Wp[(size_t)BB * NN * 32];      // 16MB packed-bf16 weights
__device__ float g_part[(size_t)256 * 16384];        // 16.8MB pooling partials
__device__ float g_st[BB * SS * HH];
__device__ float g_stg[BB * SS * HH];                // gated st
__device__ float g_qkv[BB * SS * 3 * HH];
__device__ float g_ao[BB * SS * HH];
__device__ float g_pro[BB * SS * HH];                // attn out-proj (pre-LN)
__device__ float g_st1[BB * SS * HH];
__device__ float g_h[BB * SS * 4 * HH];
__device__ float g_f2p[4][BB * SS * HH];             // ffn2 k-split partials
__device__ float g_st2[BB * SS * HH];

// ---- mma helpers ---------------------------------------------------------
__device__ __forceinline__ void mma_tf32(float c[4], uint32_t a0, uint32_t a1,
                                         uint32_t a2, uint32_t a3, uint32_t b0,
                                         uint32_t b1) {
  asm volatile(
      "mma.sync.aligned.m16n8k8.row.col.f32.tf32.tf32.f32 "
      "{%0,%1,%2,%3}, {%4,%5,%6,%7}, {%8,%9}, {%0,%1,%2,%3};\n"
      : "+f"(c[0]), "+f"(c[1]), "+f"(c[2]), "+f"(c[3])
      : "r"(a0), "r"(a1), "r"(a2), "r"(a3), "r"(b0), "r"(b1));
}
__device__ __forceinline__ void mma_bf16(float c[4], uint32_t a0, uint32_t a1,
                                         uint32_t a2, uint32_t a3, uint32_t b0,
                                         uint32_t b1) {
  asm volatile(
      "mma.sync.aligned.m16n8k16.row.col.f32.bf16.bf16.f32 "
      "{%0,%1,%2,%3}, {%4,%5,%6,%7}, {%8,%9}, {%0,%1,%2,%3};\n"
      : "+f"(c[0]), "+f"(c[1]), "+f"(c[2]), "+f"(c[3])
      : "r"(a0), "r"(a1), "r"(a2), "r"(a3), "r"(b0), "r"(b1));
}
#define F2U __float_as_uint
#define BF2U(a, b) \
  (*(uint32_t*)&(*(__nv_bfloat162*)&(__nv_bfloat162){0, 0}))

__device__ __forceinline__ uint32_t pack_bf16(float a, float b) {
  __nv_bfloat162 pk = __floats2bfloat162_rn(a, b);
  return *(uint32_t*)&pk;
}

// ===========================================================================
// KA: fused logits + softmax + pooling. 512 threads, grid (64, B).
// 512 tokens per block in 8 tiles of 64. x staging double-buffered via regs.
// Phase A: bf16 m16n8k16 (x and sq_w packed along h), split-K2 dual buffers.
// Pooling: tf32 from fp32 xs copy. Softmax writes packed-bf16 W to g_Wp.
// ===========================================================================
__global__ __launch_bounds__(512, 1) void k_assign_pool(
    const float* __restrict__ x, const float* __restrict__ sq_w,
    const float* __restrict__ sq_b) {
  extern __shared__ float sm[];
  float* xs = sm;                       // [64][XP] fp32 (pooling)
  float* lg = sm + 64 * XP;             // [64][LP]  (k-half 0 / W)
  float* lg2 = lg + 64 * LP;            // [64][LP]  (k-half 1)
  float* sb = lg2 + 64 * LP;            // [64]
  uint32_t* xsp = (uint32_t*)(sb + 64);          // [64][PXP] bf16x2
  uint32_t* wsp = xsp + 64 * PXP;                // [64][PXP] bf16x2

  const int tid = threadIdx.x;
  const int b = blockIdx.y;
  const size_t tok0 = (size_t)blockIdx.x * 512;
  const float* xb = x + (size_t)b * NN * HH;

  for (int i = tid * 4; i < 16384; i += 2048) {
    float4 v = *(const float4*)(sq_w + i);
    const int s = i >> 8, h = i & 255;
    wsp[s * PXP + (h >> 1)] = pack_bf16(v.x, v.y);
    wsp[s * PXP + (h >> 1) + 1] = pack_bf16(v.z, v.w);
  }
  if (tid < 64) sb[tid] = sq_b[tid];

  const int wid = tid >> 5, lane = tid & 31;
  const int r = lane >> 2, q = lane & 3;
  const int mA = (wid & 3) * 16;        // phase-A m-tile (4)
  const int nh = ((wid >> 2) & 1) * 4;  // phase-A nt base (2 halves of 4 nt)
  const int kpb = (wid >> 3) * 64;      // phase-A k half, in bf16 pairs
  const int hb = wid * 16;              // pooling h tile

  float stacc[8][4];
#pragma unroll
  for (int j = 0; j < 8; j++)
#pragma unroll
    for (int k = 0; k < 4; k++) stacc[j][k] = 0.f;

  // prefetch tile 0 into registers
  float4 pf[8];
  {
    const float* xsrc = xb + tok0 * 256;
#pragma unroll
    for (int it = 0; it < 8; it++)
      pf[it] = *(const float4*)(xsrc + tid * 4 + it * 2048);
  }

  for (int tile = 0; tile < 8; tile++) {
    __syncthreads();  // previous tile's xs/lg consumers done
#pragma unroll
    for (int it = 0; it < 8; it++) {
      const int i = tid * 4 + it * 2048;
      const int t = i >> 8, h = i & 255;
      *(float4*)(xs + t * XP + h) = pf[it];
      xsp[t * PXP + (h >> 1)] = pack_bf16(pf[it].x, pf[it].y);
      xsp[t * PXP + (h >> 1) + 1] = pack_bf16(pf[it].z, pf[it].w);
    }
    __syncthreads();
    if (tile < 7) {  // issue next tile's loads; overlap with compute below
      const float* xsrc = xb + (tok0 + (tile + 1) * 64) * 256;
#pragma unroll
      for (int it = 0; it < 8; it++)
        pf[it] = *(const float4*)(xsrc + tid * 4 + it * 2048);
    }

    // ---- phase A: logits via bf16 m16n8k16, warp = m16 x 4nt, K half ----
    float lacc[4][4];
#pragma unroll
    for (int j = 0; j < 4; j++)
#pragma unroll
      for (int k = 0; k < 4; k++) lacc[j][k] = 0.f;

#pragma unroll
    for (int ks = 0; ks < 8; ks++) {
      const int kp0 = kpb + ks * 8;
      uint32_t a0 = xsp[(mA + r) * PXP + kp0 + q];
      uint32_t a1 = xsp[(mA + r + 8) * PXP + kp0 + q];
      uint32_t a2 = xsp[(mA + r) * PXP + kp0 + q + 4];
      uint32_t a3 = xsp[(mA + r + 8) * PXP + kp0 + q + 4];
#pragma unroll
      for (int j = 0; j < 4; j++) {
        const int nt = nh + j;
        uint32_t b0 = wsp[(nt * 8 + r) * PXP + kp0 + q];
        uint32_t b1 = wsp[(nt * 8 + r) * PXP + kp0 + q + 4];
        mma_bf16(lacc[j], a0, a1, a2, a3, b0, b1);
      }
    }
    {
      float* lgw = (kpb == 0) ? lg : lg2;
#pragma unroll
      for (int j = 0; j < 4; j++) {
        const int nt = nh + j;
        lgw[(mA + r) * LP + nt * 8 + 2 * q] = lacc[j][0];
        lgw[(mA + r) * LP + nt * 8 + 2 * q + 1] = lacc[j][1];
        lgw[(mA + r + 8) * LP + nt * 8 + 2 * q] = lacc[j][2];
        lgw[(mA + r + 8) * LP + nt * 8 + 2 * q + 1] = lacc[j][3];
      }
    }
    __syncthreads();

    // ---- softmax: 8 threads per row ----
    {
      const int t = tid >> 3, qq = tid & 7;
      float v[8];
      float mx = -1e30f;
#pragma unroll
      for (int i = 0; i < 8; i++) {
        v[i] = lg[t * LP + qq * 8 + i] + lg2[t * LP + qq * 8 + i] +
               sb[qq * 8 + i];
        mx = fmaxf(mx, v[i]);
      }
      mx = fmaxf(mx, __shfl_xor_sync(0xffffffffu, mx, 1));
      mx = fmaxf(mx, __shfl_xor_sync(0xffffffffu, mx, 2));
      mx = fmaxf(mx, __shfl_xor_sync(0xffffffffu, mx, 4));
      float s = 0.f;
#pragma unroll
      for (int i = 0; i < 8; i++) {
        v[i] = __expf(v[i] - mx);
        s += v[i];
      }
      s += __shfl_xor_sync(0xffffffffu, s, 1);
      s += __shfl_xor_sync(0xffffffffu, s, 2);
      s += __shfl_xor_sync(0xffffffffu, s, 4);
      const float inv = 1.f / s;
      uint32_t* wp =
          g_Wp + ((size_t)b * NN + tok0 + tile * 64 + t) * 32 + qq * 4;
#pragma unroll
      for (int i = 0; i < 8; i++) {
        float w = v[i] * inv;
        v[i] = w;
        lg[t * LP + qq * 8 + i] = w;
      }
#pragma unroll
      for (int i = 0; i < 4; i++)
        wp[i] = pack_bf16(v[2 * i], v[2 * i + 1]);
    }
    __syncthreads();

    // ---- pooling: st^T[h][s] += x^T @ Wtile (tf32), warp = 16 h rows ----
    for (int ks = 0; ks < 8; ks++) {
      const int k0 = ks * 8;
      uint32_t a0 = F2U(xs[(k0 + q) * XP + hb + r]);
      uint32_t a1 = F2U(xs[(k0 + q) * XP + hb + r + 8]);
      uint32_t a2 = F2U(xs[(k0 + q + 4) * XP + hb + r]);
      uint32_t a3 = F2U(xs[(k0 + q + 4) * XP + hb + r + 8]);
#pragma unroll
      for (int nt = 0; nt < 8; nt++) {
        uint32_t b0 = F2U(lg[(k0 + q) * LP + nt * 8 + r]);
        uint32_t b1 = F2U(lg[(k0 + q + 4) * LP + nt * 8 + r]);
        mma_tf32(stacc[nt], a0, a1, a2, a3, b0, b1);
      }
    }
  }

  float* pp = g_part + (size_t)(b * 64 + blockIdx.x) * 16384;
#pragma unroll
  for (int nt = 0; nt < 8; nt++) {
    const int h0 = hb + r;
    const int s0 = nt * 8 + 2 * q;
    *(float2*)(pp + h0 * 64 + s0) = make_float2(stacc[nt][0], stacc[nt][1]);
    *(float2*)(pp + (h0 + 8) * 64 + s0) = make_float2(stacc[nt][2], stacc[nt][3]);
  }
}

// ===========================================================================
// reduce pooling partials (64 per batch) -> g_st
// ===========================================================================
__global__ __launch_bounds__(256) void k_reduce_st() {
  const int gt = blockIdx.x * 256 + threadIdx.x;  // 0..16383
  const int bb = gt >> 12;
  const int p4 = (gt & 4095) * 4;
  const float* p = g_part + (size_t)bb * 64 * 16384 + p4;
  float4 acc = make_float4(0.f, 0.f, 0.f, 0.f);
#pragma unroll 8
  for (int j = 0; j < 64; j++) {
    float4 v = *(const float4*)(p + (size_t)j * 16384);
    acc.x += v.x; acc.y += v.y; acc.z += v.z; acc.w += v.w;
  }
  const int h = p4 >> 6, s0 = p4 & 63;
  float* dst = g_st + bb * 16384 + h;
  dst[(s0 + 0) * 256] = acc.x;
  dst[(s0 + 1) * 256] = acc.y;
  dst[(s0 + 2) * 256] = acc.z;
  dst[(s0 + 3) * 256] = acc.w;
}

// ===========================================================================
// Middle GEMM via tf32 mma. 512 threads (16 warps = 4 m-tiles x 4 n-tiles),
// 32 output cols per block. smem: As[64][MP] + ws[32][MP].
// ===========================================================================
#define MIDQ_SMEM ((64 * MP + 32 * MP) * 4)

__device__ __forceinline__ void stage_mid(float* As, float* ws,
                                          const float* asrc, int lds,
                                          const float* w, int ldw, int c0,
                                          int koff, int tid) {
  for (int i = tid * 4; i < 16384; i += 2048) {
    float4 v = *(const float4*)(asrc + (i >> 8) * lds + (i & 255));
    *(float4*)(As + (i >> 8) * MP + (i & 255)) = v;
  }
  for (int i = tid * 4; i < 8192; i += 2048) {
    int cl = i >> 8, k = i & 255;
    float4 v = *(const float4*)(w + (size_t)(c0 + cl) * ldw + koff + k);
    *(float4*)(ws + cl * MP + k) = v;
  }
}

__device__ __forceinline__ void mid_mma(const float* __restrict__ As,
                                        const float* __restrict__ ws,
                                        float c[4], int mA, int nq, int r,
                                        int q) {
#pragma unroll 4
  for (int ks = 0; ks < 32; ks++) {
    const int k0 = ks * 8;
    uint32_t a0 = F2U(As[(mA + r) * MP + k0 + q]);
    uint32_t a1 = F2U(As[(mA + r + 8) * MP + k0 + q]);
    uint32_t a2 = F2U(As[(mA + r) * MP + k0 + q + 4]);
    uint32_t a3 = F2U(As[(mA + r + 8) * MP + k0 + q + 4]);
    uint32_t b0 = F2U(ws[(nq * 8 + r) * MP + k0 + q]);
    uint32_t b1 = F2U(ws[(nq * 8 + r) * MP + k0 + q + 4]);
    mma_tf32(c, a0, a1, a2, a3, b0, b1);
  }
}

#define MID_PROLOG                                     \
  const int tid = threadIdx.x;                         \
  const int b = blockIdx.y;                            \
  const int c0 = blockIdx.x * 32;                      \
  const int wid = tid >> 5, lane = tid & 31;           \
  const int r = lane >> 2, q = lane & 3;               \
  const int mA = (wid & 3) * 16, nq = wid >> 2;        \
  const int cg = c0 + nq * 8 + 2 * q;                  \
  const int row0 = mA + r, row1 = mA + r + 8;

// gate: st_gated = st + sigmoid(st @ gw^T + gb) * estate
__global__ __launch_bounds__(512) void k_gate(
    const float* __restrict__ gw, const float* __restrict__ gb,
    const float* __restrict__ estate) {
  extern __shared__ float smm[];
  float* As = smm;
  float* ws = smm + 64 * MP;
  MID_PROLOG
  stage_mid(As, ws, g_st + b * 16384, 256, gw, 256, c0, 0, tid);
  float b0v = gb[cg], b1v = gb[cg + 1];
  float c[4] = {b0v, b1v, b0v, b1v};
  __syncthreads();
  mid_mma(As, ws, c, mA, nq, r, q);
  float s0 = 1.f / (1.f + __expf(-c[0]));
  float s1 = 1.f / (1.f + __expf(-c[1]));
  float s2 = 1.f / (1.f + __expf(-c[2]));
  float s3 = 1.f / (1.f + __expf(-c[3]));
  g_stg[b * 16384 + row0 * 256 + cg] = As[row0 * MP + cg] + s0 * estate[row0 * 256 + cg];
  g_stg[b * 16384 + row0 * 256 + cg + 1] = As[row0 * MP + cg + 1] + s1 * estate[row0 * 256 + cg + 1];
  g_stg[b * 16384 + row1 * 256 + cg] = As[row1 * MP + cg] + s2 * estate[row1 * 256 + cg];
  g_stg[b * 16384 + row1 * 256 + cg + 1] = As[row1 * MP + cg + 1] + s3 * estate[row1 * 256 + cg + 1];
}

__global__ __launch_bounds__(512) void k_qkv(
    const float* __restrict__ in_w, const float* __restrict__ in_b) {
  extern __shared__ float smm[];
  float* As = smm;
  float* ws = smm + 64 * MP;
  MID_PROLOG
  stage_mid(As, ws, g_stg + b * 16384, 256, in_w, 256, c0, 0, tid);
  float b0v = in_b[cg], b1v = in_b[cg + 1];
  float c[4] = {b0v, b1v, b0v, b1v};
  __syncthreads();
  mid_mma(As, ws, c, mA, nq, r, q);
  g_qkv[(b * 64 + row0) * 768 + cg] = c[0];
  g_qkv[(b * 64 + row0) * 768 + cg + 1] = c[1];
  g_qkv[(b * 64 + row1) * 768 + cg] = c[2];
  g_qkv[(b * 64 + row1) * 768 + cg + 1] = c[3];
}

// attention per (b, head): 32 blocks, 1024 threads
__global__ __launch_bounds__(1024) void k_attn() {
  int b = blockIdx.x >> 3, hh = blockIdx.x & 7;
  __shared__ float q[64][32], kk[64][33], vv[64][32], p[64][65];
  int tid = threadIdx.x;
  for (int i = tid; i < 2048; i += 1024) {
    int s = i >> 5, d = i & 31;
    int base = (b * 64 + s) * 768 + hh * 32 + d;
    q[s][d] = g_qkv[base];
    kk[s][d] = g_qkv[base + 256];
    vv[s][d] = g_qkv[base + 512];
  }
  __syncthreads();
  for (int idx = tid; idx < 4096; idx += 1024) {
    int qi = idx >> 6, ki = idx & 63;
    float a = 0.f;
#pragma unroll
    for (int d = 0; d < 32; d++) a += q[qi][d] * kk[ki][d];
    p[qi][ki] = a * 0.17677669529663687f;
  }
  __syncthreads();
  if (tid < 512) {
    const int row = tid >> 3, qq = tid & 7;
    float v[8], mx = -1e30f;
#pragma unroll
    for (int i = 0; i < 8; i++) {
      v[i] = p[row][qq * 8 + i];
      mx = fmaxf(mx, v[i]);
    }
    mx = fmaxf(mx, __shfl_xor_sync(0xffffffffu, mx, 1));
    mx = fmaxf(mx, __shfl_xor_sync(0xffffffffu, mx, 2));
    mx = fmaxf(mx, __shfl_xor_sync(0xffffffffu, mx, 4));
    float s = 0.f;
#pragma unroll
    for (int i = 0; i < 8; i++) { v[i] = __expf(v[i] - mx); s += v[i]; }
    s += __shfl_xor_sync(0xffffffffu, s, 1);
    s += __shfl_xor_sync(0xffffffffu, s, 2);
    s += __shfl_xor_sync(0xffffffffu, s, 4);
    const float inv = 1.f / s;
#pragma unroll
    for (int i = 0; i < 8; i++) p[row][qq * 8 + i] = v[i] * inv;
  }
  __syncthreads();
  for (int idx = tid; idx < 2048; idx += 1024) {
    int qi = idx >> 5, d = idx & 31;
    float a = 0.f;
#pragma unroll
    for (int j = 0; j < 64; j++) a += p[qi][j] * vv[j][d];
    g_ao[(b * 64 + qi) * 256 + hh * 32 + d] = a;
  }
}

__global__ __launch_bounds__(512) void k_proj(
    const float* __restrict__ out_w, const float* __restrict__ out_b) {
  extern __shared__ float smm[];
  float* As = smm;
  float* ws = smm + 64 * MP;
  MID_PROLOG
  stage_mid(As, ws, g_ao + b * 16384, 256, out_w, 256, c0, 0, tid);
  float b0v = out_b[cg], b1v = out_b[cg + 1];
  float c[4] = {b0v, b1v, b0v, b1v};
  __syncthreads();
  mid_mma(As, ws, c, mA, nq, r, q);
  g_pro[(b * 64 + row0) * 256 + cg] = c[0];
  g_pro[(b * 64 + row0) * 256 + cg + 1] = c[1];
  g_pro[(b * 64 + row1) * 256 + cg] = c[2];
  g_pro[(b * 64 + row1) * 256 + cg + 1] = c[3];
}

// LN kernel (used for LN2): out = LN(a + sum of np partials)
__device__ __forceinline__ void ln4_reduce(float yv[4], float mu[4], float var[4],
                                           float wsum[4][8], float wsq[4][8],
                                           int tid) {
  float s1[4], s2[4];
#pragma unroll
  for (int r = 0; r < 4; r++) { s1[r] = yv[r]; s2[r] = yv[r] * yv[r]; }
#pragma unroll
  for (int off = 16; off; off >>= 1)
#pragma unroll
    for (int r = 0; r < 4; r++) {
      s1[r] += __shfl_xor_sync(0xffffffffu, s1[r], off);
      s2[r] += __shfl_xor_sync(0xffffffffu, s2[r], off);
    }
  int w = tid >> 5, lane = tid & 31;
  if (lane == 0)
#pragma unroll
    for (int r = 0; r < 4; r++) { wsum[r][w] = s1[r]; wsq[r][w] = s2[r]; }
  __syncthreads();
#pragma unroll
  for (int r = 0; r < 4; r++) {
    float a = 0.f, bq = 0.f;
#pragma unroll
    for (int ww = 0; ww < 8; ww++) { a += wsum[r][ww]; bq += wsq[r][ww]; }
    mu[r] = a * (1.f / 256.f);
    var[r] = bq * (1.f / 256.f) - mu[r] * mu[r];
  }
}

__global__ __launch_bounds__(256) void k_ln(
    const float* __restrict__ a, const float* __restrict__ parts, int np,
    const float* __restrict__ g, const float* __restrict__ bb,
    float* __restrict__ out) {
  int bs0 = blockIdx.x * 4;
  __shared__ float wsum[4][8], wsq[4][8];
  int tid = threadIdx.x;
  float yv[4];
#pragma unroll
  for (int r = 0; r < 4; r++) {
    int idx = (bs0 + r) * 256 + tid;
    float v = a[idx];
    for (int pz = 0; pz < np; pz++) v += parts[pz * (BB * SS * HH) + idx];
    yv[r] = v;
  }
  float mu[4], var[4];
  ln4_reduce(yv, mu, var, wsum, wsq, tid);
#pragma unroll
  for (int r = 0; r < 4; r++)
    out[(bs0 + r) * 256 + tid] =
        (yv[r] - mu[r]) * rsqrtf(var[r] + 1e-5f) * g[tid] + bb[tid];
}

// ffn1 with fused LN1: y = stg + pro; st1 = LN(y); h = GELU(st1 @ f1_w^T + b)
__global__ __launch_bounds__(512) void k_ffn1(
    const float* __restrict__ f1_w, const float* __restrict__ f1_b,
    const float* __restrict__ n1g, const float* __restrict__ n1b) {
  extern __shared__ float smm[];
  float* As = smm;
  float* ws = smm + 64 * MP;
  __shared__ float sg[256], sbv[256];
  MID_PROLOG
  for (int i = tid * 4; i < 16384; i += 2048) {
    float4 a = *(const float4*)(g_stg + b * 16384 + i);
    float4 p = *(const float4*)(g_pro + b * 16384 + i);
    a.x += p.x; a.y += p.y; a.z += p.z; a.w += p.w;
    *(float4*)(As + (i >> 8) * MP + (i & 255)) = a;
  }
  for (int i = tid * 4; i < 8192; i += 2048) {
    int cl = i >> 8, k = i & 255;
    float4 v = *(const float4*)(f1_w + (size_t)(c0 + cl) * 256 + k);
    *(float4*)(ws + cl * MP + k) = v;
  }
  if (tid < 256) {
    sg[tid] = n1g[tid];
    sbv[tid] = n1b[tid];
  }
  __syncthreads();
  {
    const int cbase = lane * 8;
    for (int rr = wid * 4; rr < wid * 4 + 4; rr++) {
      float4 v1 = *(const float4*)(As + rr * MP + cbase);
      float4 v2 = *(const float4*)(As + rr * MP + cbase + 4);
      float s1 = v1.x + v1.y + v1.z + v1.w + v2.x + v2.y + v2.z + v2.w;
      float s2 = v1.x * v1.x + v1.y * v1.y + v1.z * v1.z + v1.w * v1.w +
                 v2.x * v2.x + v2.y * v2.y + v2.z * v2.z + v2.w * v2.w;
#pragma unroll
      for (int off = 16; off; off >>= 1) {
        s1 += __shfl_xor_sync(0xffffffffu, s1, off);
        s2 += __shfl_xor_sync(0xffffffffu, s2, off);
      }
      float mu = s1 * (1.f / 256.f);
      float var = s2 * (1.f / 256.f) - mu * mu;
      float rs = rsqrtf(var + 1e-5f);
      v1.x = (v1.x - mu) * rs * sg[cbase + 0] + sbv[cbase + 0];
      v1.y = (v1.y - mu) * rs * sg[cbase + 1] + sbv[cbase + 1];
      v1.z = (v1.z - mu) * rs * sg[cbase + 2] + sbv[cbase + 2];
      v1.w = (v1.w - mu) * rs * sg[cbase + 3] + sbv[cbase + 3];
      v2.x = (v2.x - mu) * rs * sg[cbase + 4] + sbv[cbase + 4];
      v2.y = (v2.y - mu) * rs * sg[cbase + 5] + sbv[cbase + 5];
      v2.z = (v2.z - mu) * rs * sg[cbase + 6] + sbv[cbase + 6];
      v2.w = (v2.w - mu) * rs * sg[cbase + 7] + sbv[cbase + 7];
      *(float4*)(As + rr * MP + cbase) = v1;
      *(float4*)(As + rr * MP + cbase + 4) = v2;
    }
  }
  __syncthreads();
  if (blockIdx.x == 0) {
    for (int i = tid * 4; i < 16384; i += 2048)
      *(float4*)(g_st1 + b * 16384 + i) =
          *(const float4*)(As + (i >> 8) * MP + (i & 255));
  }
  float b0v = f1_b[cg], b1v = f1_b[cg + 1];
  float c[4] = {b0v, b1v, b0v, b1v};
  mid_mma(As, ws, c, mA, nq, r, q);
#pragma unroll
  for (int j = 0; j < 4; j++) {
    float v = c[j];
    c[j] = 0.5f * v * (1.f + erff(v * 0.7071067811865475f));
  }
  g_h[(b * 64 + row0) * 1024 + cg] = c[0];
  g_h[(b * 64 + row0) * 1024 + cg + 1] = c[1];
  g_h[(b * 64 + row1) * 1024 + cg] = c[2];
  g_h[(b * 64 + row1) * 1024 + cg + 1] = c[3];
}

// ffn2: K=1024 with 4-way k-split (blockIdx.z)
__global__ __launch_bounds__(512) void k_ffn2(
    const float* __restrict__ f2_w, const float* __restrict__ f2_b) {
  extern __shared__ float smm[];
  float* As = smm;
  float* ws = smm + 64 * MP;
  const int z = blockIdx.z;
  MID_PROLOG
  stage_mid(As, ws, g_h + b * 65536 + z * 256, 1024, f2_w, 1024, c0, z * 256,
            tid);
  float b0v = (z == 0) ? f2_b[cg] : 0.f;
  float b1v = (z == 0) ? f2_b[cg + 1] : 0.f;
  float c[4] = {b0v, b1v, b0v, b1v};
  __syncthreads();
  mid_mma(As, ws, c, mA, nq, r, q);
  g_f2p[z][(b * 64 + row0) * 256 + cg] = c[0];
  g_f2p[z][(b * 64 + row0) * 256 + cg + 1] = c[1];
  g_f2p[z][(b * 64 + row1) * 256 + cg] = c[2];
  g_f2p[z][(b * 64 + row1) * 256 + cg + 1] = c[3];
}

// ===========================================================================
// KC: decode out = W @ st2 + x via bf16 mma m16n8k16. 256 threads,
// 128 tokens/block, 55KB smem -> 2 blocks/SM. grid (256, B).
// ===========================================================================
__global__ __launch_bounds__(256, 2) void k_decode(const float* __restrict__ x,
                                                   float* __restrict__ out) {
  extern __shared__ float sm[];
  uint32_t* st2p = (uint32_t*)sm;             // [256][KCP]
  uint32_t* Wp = (uint32_t*)sm + 256 * KCP;   // [128][KCP]
  const int tid = threadIdx.x;
  const int b = blockIdx.y;
  const int n0 = blockIdx.x * 128;

  for (int i = tid; i < 8192; i += 256) {
    int h = i & 255, s2 = i >> 8;
    float v0 = g_st2[b * 16384 + (2 * s2) * 256 + h];
    float v1 = g_st2[b * 16384 + (2 * s2 + 1) * 256 + h];
    st2p[h * KCP + s2] = pack_bf16(v0, v1);
  }
  for (int i = tid * 4; i < 4096; i += 1024) {
    int t = i >> 5, s = i & 31;
    uint4 v = *(const uint4*)(g_Wp + ((size_t)b * NN + n0 + t) * 32 + s);
    *(uint4*)(Wp + t * KCP + s) = v;
  }
  __syncthreads();

  const int wid = tid >> 5, lane = tid & 31;
  const int r = lane >> 2, q = lane & 3;
  const int m0 = wid * 16;

  for (int nh = 0; nh < 2; nh++) {
    float acc[16][4];
#pragma unroll
    for (int i = 0; i < 16; i++)
#pragma unroll
      for (int j = 0; j < 4; j++) acc[i][j] = 0.f;

#pragma unroll
    for (int ks = 0; ks < 4; ks++) {
      const int kg = ks * 8;
      uint32_t a0 = Wp[(m0 + r) * KCP + kg + q];
      uint32_t a1 = Wp[(m0 + r + 8) * KCP + kg + q];
      uint32_t a2 = Wp[(m0 + r) * KCP + kg + q + 4];
      uint32_t a3 = Wp[(m0 + r + 8) * KCP + kg + q + 4];
#pragma unroll
      for (int nt = 0; nt < 16; nt++) {
        const int n = nh * 128 + nt * 8;
        uint32_t b0 = st2p[(n + r) * KCP + kg + q];
        uint32_t b1 = st2p[(n + r) * KCP + kg + q + 4];
        mma_bf16(acc[nt], a0, a1, a2, a3, b0, b1);
      }
    }
#pragma unroll
    for (int nt = 0; nt < 16; nt++) {
      const int n = nh * 128 + nt * 8 + 2 * q;
      const size_t base0 = ((size_t)b * NN + n0 + m0 + r) * 256 + n;
      const size_t base1 = base0 + 8 * 256;
      float2 xv0 = *(const float2*)(x + base0);
      float2 xv1 = *(const float2*)(x + base1);
      *(float2*)(out + base0) = make_float2(acc[nt][0] + xv0.x, acc[nt][1] + xv0.y);
      *(float2*)(out + base1) = make_float2(acc[nt][2] + xv1.x, acc[nt][3] + xv1.y);
    }
  }
}

// ===========================================================================
extern "C" void kernel_launch(void* const* d_in, const int* in_sizes, int n_in,
                              void* d_out, int out_size) {
  const float* x = (const float*)d_in[0];
  const float* sq_w = (const float*)d_in[1];
  const float* sq_b = (const float*)d_in[2];
  const float* eid_state = (const float*)d_in[3];
  const float* eid_gw = (const float*)d_in[4];
  const float* eid_gb = (const float*)d_in[5];
  const float* in_w = (const float*)d_in[6];
  const float* in_b = (const float*)d_in[7];
  const float* out_w = (const float*)d_in[8];
  const float* out_b = (const float*)d_in[9];
  const float* n1_g = (const float*)d_in[10];
  const float* n1_b = (const float*)d_in[11];
  const float* n2_g = (const float*)d_in[12];
  const float* n2_b = (const float*)d_in[13];
  const float* f1_w = (const float*)d_in[14];
  const float* f1_b = (const float*)d_in[15];
  const float* f2_w = (const float*)d_in[16];
  const float* f2_b = (const float*)d_in[17];
  float* out = (float*)d_out;

  const int smem_ka =
      (64 * XP + 64 * LP * 2 + 64 + 64 * PXP * 2) * 4;  // ~173KB
  const int smem_kc = (256 * KCP + 128 * KCP) * 4;
  cudaFuncSetAttribute(k_assign_pool, cudaFuncAttributeMaxDynamicSharedMemorySize, smem_ka);
  cudaFuncSetAttribute(k_decode, cudaFuncAttributeMaxDynamicSharedMemorySize, smem_kc);
  cudaFuncSetAttribute(k_gate, cudaFuncAttributeMaxDynamicSharedMemorySize, MIDQ_SMEM);
  cudaFuncSetAttribute(k_qkv, cudaFuncAttributeMaxDynamicSharedMemorySize, MIDQ_SMEM);
  cudaFuncSetAttribute(k_proj, cudaFuncAttributeMaxDynamicSharedMemorySize, MIDQ_SMEM);
  cudaFuncSetAttribute(k_ffn1, cudaFuncAttributeMaxDynamicSharedMemorySize, MIDQ_SMEM);
  cudaFuncSetAttribute(k_ffn2, cudaFuncAttributeMaxDynamicSharedMemorySize, MIDQ_SMEM);

  float *p_st1, *p_f2p, *p_st2;
  cudaGetSymbolAddress((void**)&p_st1, g_st1);
  cudaGetSymbolAddress((void**)&p_f2p, g_f2p);
  cudaGetSymbolAddress((void**)&p_st2, g_st2);

  k_assign_pool<<<dim3(64, BB), 512, smem_ka>>>(x, sq_w, sq_b);
  k_reduce_st<<<64, 256>>>();
  k_gate<<<dim3(8, BB), 512, MIDQ_SMEM>>>(eid_gw, eid_gb, eid_state);
  k_qkv<<<dim3(24, BB), 512, MIDQ_SMEM>>>(in_w, in_b);
  k_attn<<<32, 1024>>>();
  k_proj<<<dim3(8, BB), 512, MIDQ_SMEM>>>(out_w, out_b);
  k_ffn1<<<dim3(32, BB), 512, MIDQ_SMEM>>>(f1_w, f1_b, n1_g, n1_b);
  k_ffn2<<<dim3(8, BB, 4), 512, MIDQ_SMEM>>>(f2_w, f2_b);
  k_ln<<<64, 256>>>(p_st1, p_f2p, 4, n2_g, n2_b, p_st2);
  k_decode<<<dim3(256, BB), 256, smem_kc>>>(x, out);
}

// round 16
// speedup vs baseline: 1.4108x; 1.0060x over previous
#include <cuda_runtime.h>
#include <cuda_bf16.h>
#include <stdint.h>
#include <math.h>

#define BB 4
#define NN 32768
#define HH 256
#define SS 64

#define XP 268   // xs row pad (floats)
#define PXP 132  // packed bf16 row pad (uint32)
#define LP 72    // logits/W tile row pad
#define MP 268   // middle-gemm row pad
#define KCP 36   // KC packed row pad (uint32)
#define KAB 74   // KA blocks per batch (2*148 total)

// ---------------- scratch (static device allocations only) ----------------
__device__ uint32_t g_Wp[(size_t)BB * NN * 32];      // 16MB packed-bf16 weights
__device__ float g_part[(size_t)BB * KAB * 16384];   // pooling partials
__device__ float g_st[BB * SS * HH];
__device__ float g_stg[BB * SS * HH];                // gated st
__device__ float g_qkv[BB * SS * 3 * HH];
__device__ float g_ao[BB * SS * HH];
__device__ float g_pro[BB * SS * HH];                // attn out-proj (pre-LN)
__device__ float g_st1[BB * SS * HH];
__device__ uint32_t g_hp[BB * SS * 512];             // packed-bf16 GELU acts
__device__ float g_f2p[4][BB * SS * HH];             // ffn2 k-split partials
__device__ float g_st2[BB * SS * HH];

// ---- mma helpers ---------------------------------------------------------
__device__ __forceinline__ void mma_tf32(float c[4], uint32_t a0, uint32_t a1,
                                         uint32_t a2, uint32_t a3, uint32_t b0,
                                         uint32_t b1) {
  asm volatile(
      "mma.sync.aligned.m16n8k8.row.col.f32.tf32.tf32.f32 "
      "{%0,%1,%2,%3}, {%4,%5,%6,%7}, {%8,%9}, {%0,%1,%2,%3};\n"
      : "+f"(c[0]), "+f"(c[1]), "+f"(c[2]), "+f"(c[3])
      : "r"(a0), "r"(a1), "r"(a2), "r"(a3), "r"(b0), "r"(b1));
}
__device__ __forceinline__ void mma_bf16(float c[4], uint32_t a0, uint32_t a1,
                                         uint32_t a2, uint32_t a3, uint32_t b0,
                                         uint32_t b1) {
  asm volatile(
      "mma.sync.aligned.m16n8k16.row.col.f32.bf16.bf16.f32 "
      "{%0,%1,%2,%3}, {%4,%5,%6,%7}, {%8,%9}, {%0,%1,%2,%3};\n"
      : "+f"(c[0]), "+f"(c[1]), "+f"(c[2]), "+f"(c[3])
      : "r"(a0), "r"(a1), "r"(a2), "r"(a3), "r"(b0), "r"(b1));
}
#define F2U __float_as_uint

__device__ __forceinline__ uint32_t pack_bf16(float a, float b) {
  __nv_bfloat162 pk = __floats2bfloat162_rn(a, b);
  return *(uint32_t*)&pk;
}

// ===========================================================================
// KA: fused logits + softmax + pooling. 512 threads, grid (74, B) = 296
// blocks (exactly 2 per SM). Each block covers 6-7 tiles of 64 tokens.
// Phase A: bf16 m16n8k16, split-K2 dual logit buffers.
// Pooling: tf32, warp = 32h x 32slots (B-fragments amortized over 2 m-tiles).
// ===========================================================================
__global__ __launch_bounds__(512, 1) void k_assign_pool(
    const float* __restrict__ x, const float* __restrict__ sq_w,
    const float* __restrict__ sq_b) {
  extern __shared__ float sm[];
  float* xs = sm;                       // [64][XP] fp32 (pooling)
  float* lg = sm + 64 * XP;             // [64][LP]  (k-half 0 / W)
  float* lg2 = lg + 64 * LP;            // [64][LP]  (k-half 1)
  float* sb = lg2 + 64 * LP;            // [64]
  uint32_t* xsp = (uint32_t*)(sb + 64);          // [64][PXP] bf16x2
  uint32_t* wsp = xsp + 64 * PXP;                // [64][PXP] bf16x2

  const int tid = threadIdx.x;
  const int b = blockIdx.y;
  const int tstart = (blockIdx.x * 512) / KAB;
  const int tend = ((blockIdx.x + 1) * 512) / KAB;
  const float* xb = x + (size_t)b * NN * HH;

  for (int i = tid * 4; i < 16384; i += 2048) {
    float4 v = *(const float4*)(sq_w + i);
    const int s = i >> 8, h = i & 255;
    wsp[s * PXP + (h >> 1)] = pack_bf16(v.x, v.y);
    wsp[s * PXP + (h >> 1) + 1] = pack_bf16(v.z, v.w);
  }
  if (tid < 64) sb[tid] = sq_b[tid];

  const int wid = tid >> 5, lane = tid & 31;
  const int r = lane >> 2, q = lane & 3;
  const int mA = (wid & 3) * 16;        // phase-A m-tile (4)
  const int nh = ((wid >> 2) & 1) * 4;  // phase-A nt base (2 halves of 4 nt)
  const int kpb = (wid >> 3) * 64;      // phase-A k half, in bf16 pairs
  const int hb2 = (wid & 7) * 32;       // pooling h base (2 m-tiles of 16)
  const int np4 = (wid >> 3) * 4;       // pooling nt base (4 nt)

  float stacc[2][4][4];
#pragma unroll
  for (int m = 0; m < 2; m++)
#pragma unroll
    for (int j = 0; j < 4; j++)
#pragma unroll
      for (int k = 0; k < 4; k++) stacc[m][j][k] = 0.f;

  // prefetch first tile into registers
  float4 pf[8];
  {
    const float* xsrc = xb + (size_t)tstart * 64 * 256;
#pragma unroll
    for (int it = 0; it < 8; it++)
      pf[it] = *(const float4*)(xsrc + tid * 4 + it * 2048);
  }

  for (int tt = tstart; tt < tend; tt++) {
    __syncthreads();  // previous tile's xs/lg consumers done
#pragma unroll
    for (int it = 0; it < 8; it++) {
      const int i = tid * 4 + it * 2048;
      const int t = i >> 8, h = i & 255;
      *(float4*)(xs + t * XP + h) = pf[it];
      xsp[t * PXP + (h >> 1)] = pack_bf16(pf[it].x, pf[it].y);
      xsp[t * PXP + (h >> 1) + 1] = pack_bf16(pf[it].z, pf[it].w);
    }
    __syncthreads();
    if (tt + 1 < tend) {  // overlap next tile's loads with compute
      const float* xsrc = xb + (size_t)(tt + 1) * 64 * 256;
#pragma unroll
      for (int it = 0; it < 8; it++)
        pf[it] = *(const float4*)(xsrc + tid * 4 + it * 2048);
    }

    // ---- phase A: logits via bf16 m16n8k16, warp = m16 x 4nt, K half ----
    float lacc[4][4];
#pragma unroll
    for (int j = 0; j < 4; j++)
#pragma unroll
      for (int k = 0; k < 4; k++) lacc[j][k] = 0.f;

#pragma unroll
    for (int ks = 0; ks < 8; ks++) {
      const int kp0 = kpb + ks * 8;
      uint32_t a0 = xsp[(mA + r) * PXP + kp0 + q];
      uint32_t a1 = xsp[(mA + r + 8) * PXP + kp0 + q];
      uint32_t a2 = xsp[(mA + r) * PXP + kp0 + q + 4];
      uint32_t a3 = xsp[(mA + r + 8) * PXP + kp0 + q + 4];
#pragma unroll
      for (int j = 0; j < 4; j++) {
        const int nt = nh + j;
        uint32_t b0 = wsp[(nt * 8 + r) * PXP + kp0 + q];
        uint32_t b1 = wsp[(nt * 8 + r) * PXP + kp0 + q + 4];
        mma_bf16(lacc[j], a0, a1, a2, a3, b0, b1);
      }
    }
    {
      float* lgw = (kpb == 0) ? lg : lg2;
#pragma unroll
      for (int j = 0; j < 4; j++) {
        const int nt = nh + j;
        lgw[(mA + r) * LP + nt * 8 + 2 * q] = lacc[j][0];
        lgw[(mA + r) * LP + nt * 8 + 2 * q + 1] = lacc[j][1];
        lgw[(mA + r + 8) * LP + nt * 8 + 2 * q] = lacc[j][2];
        lgw[(mA + r + 8) * LP + nt * 8 + 2 * q + 1] = lacc[j][3];
      }
    }
    __syncthreads();

    // ---- softmax: 8 threads per row ----
    {
      const int t = tid >> 3, qq = tid & 7;
      float v[8];
      float mx = -1e30f;
#pragma unroll
      for (int i = 0; i < 8; i++) {
        v[i] = lg[t * LP + qq * 8 + i] + lg2[t * LP + qq * 8 + i] +
               sb[qq * 8 + i];
        mx = fmaxf(mx, v[i]);
      }
      mx = fmaxf(mx, __shfl_xor_sync(0xffffffffu, mx, 1));
      mx = fmaxf(mx, __shfl_xor_sync(0xffffffffu, mx, 2));
      mx = fmaxf(mx, __shfl_xor_sync(0xffffffffu, mx, 4));
      float s = 0.f;
#pragma unroll
      for (int i = 0; i < 8; i++) {
        v[i] = __expf(v[i] - mx);
        s += v[i];
      }
      s += __shfl_xor_sync(0xffffffffu, s, 1);
      s += __shfl_xor_sync(0xffffffffu, s, 2);
      s += __shfl_xor_sync(0xffffffffu, s, 4);
      const float inv = 1.f / s;
      uint32_t* wp =
          g_Wp + ((size_t)b * NN + (size_t)tt * 64 + t) * 32 + qq * 4;
#pragma unroll
      for (int i = 0; i < 8; i++) {
        float w = v[i] * inv;
        v[i] = w;
        lg[t * LP + qq * 8 + i] = w;
      }
#pragma unroll
      for (int i = 0; i < 4; i++)
        wp[i] = pack_bf16(v[2 * i], v[2 * i + 1]);
    }
    __syncthreads();

    // ---- pooling: tf32, warp = 32h x 32slots ----
    for (int ks = 0; ks < 8; ks++) {
      const int k0 = ks * 8;
      uint32_t a[2][4];
#pragma unroll
      for (int mt = 0; mt < 2; mt++) {
        const int h0 = hb2 + mt * 16;
        a[mt][0] = F2U(xs[(k0 + q) * XP + h0 + r]);
        a[mt][1] = F2U(xs[(k0 + q) * XP + h0 + r + 8]);
        a[mt][2] = F2U(xs[(k0 + q + 4) * XP + h0 + r]);
        a[mt][3] = F2U(xs[(k0 + q + 4) * XP + h0 + r + 8]);
      }
#pragma unroll
      for (int j = 0; j < 4; j++) {
        const int nt = np4 + j;
        uint32_t b0 = F2U(lg[(k0 + q) * LP + nt * 8 + r]);
        uint32_t b1 = F2U(lg[(k0 + q + 4) * LP + nt * 8 + r]);
        mma_tf32(stacc[0][j], a[0][0], a[0][1], a[0][2], a[0][3], b0, b1);
        mma_tf32(stacc[1][j], a[1][0], a[1][1], a[1][2], a[1][3], b0, b1);
      }
    }
  }

  float* pp = g_part + (size_t)(b * KAB + blockIdx.x) * 16384;
#pragma unroll
  for (int mt = 0; mt < 2; mt++) {
#pragma unroll
    for (int j = 0; j < 4; j++) {
      const int h0 = hb2 + mt * 16 + r;
      const int s0 = (np4 + j) * 8 + 2 * q;
      *(float2*)(pp + h0 * 64 + s0) =
          make_float2(stacc[mt][j][0], stacc[mt][j][1]);
      *(float2*)(pp + (h0 + 8) * 64 + s0) =
          make_float2(stacc[mt][j][2], stacc[mt][j][3]);
    }
  }
}

// ===========================================================================
// reduce pooling partials (74 per batch) -> g_st
// ===========================================================================
__global__ __launch_bounds__(256) void k_reduce_st() {
  const int gt = blockIdx.x * 256 + threadIdx.x;  // 0..16383
  const int bb = gt >> 12;
  const int p4 = (gt & 4095) * 4;
  const float* p = g_part + (size_t)bb * KAB * 16384 + p4;
  float4 acc = make_float4(0.f, 0.f, 0.f, 0.f);
#pragma unroll 2
  for (int j = 0; j < KAB; j++) {
    float4 v = *(const float4*)(p + (size_t)j * 16384);
    acc.x += v.x; acc.y += v.y; acc.z += v.z; acc.w += v.w;
  }
  const int h = p4 >> 6, s0 = p4 & 63;
  float* dst = g_st + bb * 16384 + h;
  dst[(s0 + 0) * 256] = acc.x;
  dst[(s0 + 1) * 256] = acc.y;
  dst[(s0 + 2) * 256] = acc.z;
  dst[(s0 + 3) * 256] = acc.w;
}

// ===========================================================================
// Middle GEMM via tf32 mma (gate/qkv/proj). 512 threads, 32 cols/block.
// ===========================================================================
#define MIDQ_SMEM ((64 * MP + 32 * MP) * 4)

__device__ __forceinline__ void stage_mid(float* As, float* ws,
                                          const float* asrc, int lds,
                                          const float* w, int ldw, int c0,
                                          int koff, int tid) {
  for (int i = tid * 4; i < 16384; i += 2048) {
    float4 v = *(const float4*)(asrc + (i >> 8) * lds + (i & 255));
    *(float4*)(As + (i >> 8) * MP + (i & 255)) = v;
  }
  for (int i = tid * 4; i < 8192; i += 2048) {
    int cl = i >> 8, k = i & 255;
    float4 v = *(const float4*)(w + (size_t)(c0 + cl) * ldw + koff + k);
    *(float4*)(ws + cl * MP + k) = v;
  }
}

__device__ __forceinline__ void mid_mma(const float* __restrict__ As,
                                        const float* __restrict__ ws,
                                        float c[4], int mA, int nq, int r,
                                        int q) {
#pragma unroll 4
  for (int ks = 0; ks < 32; ks++) {
    const int k0 = ks * 8;
    uint32_t a0 = F2U(As[(mA + r) * MP + k0 + q]);
    uint32_t a1 = F2U(As[(mA + r + 8) * MP + k0 + q]);
    uint32_t a2 = F2U(As[(mA + r) * MP + k0 + q + 4]);
    uint32_t a3 = F2U(As[(mA + r + 8) * MP + k0 + q + 4]);
    uint32_t b0 = F2U(ws[(nq * 8 + r) * MP + k0 + q]);
    uint32_t b1 = F2U(ws[(nq * 8 + r) * MP + k0 + q + 4]);
    mma_tf32(c, a0, a1, a2, a3, b0, b1);
  }
}

__device__ __forceinline__ void mid_mma_bf16(const uint32_t* __restrict__ asp,
                                             const uint32_t* __restrict__ wsp,
                                             float c[4], int mA, int nq, int r,
                                             int q) {
#pragma unroll 4
  for (int ks = 0; ks < 16; ks++) {
    const int kp0 = ks * 8;
    uint32_t a0 = asp[(mA + r) * PXP + kp0 + q];
    uint32_t a1 = asp[(mA + r + 8) * PXP + kp0 + q];
    uint32_t a2 = asp[(mA + r) * PXP + kp0 + q + 4];
    uint32_t a3 = asp[(mA + r + 8) * PXP + kp0 + q + 4];
    uint32_t b0 = wsp[(nq * 8 + r) * PXP + kp0 + q];
    uint32_t b1 = wsp[(nq * 8 + r) * PXP + kp0 + q + 4];
    mma_bf16(c, a0, a1, a2, a3, b0, b1);
  }
}

#define MID_PROLOG                                     \
  const int tid = threadIdx.x;                         \
  const int b = blockIdx.y;                            \
  const int c0 = blockIdx.x * 32;                      \
  const int wid = tid >> 5, lane = tid & 31;           \
  const int r = lane >> 2, q = lane & 3;               \
  const int mA = (wid & 3) * 16, nq = wid >> 2;        \
  const int cg = c0 + nq * 8 + 2 * q;                  \
  const int row0 = mA + r, row1 = mA + r + 8;

// gate: st_gated = st + sigmoid(st @ gw^T + gb) * estate
__global__ __launch_bounds__(512) void k_gate(
    const float* __restrict__ gw, const float* __restrict__ gb,
    const float* __restrict__ estate) {
  extern __shared__ float smm[];
  float* As = smm;
  float* ws = smm + 64 * MP;
  MID_PROLOG
  stage_mid(As, ws, g_st + b * 16384, 256, gw, 256, c0, 0, tid);
  float b0v = gb[cg], b1v = gb[cg + 1];
  float c[4] = {b0v, b1v, b0v, b1v};
  __syncthreads();
  mid_mma(As, ws, c, mA, nq, r, q);
  float s0 = 1.f / (1.f + __expf(-c[0]));
  float s1 = 1.f / (1.f + __expf(-c[1]));
  float s2 = 1.f / (1.f + __expf(-c[2]));
  float s3 = 1.f / (1.f + __expf(-c[3]));
  g_stg[b * 16384 + row0 * 256 + cg] = As[row0 * MP + cg] + s0 * estate[row0 * 256 + cg];
  g_stg[b * 16384 + row0 * 256 + cg + 1] = As[row0 * MP + cg + 1] + s1 * estate[row0 * 256 + cg + 1];
  g_stg[b * 16384 + row1 * 256 + cg] = As[row1 * MP + cg] + s2 * estate[row1 * 256 + cg];
  g_stg[b * 16384 + row1 * 256 + cg + 1] = As[row1 * MP + cg + 1] + s3 * estate[row1 * 256 + cg + 1];
}

__global__ __launch_bounds__(512) void k_qkv(
    const float* __restrict__ in_w, const float* __restrict__ in_b) {
  extern __shared__ float smm[];
  float* As = smm;
  float* ws = smm + 64 * MP;
  MID_PROLOG
  stage_mid(As, ws, g_stg + b * 16384, 256, in_w, 256, c0, 0, tid);
  float b0v = in_b[cg], b1v = in_b[cg + 1];
  float c[4] = {b0v, b1v, b0v, b1v};
  __syncthreads();
  mid_mma(As, ws, c, mA, nq, r, q);
  g_qkv[(b * 64 + row0) * 768 + cg] = c[0];
  g_qkv[(b * 64 + row0) * 768 + cg + 1] = c[1];
  g_qkv[(b * 64 + row1) * 768 + cg] = c[2];
  g_qkv[(b * 64 + row1) * 768 + cg + 1] = c[3];
}

// attention per (b, head): 32 blocks, 1024 threads
__global__ __launch_bounds__(1024) void k_attn() {
  int b = blockIdx.x >> 3, hh = blockIdx.x & 7;
  __shared__ float q[64][32], kk[64][33], vv[64][32], p[64][65];
  int tid = threadIdx.x;
  for (int i = tid; i < 2048; i += 1024) {
    int s = i >> 5, d = i & 31;
    int base = (b * 64 + s) * 768 + hh * 32 + d;
    q[s][d] = g_qkv[base];
    kk[s][d] = g_qkv[base + 256];
    vv[s][d] = g_qkv[base + 512];
  }
  __syncthreads();
  for (int idx = tid; idx < 4096; idx += 1024) {
    int qi = idx >> 6, ki = idx & 63;
    float a = 0.f;
#pragma unroll
    for (int d = 0; d < 32; d++) a += q[qi][d] * kk[ki][d];
    p[qi][ki] = a * 0.17677669529663687f;
  }
  __syncthreads();
  if (tid < 512) {
    const int row = tid >> 3, qq = tid & 7;
    float v[8], mx = -1e30f;
#pragma unroll
    for (int i = 0; i < 8; i++) {
      v[i] = p[row][qq * 8 + i];
      mx = fmaxf(mx, v[i]);
    }
    mx = fmaxf(mx, __shfl_xor_sync(0xffffffffu, mx, 1));
    mx = fmaxf(mx, __shfl_xor_sync(0xffffffffu, mx, 2));
    mx = fmaxf(mx, __shfl_xor_sync(0xffffffffu, mx, 4));
    float s = 0.f;
#pragma unroll
    for (int i = 0; i < 8; i++) { v[i] = __expf(v[i] - mx); s += v[i]; }
    s += __shfl_xor_sync(0xffffffffu, s, 1);
    s += __shfl_xor_sync(0xffffffffu, s, 2);
    s += __shfl_xor_sync(0xffffffffu, s, 4);
    const float inv = 1.f / s;
#pragma unroll
    for (int i = 0; i < 8; i++) p[row][qq * 8 + i] = v[i] * inv;
  }
  __syncthreads();
  for (int idx = tid; idx < 2048; idx += 1024) {
    int qi = idx >> 5, d = idx & 31;
    float a = 0.f;
#pragma unroll
    for (int j = 0; j < 64; j++) a += p[qi][j] * vv[j][d];
    g_ao[(b * 64 + qi) * 256 + hh * 32 + d] = a;
  }
}

__global__ __launch_bounds__(512) void k_proj(
    const float* __restrict__ out_w, const float* __restrict__ out_b) {
  extern __shared__ float smm[];
  float* As = smm;
  float* ws = smm + 64 * MP;
  MID_PROLOG
  stage_mid(As, ws, g_ao + b * 16384, 256, out_w, 256, c0, 0, tid);
  float b0v = out_b[cg], b1v = out_b[cg + 1];
  float c[4] = {b0v, b1v, b0v, b1v};
  __syncthreads();
  mid_mma(As, ws, c, mA, nq, r, q);
  g_pro[(b * 64 + row0) * 256 + cg] = c[0];
  g_pro[(b * 64 + row0) * 256 + cg + 1] = c[1];
  g_pro[(b * 64 + row1) * 256 + cg] = c[2];
  g_pro[(b * 64 + row1) * 256 + cg + 1] = c[3];
}

// LN kernel (LN2): out = LN(a + sum of np partials)
__device__ __forceinline__ void ln4_reduce(float yv[4], float mu[4], float var[4],
                                           float wsum[4][8], float wsq[4][8],
                                           int tid) {
  float s1[4], s2[4];
#pragma unroll
  for (int r = 0; r < 4; r++) { s1[r] = yv[r]; s2[r] = yv[r] * yv[r]; }
#pragma unroll
  for (int off = 16; off; off >>= 1)
#pragma unroll
    for (int r = 0; r < 4; r++) {
      s1[r] += __shfl_xor_sync(0xffffffffu, s1[r], off);
      s2[r] += __shfl_xor_sync(0xffffffffu, s2[r], off);
    }
  int w = tid >> 5, lane = tid & 31;
  if (lane == 0)
#pragma unroll
    for (int r = 0; r < 4; r++) { wsum[r][w] = s1[r]; wsq[r][w] = s2[r]; }
  __syncthreads();
#pragma unroll
  for (int r = 0; r < 4; r++) {
    float a = 0.f, bq = 0.f;
#pragma unroll
    for (int ww = 0; ww < 8; ww++) { a += wsum[r][ww]; bq += wsq[r][ww]; }
    mu[r] = a * (1.f / 256.f);
    var[r] = bq * (1.f / 256.f) - mu[r] * mu[r];
  }
}

__global__ __launch_bounds__(256) void k_ln(
    const float* __restrict__ a, const float* __restrict__ parts, int np,
    const float* __restrict__ g, const float* __restrict__ bb,
    float* __restrict__ out) {
  int bs0 = blockIdx.x * 4;
  __shared__ float wsum[4][8], wsq[4][8];
  int tid = threadIdx.x;
  float yv[4];
#pragma unroll
  for (int r = 0; r < 4; r++) {
    int idx = (bs0 + r) * 256 + tid;
    float v = a[idx];
    for (int pz = 0; pz < np; pz++) v += parts[pz * (BB * SS * HH) + idx];
    yv[r] = v;
  }
  float mu[4], var[4];
  ln4_reduce(yv, mu, var, wsum, wsq, tid);
#pragma unroll
  for (int r = 0; r < 4; r++)
    out[(bs0 + r) * 256 + tid] =
        (yv[r] - mu[r]) * rsqrtf(var[r] + 1e-5f) * g[tid] + bb[tid];
}

// ffn1 with fused LN1, bf16 mma: y = stg+pro; st1 = LN(y); h = GELU(st1@W^T+b)
// smem: As fp32 [64][MP] + asp [64][PXP] + wsp [32][PXP]
#define FFN1_SMEM ((64 * MP) * 4 + (64 * PXP + 32 * PXP) * 4)
__global__ __launch_bounds__(512) void k_ffn1(
    const float* __restrict__ f1_w, const float* __restrict__ f1_b,
    const float* __restrict__ n1g, const float* __restrict__ n1b) {
  extern __shared__ float smm[];
  float* As = smm;
  uint32_t* asp = (uint32_t*)(smm + 64 * MP);
  uint32_t* wsp = asp + 64 * PXP;
  __shared__ float sg[256], sbv[256];
  MID_PROLOG
  for (int i = tid * 4; i < 16384; i += 2048) {
    float4 a = *(const float4*)(g_stg + b * 16384 + i);
    float4 p = *(const float4*)(g_pro + b * 16384 + i);
    a.x += p.x; a.y += p.y; a.z += p.z; a.w += p.w;
    *(float4*)(As + (i >> 8) * MP + (i & 255)) = a;
  }
  for (int i = tid * 4; i < 8192; i += 2048) {
    int cl = i >> 8, k = i & 255;
    float4 v = *(const float4*)(f1_w + (size_t)(c0 + cl) * 256 + k);
    wsp[cl * PXP + (k >> 1)] = pack_bf16(v.x, v.y);
    wsp[cl * PXP + (k >> 1) + 1] = pack_bf16(v.z, v.w);
  }
  if (tid < 256) {
    sg[tid] = n1g[tid];
    sbv[tid] = n1b[tid];
  }
  __syncthreads();
  // LN in-block: 16 warps x 4 rows, each lane 8 cols
  {
    const int cbase = lane * 8;
    for (int rr = wid * 4; rr < wid * 4 + 4; rr++) {
      float4 v1 = *(const float4*)(As + rr * MP + cbase);
      float4 v2 = *(const float4*)(As + rr * MP + cbase + 4);
      float s1 = v1.x + v1.y + v1.z + v1.w + v2.x + v2.y + v2.z + v2.w;
      float s2 = v1.x * v1.x + v1.y * v1.y + v1.z * v1.z + v1.w * v1.w +
                 v2.x * v2.x + v2.y * v2.y + v2.z * v2.z + v2.w * v2.w;
#pragma unroll
      for (int off = 16; off; off >>= 1) {
        s1 += __shfl_xor_sync(0xffffffffu, s1, off);
        s2 += __shfl_xor_sync(0xffffffffu, s2, off);
      }
      float mu = s1 * (1.f / 256.f);
      float var = s2 * (1.f / 256.f) - mu * mu;
      float rs = rsqrtf(var + 1e-5f);
      v1.x = (v1.x - mu) * rs * sg[cbase + 0] + sbv[cbase + 0];
      v1.y = (v1.y - mu) * rs * sg[cbase + 1] + sbv[cbase + 1];
      v1.z = (v1.z - mu) * rs * sg[cbase + 2] + sbv[cbase + 2];
      v1.w = (v1.w - mu) * rs * sg[cbase + 3] + sbv[cbase + 3];
      v2.x = (v2.x - mu) * rs * sg[cbase + 4] + sbv[cbase + 4];
      v2.y = (v2.y - mu) * rs * sg[cbase + 5] + sbv[cbase + 5];
      v2.z = (v2.z - mu) * rs * sg[cbase + 6] + sbv[cbase + 6];
      v2.w = (v2.w - mu) * rs * sg[cbase + 7] + sbv[cbase + 7];
      *(float4*)(As + rr * MP + cbase) = v1;
      *(float4*)(As + rr * MP + cbase + 4) = v2;
    }
  }
  __syncthreads();
  if (blockIdx.x == 0) {
    for (int i = tid * 4; i < 16384; i += 2048)
      *(float4*)(g_st1 + b * 16384 + i) =
          *(const float4*)(As + (i >> 8) * MP + (i & 255));
  }
  // pack st1 -> asp
  for (int i = tid * 4; i < 16384; i += 2048) {
    int row = i >> 8, k = i & 255;
    float4 v = *(const float4*)(As + row * MP + k);
    asp[row * PXP + (k >> 1)] = pack_bf16(v.x, v.y);
    asp[row * PXP + (k >> 1) + 1] = pack_bf16(v.z, v.w);
  }
  __syncthreads();
  float b0v = f1_b[cg], b1v = f1_b[cg + 1];
  float c[4] = {b0v, b1v, b0v, b1v};
  mid_mma_bf16(asp, wsp, c, mA, nq, r, q);
#pragma unroll
  for (int j = 0; j < 4; j++) {
    float v = c[j];
    c[j] = 0.5f * v * (1.f + erff(v * 0.7071067811865475f));
  }
  g_hp[(b * 64 + row0) * 512 + (cg >> 1)] = pack_bf16(c[0], c[1]);
  g_hp[(b * 64 + row1) * 512 + (cg >> 1)] = pack_bf16(c[2], c[3]);
}

// ffn2 bf16: K=1024 with 4-way k-split; h already packed in g_hp.
// smem: asp [64][PXP] + wsp [32][PXP] = 49.5KB -> 2 blocks/SM.
#define FFN2_SMEM ((64 * PXP + 32 * PXP) * 4)
__global__ __launch_bounds__(512, 2) void k_ffn2(
    const float* __restrict__ f2_w, const float* __restrict__ f2_b) {
  extern __shared__ float smm[];
  uint32_t* asp = (uint32_t*)smm;
  uint32_t* wsp = asp + 64 * PXP;
  const int z = blockIdx.z;
  MID_PROLOG
  // stage h chunk (packed pairs): rows 64, 128 pairs each
  for (int i = tid * 4; i < 8192; i += 2048) {
    int row = i >> 7, kp = i & 127;
    uint4 v = *(const uint4*)(g_hp + (b * 64 + row) * 512 + z * 128 + kp);
    *(uint4*)(asp + row * PXP + kp) = v;
  }
  for (int i = tid * 4; i < 8192; i += 2048) {
    int cl = i >> 8, k = i & 255;
    float4 v = *(const float4*)(f2_w + (size_t)(c0 + cl) * 1024 + z * 256 + k);
    wsp[cl * PXP + (k >> 1)] = pack_bf16(v.x, v.y);
    wsp[cl * PXP + (k >> 1) + 1] = pack_bf16(v.z, v.w);
  }
  float b0v = (z == 0) ? f2_b[cg] : 0.f;
  float b1v = (z == 0) ? f2_b[cg + 1] : 0.f;
  float c[4] = {b0v, b1v, b0v, b1v};
  __syncthreads();
  mid_mma_bf16(asp, wsp, c, mA, nq, r, q);
  g_f2p[z][(b * 64 + row0) * 256 + cg] = c[0];
  g_f2p[z][(b * 64 + row0) * 256 + cg + 1] = c[1];
  g_f2p[z][(b * 64 + row1) * 256 + cg] = c[2];
  g_f2p[z][(b * 64 + row1) * 256 + cg + 1] = c[3];
}

// ===========================================================================
// KC: decode out = W @ st2 + x via bf16 mma m16n8k16. 256 threads,
// 128 tokens/block, 55KB smem -> 2 blocks/SM. grid (256, B).
// ===========================================================================
__global__ __launch_bounds__(256, 2) void k_decode(const float* __restrict__ x,
                                                   float* __restrict__ out) {
  extern __shared__ float sm[];
  uint32_t* st2p = (uint32_t*)sm;             // [256][KCP]
  uint32_t* Wp = (uint32_t*)sm + 256 * KCP;   // [128][KCP]
  const int tid = threadIdx.x;
  const int b = blockIdx.y;
  const int n0 = blockIdx.x * 128;

  for (int i = tid; i < 8192; i += 256) {
    int h = i & 255, s2 = i >> 8;
    float v0 = g_st2[b * 16384 + (2 * s2) * 256 + h];
    float v1 = g_st2[b * 16384 + (2 * s2 + 1) * 256 + h];
    st2p[h * KCP + s2] = pack_bf16(v0, v1);
  }
  for (int i = tid * 4; i < 4096; i += 1024) {
    int t = i >> 5, s = i & 31;
    uint4 v = *(const uint4*)(g_Wp + ((size_t)b * NN + n0 + t) * 32 + s);
    *(uint4*)(Wp + t * KCP + s) = v;
  }
  __syncthreads();

  const int wid = tid >> 5, lane = tid & 31;
  const int r = lane >> 2, q = lane & 3;
  const int m0 = wid * 16;

  for (int nh = 0; nh < 2; nh++) {
    float acc[16][4];
#pragma unroll
    for (int i = 0; i < 16; i++)
#pragma unroll
      for (int j = 0; j < 4; j++) acc[i][j] = 0.f;

#pragma unroll
    for (int ks = 0; ks < 4; ks++) {
      const int kg = ks * 8;
      uint32_t a0 = Wp[(m0 + r) * KCP + kg + q];
      uint32_t a1 = Wp[(m0 + r + 8) * KCP + kg + q];
      uint32_t a2 = Wp[(m0 + r) * KCP + kg + q + 4];
      uint32_t a3 = Wp[(m0 + r + 8) * KCP + kg + q + 4];
#pragma unroll
      for (int nt = 0; nt < 16; nt++) {
        const int n = nh * 128 + nt * 8;
        uint32_t b0 = st2p[(n + r) * KCP + kg + q];
        uint32_t b1 = st2p[(n + r) * KCP + kg + q + 4];
        mma_bf16(acc[nt], a0, a1, a2, a3, b0, b1);
      }
    }
#pragma unroll
    for (int nt = 0; nt < 16; nt++) {
      const int n = nh * 128 + nt * 8 + 2 * q;
      const size_t base0 = ((size_t)b * NN + n0 + m0 + r) * 256 + n;
      const size_t base1 = base0 + 8 * 256;
      float2 xv0 = *(const float2*)(x + base0);
      float2 xv1 = *(const float2*)(x + base1);
      *(float2*)(out + base0) = make_float2(acc[nt][0] + xv0.x, acc[nt][1] + xv0.y);
      *(float2*)(out + base1) = make_float2(acc[nt][2] + xv1.x, acc[nt][3] + xv1.y);
    }
  }
}

// ===========================================================================
extern "C" void kernel_launch(void* const* d_in, const int* in_sizes, int n_in,
                              void* d_out, int out_size) {
  const float* x = (const float*)d_in[0];
  const float* sq_w = (const float*)d_in[1];
  const float* sq_b = (const float*)d_in[2];
  const float* eid_state = (const float*)d_in[3];
  const float* eid_gw = (const float*)d_in[4];
  const float* eid_gb = (const float*)d_in[5];
  const float* in_w = (const float*)d_in[6];
  const float* in_b = (const float*)d_in[7];
  const float* out_w = (const float*)d_in[8];
  const float* out_b = (const float*)d_in[9];
  const float* n1_g = (const float*)d_in[10];
  const float* n1_b = (const float*)d_in[11];
  const float* n2_g = (const float*)d_in[12];
  const float* n2_b = (const float*)d_in[13];
  const float* f1_w = (const float*)d_in[14];
  const float* f1_b = (const float*)d_in[15];
  const float* f2_w = (const float*)d_in[16];
  const float* f2_b = (const float*)d_in[17];
  float* out = (float*)d_out;

  const int smem_ka =
      (64 * XP + 64 * LP * 2 + 64 + 64 * PXP * 2) * 4;  // ~173KB
  const int smem_kc = (256 * KCP + 128 * KCP) * 4;
  cudaFuncSetAttribute(k_assign_pool, cudaFuncAttributeMaxDynamicSharedMemorySize, smem_ka);
  cudaFuncSetAttribute(k_decode, cudaFuncAttributeMaxDynamicSharedMemorySize, smem_kc);
  cudaFuncSetAttribute(k_gate, cudaFuncAttributeMaxDynamicSharedMemorySize, MIDQ_SMEM);
  cudaFuncSetAttribute(k_qkv, cudaFuncAttributeMaxDynamicSharedMemorySize, MIDQ_SMEM);
  cudaFuncSetAttribute(k_proj, cudaFuncAttributeMaxDynamicSharedMemorySize, MIDQ_SMEM);
  cudaFuncSetAttribute(k_ffn1, cudaFuncAttributeMaxDynamicSharedMemorySize, FFN1_SMEM);
  cudaFuncSetAttribute(k_ffn2, cudaFuncAttributeMaxDynamicSharedMemorySize, FFN2_SMEM);

  float *p_st1, *p_f2p, *p_st2;
  cudaGetSymbolAddress((void**)&p_st1, g_st1);
  cudaGetSymbolAddress((void**)&p_f2p, g_f2p);
  cudaGetSymbolAddress((void**)&p_st2, g_st2);

  k_assign_pool<<<dim3(KAB, BB), 512, smem_ka>>>(x, sq_w, sq_b);
  k_reduce_st<<<64, 256>>>();
  k_gate<<<dim3(8, BB), 512, MIDQ_SMEM>>>(eid_gw, eid_gb, eid_state);
  k_qkv<<<dim3(24, BB), 512, MIDQ_SMEM>>>(in_w, in_b);
  k_attn<<<32, 1024>>>();
  k_proj<<<dim3(8, BB), 512, MIDQ_SMEM>>>(out_w, out_b);
  k_ffn1<<<dim3(32, BB), 512, FFN1_SMEM>>>(f1_w, f1_b, n1_g, n1_b);
  k_ffn2<<<dim3(8, BB, 4), 512, FFN2_SMEM>>>(f2_w, f2_b);
  k_ln<<<64, 256>>>(p_st1, p_f2p, 4, n2_g, n2_b, p_st2);
  k_decode<<<dim3(256, BB), 256, smem_kc>>>(x, out);
}

// round 17
// speedup vs baseline: 1.5061x; 1.0675x over previous
#include <cuda_runtime.h>
#include <cuda_bf16.h>
#include <stdint.h>
#include <math.h>

#define BB 4
#define NN 32768
#define HH 256
#define SS 64

#define PXP 132  // packed bf16 row pad (uint32)
#define LP 72    // logits/W tile row pad
#define MP 268   // middle-gemm row pad (fp32, ffn1 only)
#define KCP 36   // KC packed row pad (uint32)
#define KAB 74   // KA blocks per batch (2*148 total)

// ---------------- scratch (static device allocations only) ----------------
__device__ uint32_t g_Wp[(size_t)BB * NN * 32];      // 16MB packed-bf16 weights
__device__ float g_part[(size_t)BB * KAB * 16384];   // pooling partials
__device__ float g_st[BB * SS * HH];
__device__ float g_stg[BB * SS * HH];                // gated st
__device__ float g_qkv[BB * SS * 3 * HH];
__device__ float g_ao[BB * SS * HH];
__device__ float g_pro[BB * SS * HH];                // attn out-proj (pre-LN)
__device__ float g_st1[BB * SS * HH];
__device__ uint32_t g_hp[BB * SS * 512];             // packed-bf16 GELU acts
__device__ float g_f2p[4][BB * SS * HH];             // ffn2 k-split partials
__device__ float g_st2[BB * SS * HH];

// ---- mma helpers ---------------------------------------------------------
__device__ __forceinline__ void mma_tf32(float c[4], uint32_t a0, uint32_t a1,
                                         uint32_t a2, uint32_t a3, uint32_t b0,
                                         uint32_t b1) {
  asm volatile(
      "mma.sync.aligned.m16n8k8.row.col.f32.tf32.tf32.f32 "
      "{%0,%1,%2,%3}, {%4,%5,%6,%7}, {%8,%9}, {%0,%1,%2,%3};\n"
      : "+f"(c[0]), "+f"(c[1]), "+f"(c[2]), "+f"(c[3])
      : "r"(a0), "r"(a1), "r"(a2), "r"(a3), "r"(b0), "r"(b1));
}
__device__ __forceinline__ void mma_bf16(float c[4], uint32_t a0, uint32_t a1,
                                         uint32_t a2, uint32_t a3, uint32_t b0,
                                         uint32_t b1) {
  asm volatile(
      "mma.sync.aligned.m16n8k16.row.col.f32.bf16.bf16.f32 "
      "{%0,%1,%2,%3}, {%4,%5,%6,%7}, {%8,%9}, {%0,%1,%2,%3};\n"
      : "+f"(c[0]), "+f"(c[1]), "+f"(c[2]), "+f"(c[3])
      : "r"(a0), "r"(a1), "r"(a2), "r"(a3), "r"(b0), "r"(b1));
}
#define F2U __float_as_uint

__device__ __forceinline__ uint32_t pack_bf16(float a, float b) {
  __nv_bfloat162 pk = __floats2bfloat162_rn(a, b);
  return *(uint32_t*)&pk;
}

// ===========================================================================
// KA: fused logits + softmax + pooling. 512 threads, grid (74, B) = 296
// blocks; smem 102.3KB -> 2 blocks/SM co-resident -> ONE wave.
// Phase A: bf16 m16n8k16, split-K2 dual logit buffers.
// Pooling: tf32 with A-operands unpacked from the bf16 xsp buffer.
// ===========================================================================
__global__ __launch_bounds__(512, 2) void k_assign_pool(
    const float* __restrict__ x, const float* __restrict__ sq_w,
    const float* __restrict__ sq_b) {
  extern __shared__ float sm[];
  float* lg = sm;                        // [64][LP]  (k-half 0 / W)
  float* lg2 = lg + 64 * LP;             // [64][LP]  (k-half 1)
  float* sb = lg2 + 64 * LP;             // [64]
  uint32_t* xsp = (uint32_t*)(sb + 64);  // [64][PXP] bf16x2 (h-pairs)
  uint32_t* wsp = xsp + 64 * PXP;        // [64][PXP] bf16x2

  const int tid = threadIdx.x;
  const int b = blockIdx.y;
  const int tstart = (blockIdx.x * 512) / KAB;
  const int tend = ((blockIdx.x + 1) * 512) / KAB;
  const float* xb = x + (size_t)b * NN * HH;

  for (int i = tid * 4; i < 16384; i += 2048) {
    float4 v = *(const float4*)(sq_w + i);
    const int s = i >> 8, h = i & 255;
    wsp[s * PXP + (h >> 1)] = pack_bf16(v.x, v.y);
    wsp[s * PXP + (h >> 1) + 1] = pack_bf16(v.z, v.w);
  }
  if (tid < 64) sb[tid] = sq_b[tid];

  const int wid = tid >> 5, lane = tid & 31;
  const int r = lane >> 2, q = lane & 3;
  const int mA = (wid & 3) * 16;        // phase-A m-tile (4)
  const int nh = ((wid >> 2) & 1) * 4;  // phase-A nt base (2 halves of 4 nt)
  const int kpb = (wid >> 3) * 64;      // phase-A k half, in bf16 pairs
  const int hw0 = (wid & 7) * 16;       // pooling h base in pairs (32 h)
  const int np4 = (wid >> 3) * 4;       // pooling nt base (4 nt)

  float stacc[2][4][4];
#pragma unroll
  for (int m = 0; m < 2; m++)
#pragma unroll
    for (int j = 0; j < 4; j++)
#pragma unroll
      for (int k = 0; k < 4; k++) stacc[m][j][k] = 0.f;

  for (int tt = tstart; tt < tend; tt++) {
    __syncthreads();  // previous tile's xsp/lg consumers done
    {
      const float* xsrc = xb + (size_t)tt * 64 * 256;
#pragma unroll
      for (int it = 0; it < 8; it++) {
        const int i = tid * 4 + it * 2048;
        float4 v = *(const float4*)(xsrc + i);
        const int t = i >> 8, h = i & 255;
        xsp[t * PXP + (h >> 1)] = pack_bf16(v.x, v.y);
        xsp[t * PXP + (h >> 1) + 1] = pack_bf16(v.z, v.w);
      }
    }
    __syncthreads();

    // ---- phase A: logits via bf16 m16n8k16, warp = m16 x 4nt, K half ----
    float lacc[4][4];
#pragma unroll
    for (int j = 0; j < 4; j++)
#pragma unroll
      for (int k = 0; k < 4; k++) lacc[j][k] = 0.f;

#pragma unroll
    for (int ks = 0; ks < 8; ks++) {
      const int kp0 = kpb + ks * 8;
      uint32_t a0 = xsp[(mA + r) * PXP + kp0 + q];
      uint32_t a1 = xsp[(mA + r + 8) * PXP + kp0 + q];
      uint32_t a2 = xsp[(mA + r) * PXP + kp0 + q + 4];
      uint32_t a3 = xsp[(mA + r + 8) * PXP + kp0 + q + 4];
#pragma unroll
      for (int j = 0; j < 4; j++) {
        const int nt = nh + j;
        uint32_t b0 = wsp[(nt * 8 + r) * PXP + kp0 + q];
        uint32_t b1 = wsp[(nt * 8 + r) * PXP + kp0 + q + 4];
        mma_bf16(lacc[j], a0, a1, a2, a3, b0, b1);
      }
    }
    {
      float* lgw = (kpb == 0) ? lg : lg2;
#pragma unroll
      for (int j = 0; j < 4; j++) {
        const int nt = nh + j;
        lgw[(mA + r) * LP + nt * 8 + 2 * q] = lacc[j][0];
        lgw[(mA + r) * LP + nt * 8 + 2 * q + 1] = lacc[j][1];
        lgw[(mA + r + 8) * LP + nt * 8 + 2 * q] = lacc[j][2];
        lgw[(mA + r + 8) * LP + nt * 8 + 2 * q + 1] = lacc[j][3];
      }
    }
    __syncthreads();

    // ---- softmax: 8 threads per row ----
    {
      const int t = tid >> 3, qq = tid & 7;
      float v[8];
      float mx = -1e30f;
#pragma unroll
      for (int i = 0; i < 8; i++) {
        v[i] = lg[t * LP + qq * 8 + i] + lg2[t * LP + qq * 8 + i] +
               sb[qq * 8 + i];
        mx = fmaxf(mx, v[i]);
      }
      mx = fmaxf(mx, __shfl_xor_sync(0xffffffffu, mx, 1));
      mx = fmaxf(mx, __shfl_xor_sync(0xffffffffu, mx, 2));
      mx = fmaxf(mx, __shfl_xor_sync(0xffffffffu, mx, 4));
      float s = 0.f;
#pragma unroll
      for (int i = 0; i < 8; i++) {
        v[i] = __expf(v[i] - mx);
        s += v[i];
      }
      s += __shfl_xor_sync(0xffffffffu, s, 1);
      s += __shfl_xor_sync(0xffffffffu, s, 2);
      s += __shfl_xor_sync(0xffffffffu, s, 4);
      const float inv = 1.f / s;
      uint32_t* wp =
          g_Wp + ((size_t)b * NN + (size_t)tt * 64 + t) * 32 + qq * 4;
#pragma unroll
      for (int i = 0; i < 8; i++) {
        float w = v[i] * inv;
        v[i] = w;
        lg[t * LP + qq * 8 + i] = w;
      }
#pragma unroll
      for (int i = 0; i < 4; i++)
        wp[i] = pack_bf16(v[2 * i], v[2 * i + 1]);
    }
    __syncthreads();

    // ---- pooling: tf32, A-operands unpacked from xsp ----
    for (int ks = 0; ks < 8; ks++) {
      const int k0 = ks * 8;
      uint32_t a[2][4];
#pragma unroll
      for (int mt = 0; mt < 2; mt++) {
        const int hw = hw0 + mt * 8 + (r >> 1);
        uint32_t u0 = xsp[(k0 + q) * PXP + hw];
        uint32_t u1 = xsp[(k0 + q) * PXP + hw + 4];
        uint32_t u2 = xsp[(k0 + q + 4) * PXP + hw];
        uint32_t u3 = xsp[(k0 + q + 4) * PXP + hw + 4];
        if (r & 1) {
          a[mt][0] = u0 & 0xffff0000u;
          a[mt][1] = u1 & 0xffff0000u;
          a[mt][2] = u2 & 0xffff0000u;
          a[mt][3] = u3 & 0xffff0000u;
        } else {
          a[mt][0] = u0 << 16;
          a[mt][1] = u1 << 16;
          a[mt][2] = u2 << 16;
          a[mt][3] = u3 << 16;
        }
      }
#pragma unroll
      for (int j = 0; j < 4; j++) {
        const int nt = np4 + j;
        uint32_t b0 = F2U(lg[(k0 + q) * LP + nt * 8 + r]);
        uint32_t b1 = F2U(lg[(k0 + q + 4) * LP + nt * 8 + r]);
        mma_tf32(stacc[0][j], a[0][0], a[0][1], a[0][2], a[0][3], b0, b1);
        mma_tf32(stacc[1][j], a[1][0], a[1][1], a[1][2], a[1][3], b0, b1);
      }
    }
  }

  float* pp = g_part + (size_t)(b * KAB + blockIdx.x) * 16384;
#pragma unroll
  for (int mt = 0; mt < 2; mt++) {
#pragma unroll
    for (int j = 0; j < 4; j++) {
      const int h0 = (wid & 7) * 32 + mt * 16 + r;
      const int s0 = (np4 + j) * 8 + 2 * q;
      *(float2*)(pp + h0 * 64 + s0) =
          make_float2(stacc[mt][j][0], stacc[mt][j][1]);
      *(float2*)(pp + (h0 + 8) * 64 + s0) =
          make_float2(stacc[mt][j][2], stacc[mt][j][3]);
    }
  }
}

// ===========================================================================
// reduce pooling partials (74 per batch) -> g_st
// ===========================================================================
__global__ __launch_bounds__(256) void k_reduce_st() {
  const int gt = blockIdx.x * 256 + threadIdx.x;  // 0..16383
  const int bb = gt >> 12;
  const int p4 = (gt & 4095) * 4;
  const float* p = g_part + (size_t)bb * KAB * 16384 + p4;
  float4 acc = make_float4(0.f, 0.f, 0.f, 0.f);
#pragma unroll 2
  for (int j = 0; j < KAB; j++) {
    float4 v = *(const float4*)(p + (size_t)j * 16384);
    acc.x += v.x; acc.y += v.y; acc.z += v.z; acc.w += v.w;
  }
  const int h = p4 >> 6, s0 = p4 & 63;
  float* dst = g_st + bb * 16384 + h;
  dst[(s0 + 0) * 256] = acc.x;
  dst[(s0 + 1) * 256] = acc.y;
  dst[(s0 + 2) * 256] = acc.z;
  dst[(s0 + 3) * 256] = acc.w;
}

// ===========================================================================
// Middle GEMMs via bf16 mma. 512 threads, 32 cols/block, 49.5KB smem
// -> 2 blocks/SM.
// ===========================================================================
#define MIDB_SMEM ((64 * PXP + 32 * PXP) * 4)

__device__ __forceinline__ void stage_mid_bf16(uint32_t* asp, uint32_t* wsp,
                                               const float* asrc, int lds,
                                               const float* w, int ldw, int c0,
                                               int koff, int tid) {
  for (int i = tid * 4; i < 16384; i += 2048) {
    float4 v = *(const float4*)(asrc + (i >> 8) * lds + (i & 255));
    int row = i >> 8, k = i & 255;
    asp[row * PXP + (k >> 1)] = pack_bf16(v.x, v.y);
    asp[row * PXP + (k >> 1) + 1] = pack_bf16(v.z, v.w);
  }
  for (int i = tid * 4; i < 8192; i += 2048) {
    int cl = i >> 8, k = i & 255;
    float4 v = *(const float4*)(w + (size_t)(c0 + cl) * ldw + koff + k);
    wsp[cl * PXP + (k >> 1)] = pack_bf16(v.x, v.y);
    wsp[cl * PXP + (k >> 1) + 1] = pack_bf16(v.z, v.w);
  }
}

__device__ __forceinline__ void mid_mma_bf16(const uint32_t* __restrict__ asp,
                                             const uint32_t* __restrict__ wsp,
                                             float c[4], int mA, int nq, int r,
                                             int q) {
#pragma unroll 4
  for (int ks = 0; ks < 16; ks++) {
    const int kp0 = ks * 8;
    uint32_t a0 = asp[(mA + r) * PXP + kp0 + q];
    uint32_t a1 = asp[(mA + r + 8) * PXP + kp0 + q];
    uint32_t a2 = asp[(mA + r) * PXP + kp0 + q + 4];
    uint32_t a3 = asp[(mA + r + 8) * PXP + kp0 + q + 4];
    uint32_t b0 = wsp[(nq * 8 + r) * PXP + kp0 + q];
    uint32_t b1 = wsp[(nq * 8 + r) * PXP + kp0 + q + 4];
    mma_bf16(c, a0, a1, a2, a3, b0, b1);
  }
}

#define MID_PROLOG                                     \
  const int tid = threadIdx.x;                         \
  const int b = blockIdx.y;                            \
  const int c0 = blockIdx.x * 32;                      \
  const int wid = tid >> 5, lane = tid & 31;           \
  const int r = lane >> 2, q = lane & 3;               \
  const int mA = (wid & 3) * 16, nq = wid >> 2;        \
  const int cg = c0 + nq * 8 + 2 * q;                  \
  const int row0 = mA + r, row1 = mA + r + 8;

// gate: st_gated = st + sigmoid(st @ gw^T + gb) * estate
__global__ __launch_bounds__(512, 2) void k_gate(
    const float* __restrict__ gw, const float* __restrict__ gb,
    const float* __restrict__ estate) {
  extern __shared__ float smm[];
  uint32_t* asp = (uint32_t*)smm;
  uint32_t* wsp = asp + 64 * PXP;
  MID_PROLOG
  stage_mid_bf16(asp, wsp, g_st + b * 16384, 256, gw, 256, c0, 0, tid);
  float b0v = gb[cg], b1v = gb[cg + 1];
  float c[4] = {b0v, b1v, b0v, b1v};
  __syncthreads();
  mid_mma_bf16(asp, wsp, c, mA, nq, r, q);
  float s0 = 1.f / (1.f + __expf(-c[0]));
  float s1 = 1.f / (1.f + __expf(-c[1]));
  float s2 = 1.f / (1.f + __expf(-c[2]));
  float s3 = 1.f / (1.f + __expf(-c[3]));
  const float* stb = g_st + b * 16384;
  g_stg[b * 16384 + row0 * 256 + cg] = stb[row0 * 256 + cg] + s0 * estate[row0 * 256 + cg];
  g_stg[b * 16384 + row0 * 256 + cg + 1] = stb[row0 * 256 + cg + 1] + s1 * estate[row0 * 256 + cg + 1];
  g_stg[b * 16384 + row1 * 256 + cg] = stb[row1 * 256 + cg] + s2 * estate[row1 * 256 + cg];
  g_stg[b * 16384 + row1 * 256 + cg + 1] = stb[row1 * 256 + cg + 1] + s3 * estate[row1 * 256 + cg + 1];
}

__global__ __launch_bounds__(512, 2) void k_qkv(
    const float* __restrict__ in_w, const float* __restrict__ in_b) {
  extern __shared__ float smm[];
  uint32_t* asp = (uint32_t*)smm;
  uint32_t* wsp = asp + 64 * PXP;
  MID_PROLOG
  stage_mid_bf16(asp, wsp, g_stg + b * 16384, 256, in_w, 256, c0, 0, tid);
  float b0v = in_b[cg], b1v = in_b[cg + 1];
  float c[4] = {b0v, b1v, b0v, b1v};
  __syncthreads();
  mid_mma_bf16(asp, wsp, c, mA, nq, r, q);
  g_qkv[(b * 64 + row0) * 768 + cg] = c[0];
  g_qkv[(b * 64 + row0) * 768 + cg + 1] = c[1];
  g_qkv[(b * 64 + row1) * 768 + cg] = c[2];
  g_qkv[(b * 64 + row1) * 768 + cg + 1] = c[3];
}

// attention per (b, head): 32 blocks, 1024 threads
__global__ __launch_bounds__(1024) void k_attn() {
  int b = blockIdx.x >> 3, hh = blockIdx.x & 7;
  __shared__ float q[64][32], kk[64][33], vv[64][32], p[64][65];
  int tid = threadIdx.x;
  for (int i = tid; i < 2048; i += 1024) {
    int s = i >> 5, d = i & 31;
    int base = (b * 64 + s) * 768 + hh * 32 + d;
    q[s][d] = g_qkv[base];
    kk[s][d] = g_qkv[base + 256];
    vv[s][d] = g_qkv[base + 512];
  }
  __syncthreads();
  for (int idx = tid; idx < 4096; idx += 1024) {
    int qi = idx >> 6, ki = idx & 63;
    float a = 0.f;
#pragma unroll
    for (int d = 0; d < 32; d++) a += q[qi][d] * kk[ki][d];
    p[qi][ki] = a * 0.17677669529663687f;
  }
  __syncthreads();
  if (tid < 512) {
    const int row = tid >> 3, qq = tid & 7;
    float v[8], mx = -1e30f;
#pragma unroll
    for (int i = 0; i < 8; i++) {
      v[i] = p[row][qq * 8 + i];
      mx = fmaxf(mx, v[i]);
    }
    mx = fmaxf(mx, __shfl_xor_sync(0xffffffffu, mx, 1));
    mx = fmaxf(mx, __shfl_xor_sync(0xffffffffu, mx, 2));
    mx = fmaxf(mx, __shfl_xor_sync(0xffffffffu, mx, 4));
    float s = 0.f;
#pragma unroll
    for (int i = 0; i < 8; i++) { v[i] = __expf(v[i] - mx); s += v[i]; }
    s += __shfl_xor_sync(0xffffffffu, s, 1);
    s += __shfl_xor_sync(0xffffffffu, s, 2);
    s += __shfl_xor_sync(0xffffffffu, s, 4);
    const float inv = 1.f / s;
#pragma unroll
    for (int i = 0; i < 8; i++) p[row][qq * 8 + i] = v[i] * inv;
  }
  __syncthreads();
  for (int idx = tid; idx < 2048; idx += 1024) {
    int qi = idx >> 5, d = idx & 31;
    float a = 0.f;
#pragma unroll
    for (int j = 0; j < 64; j++) a += p[qi][j] * vv[j][d];
    g_ao[(b * 64 + qi) * 256 + hh * 32 + d] = a;
  }
}

__global__ __launch_bounds__(512, 2) void k_proj(
    const float* __restrict__ out_w, const float* __restrict__ out_b) {
  extern __shared__ float smm[];
  uint32_t* asp = (uint32_t*)smm;
  uint32_t* wsp = asp + 64 * PXP;
  MID_PROLOG
  stage_mid_bf16(asp, wsp, g_ao + b * 16384, 256, out_w, 256, c0, 0, tid);
  float b0v = out_b[cg], b1v = out_b[cg + 1];
  float c[4] = {b0v, b1v, b0v, b1v};
  __syncthreads();
  mid_mma_bf16(asp, wsp, c, mA, nq, r, q);
  g_pro[(b * 64 + row0) * 256 + cg] = c[0];
  g_pro[(b * 64 + row0) * 256 + cg + 1] = c[1];
  g_pro[(b * 64 + row1) * 256 + cg] = c[2];
  g_pro[(b * 64 + row1) * 256 + cg + 1] = c[3];
}

// LN kernel (LN2): out = LN(a + sum of np partials)
__device__ __forceinline__ void ln4_reduce(float yv[4], float mu[4], float var[4],
                                           float wsum[4][8], float wsq[4][8],
                                           int tid) {
  float s1[4], s2[4];
#pragma unroll
  for (int r = 0; r < 4; r++) { s1[r] = yv[r]; s2[r] = yv[r] * yv[r]; }
#pragma unroll
  for (int off = 16; off; off >>= 1)
#pragma unroll
    for (int r = 0; r < 4; r++) {
      s1[r] += __shfl_xor_sync(0xffffffffu, s1[r], off);
      s2[r] += __shfl_xor_sync(0xffffffffu, s2[r], off);
    }
  int w = tid >> 5, lane = tid & 31;
  if (lane == 0)
#pragma unroll
    for (int r = 0; r < 4; r++) { wsum[r][w] = s1[r]; wsq[r][w] = s2[r]; }
  __syncthreads();
#pragma unroll
  for (int r = 0; r < 4; r++) {
    float a = 0.f, bq = 0.f;
#pragma unroll
    for (int ww = 0; ww < 8; ww++) { a += wsum[r][ww]; bq += wsq[r][ww]; }
    mu[r] = a * (1.f / 256.f);
    var[r] = bq * (1.f / 256.f) - mu[r] * mu[r];
  }
}

__global__ __launch_bounds__(256) void k_ln(
    const float* __restrict__ a, const float* __restrict__ parts, int np,
    const float* __restrict__ g, const float* __restrict__ bb,
    float* __restrict__ out) {
  int bs0 = blockIdx.x * 4;
  __shared__ float wsum[4][8], wsq[4][8];
  int tid = threadIdx.x;
  float yv[4];
#pragma unroll
  for (int r = 0; r < 4; r++) {
    int idx = (bs0 + r) * 256 + tid;
    float v = a[idx];
    for (int pz = 0; pz < np; pz++) v += parts[pz * (BB * SS * HH) + idx];
    yv[r] = v;
  }
  float mu[4], var[4];
  ln4_reduce(yv, mu, var, wsum, wsq, tid);
#pragma unroll
  for (int r = 0; r < 4; r++)
    out[(bs0 + r) * 256 + tid] =
        (yv[r] - mu[r]) * rsqrtf(var[r] + 1e-5f) * g[tid] + bb[tid];
}

// ffn1 with fused LN1, bf16 mma
#define FFN1_SMEM ((64 * MP) * 4 + (64 * PXP + 32 * PXP) * 4)
__global__ __launch_bounds__(512) void k_ffn1(
    const float* __restrict__ f1_w, const float* __restrict__ f1_b,
    const float* __restrict__ n1g, const float* __restrict__ n1b) {
  extern __shared__ float smm[];
  float* As = smm;
  uint32_t* asp = (uint32_t*)(smm + 64 * MP);
  uint32_t* wsp = asp + 64 * PXP;
  __shared__ float sg[256], sbv[256];
  MID_PROLOG
  for (int i = tid * 4; i < 16384; i += 2048) {
    float4 a = *(const float4*)(g_stg + b * 16384 + i);
    float4 p = *(const float4*)(g_pro + b * 16384 + i);
    a.x += p.x; a.y += p.y; a.z += p.z; a.w += p.w;
    *(float4*)(As + (i >> 8) * MP + (i & 255)) = a;
  }
  for (int i = tid * 4; i < 8192; i += 2048) {
    int cl = i >> 8, k = i & 255;
    float4 v = *(const float4*)(f1_w + (size_t)(c0 + cl) * 256 + k);
    wsp[cl * PXP + (k >> 1)] = pack_bf16(v.x, v.y);
    wsp[cl * PXP + (k >> 1) + 1] = pack_bf16(v.z, v.w);
  }
  if (tid < 256) {
    sg[tid] = n1g[tid];
    sbv[tid] = n1b[tid];
  }
  __syncthreads();
  {
    const int cbase = lane * 8;
    for (int rr = wid * 4; rr < wid * 4 + 4; rr++) {
      float4 v1 = *(const float4*)(As + rr * MP + cbase);
      float4 v2 = *(const float4*)(As + rr * MP + cbase + 4);
      float s1 = v1.x + v1.y + v1.z + v1.w + v2.x + v2.y + v2.z + v2.w;
      float s2 = v1.x * v1.x + v1.y * v1.y + v1.z * v1.z + v1.w * v1.w +
                 v2.x * v2.x + v2.y * v2.y + v2.z * v2.z + v2.w * v2.w;
#pragma unroll
      for (int off = 16; off; off >>= 1) {
        s1 += __shfl_xor_sync(0xffffffffu, s1, off);
        s2 += __shfl_xor_sync(0xffffffffu, s2, off);
      }
      float mu = s1 * (1.f / 256.f);
      float var = s2 * (1.f / 256.f) - mu * mu;
      float rs = rsqrtf(var + 1e-5f);
      v1.x = (v1.x - mu) * rs * sg[cbase + 0] + sbv[cbase + 0];
      v1.y = (v1.y - mu) * rs * sg[cbase + 1] + sbv[cbase + 1];
      v1.z = (v1.z - mu) * rs * sg[cbase + 2] + sbv[cbase + 2];
      v1.w = (v1.w - mu) * rs * sg[cbase + 3] + sbv[cbase + 3];
      v2.x = (v2.x - mu) * rs * sg[cbase + 4] + sbv[cbase + 4];
      v2.y = (v2.y - mu) * rs * sg[cbase + 5] + sbv[cbase + 5];
      v2.z = (v2.z - mu) * rs * sg[cbase + 6] + sbv[cbase + 6];
      v2.w = (v2.w - mu) * rs * sg[cbase + 7] + sbv[cbase + 7];
      *(float4*)(As + rr * MP + cbase) = v1;
      *(float4*)(As + rr * MP + cbase + 4) = v2;
    }
  }
  __syncthreads();
  if (blockIdx.x == 0) {
    for (int i = tid * 4; i < 16384; i += 2048)
      *(float4*)(g_st1 + b * 16384 + i) =
          *(const float4*)(As + (i >> 8) * MP + (i & 255));
  }
  for (int i = tid * 4; i < 16384; i += 2048) {
    int row = i >> 8, k = i & 255;
    float4 v = *(const float4*)(As + row * MP + k);
    asp[row * PXP + (k >> 1)] = pack_bf16(v.x, v.y);
    asp[row * PXP + (k >> 1) + 1] = pack_bf16(v.z, v.w);
  }
  __syncthreads();
  float b0v = f1_b[cg], b1v = f1_b[cg + 1];
  float c[4] = {b0v, b1v, b0v, b1v};
  mid_mma_bf16(asp, wsp, c, mA, nq, r, q);
#pragma unroll
  for (int j = 0; j < 4; j++) {
    float v = c[j];
    c[j] = 0.5f * v * (1.f + erff(v * 0.7071067811865475f));
  }
  g_hp[(b * 64 + row0) * 512 + (cg >> 1)] = pack_bf16(c[0], c[1]);
  g_hp[(b * 64 + row1) * 512 + (cg >> 1)] = pack_bf16(c[2], c[3]);
}

// ffn2 bf16: K=1024 with 4-way k-split; h packed in g_hp.
#define FFN2_SMEM ((64 * PXP + 32 * PXP) * 4)
__global__ __launch_bounds__(512, 2) void k_ffn2(
    const float* __restrict__ f2_w, const float* __restrict__ f2_b) {
  extern __shared__ float smm[];
  uint32_t* asp = (uint32_t*)smm;
  uint32_t* wsp = asp + 64 * PXP;
  const int z = blockIdx.z;
  MID_PROLOG
  for (int i = tid * 4; i < 8192; i += 2048) {
    int row = i >> 7, kp = i & 127;
    uint4 v = *(const uint4*)(g_hp + (b * 64 + row) * 512 + z * 128 + kp);
    *(uint4*)(asp + row * PXP + kp) = v;
  }
  for (int i = tid * 4; i < 8192; i += 2048) {
    int cl = i >> 8, k = i & 255;
    float4 v = *(const float4*)(f2_w + (size_t)(c0 + cl) * 1024 + z * 256 + k);
    wsp[cl * PXP + (k >> 1)] = pack_bf16(v.x, v.y);
    wsp[cl * PXP + (k >> 1) + 1] = pack_bf16(v.z, v.w);
  }
  float b0v = (z == 0) ? f2_b[cg] : 0.f;
  float b1v = (z == 0) ? f2_b[cg + 1] : 0.f;
  float c[4] = {b0v, b1v, b0v, b1v};
  __syncthreads();
  mid_mma_bf16(asp, wsp, c, mA, nq, r, q);
  g_f2p[z][(b * 64 + row0) * 256 + cg] = c[0];
  g_f2p[z][(b * 64 + row0) * 256 + cg + 1] = c[1];
  g_f2p[z][(b * 64 + row1) * 256 + cg] = c[2];
  g_f2p[z][(b * 64 + row1) * 256 + cg + 1] = c[3];
}

// ===========================================================================
// KC: decode out = W @ st2 + x via bf16 mma m16n8k16.
// ===========================================================================
__global__ __launch_bounds__(256, 2) void k_decode(const float* __restrict__ x,
                                                   float* __restrict__ out) {
  extern __shared__ float sm[];
  uint32_t* st2p = (uint32_t*)sm;             // [256][KCP]
  uint32_t* Wp = (uint32_t*)sm + 256 * KCP;   // [128][KCP]
  const int tid = threadIdx.x;
  const int b = blockIdx.y;
  const int n0 = blockIdx.x * 128;

  for (int i = tid; i < 8192; i += 256) {
    int h = i & 255, s2 = i >> 8;
    float v0 = g_st2[b * 16384 + (2 * s2) * 256 + h];
    float v1 = g_st2[b * 16384 + (2 * s2 + 1) * 256 + h];
    st2p[h * KCP + s2] = pack_bf16(v0, v1);
  }
  for (int i = tid * 4; i < 4096; i += 1024) {
    int t = i >> 5, s = i & 31;
    uint4 v = *(const uint4*)(g_Wp + ((size_t)b * NN + n0 + t) * 32 + s);
    *(uint4*)(Wp + t * KCP + s) = v;
  }
  __syncthreads();

  const int wid = tid >> 5, lane = tid & 31;
  const int r = lane >> 2, q = lane & 3;
  const int m0 = wid * 16;

  for (int nh = 0; nh < 2; nh++) {
    float acc[16][4];
#pragma unroll
    for (int i = 0; i < 16; i++)
#pragma unroll
      for (int j = 0; j < 4; j++) acc[i][j] = 0.f;

#pragma unroll
    for (int ks = 0; ks < 4; ks++) {
      const int kg = ks * 8;
      uint32_t a0 = Wp[(m0 + r) * KCP + kg + q];
      uint32_t a1 = Wp[(m0 + r + 8) * KCP + kg + q];
      uint32_t a2 = Wp[(m0 + r) * KCP + kg + q + 4];
      uint32_t a3 = Wp[(m0 + r + 8) * KCP + kg + q + 4];
#pragma unroll
      for (int nt = 0; nt < 16; nt++) {
        const int n = nh * 128 + nt * 8;
        uint32_t b0 = st2p[(n + r) * KCP + kg + q];
        uint32_t b1 = st2p[(n + r) * KCP + kg + q + 4];
        mma_bf16(acc[nt], a0, a1, a2, a3, b0, b1);
      }
    }
#pragma unroll
    for (int nt = 0; nt < 16; nt++) {
      const int n = nh * 128 + nt * 8 + 2 * q;
      const size_t base0 = ((size_t)b * NN + n0 + m0 + r) * 256 + n;
      const size_t base1 = base0 + 8 * 256;
      float2 xv0 = *(const float2*)(x + base0);
      float2 xv1 = *(const float2*)(x + base1);
      *(float2*)(out + base0) = make_float2(acc[nt][0] + xv0.x, acc[nt][1] + xv0.y);
      *(float2*)(out + base1) = make_float2(acc[nt][2] + xv1.x, acc[nt][3] + xv1.y);
    }
  }
}

// ===========================================================================
extern "C" void kernel_launch(void* const* d_in, const int* in_sizes, int n_in,
                              void* d_out, int out_size) {
  const float* x = (const float*)d_in[0];
  const float* sq_w = (const float*)d_in[1];
  const float* sq_b = (const float*)d_in[2];
  const float* eid_state = (const float*)d_in[3];
  const float* eid_gw = (const float*)d_in[4];
  const float* eid_gb = (const float*)d_in[5];
  const float* in_w = (const float*)d_in[6];
  const float* in_b = (const float*)d_in[7];
  const float* out_w = (const float*)d_in[8];
  const float* out_b = (const float*)d_in[9];
  const float* n1_g = (const float*)d_in[10];
  const float* n1_b = (const float*)d_in[11];
  const float* n2_g = (const float*)d_in[12];
  const float* n2_b = (const float*)d_in[13];
  const float* f1_w = (const float*)d_in[14];
  const float* f1_b = (const float*)d_in[15];
  const float* f2_w = (const float*)d_in[16];
  const float* f2_b = (const float*)d_in[17];
  float* out = (float*)d_out;

  const int smem_ka = (64 * LP * 2 + 64 + 64 * PXP * 2) * 4;  // ~102.3KB
  const int smem_kc = (256 * KCP + 128 * KCP) * 4;
  cudaFuncSetAttribute(k_assign_pool, cudaFuncAttributeMaxDynamicSharedMemorySize, smem_ka);
  cudaFuncSetAttribute(k_decode, cudaFuncAttributeMaxDynamicSharedMemorySize, smem_kc);
  cudaFuncSetAttribute(k_gate, cudaFuncAttributeMaxDynamicSharedMemorySize, MIDB_SMEM);
  cudaFuncSetAttribute(k_qkv, cudaFuncAttributeMaxDynamicSharedMemorySize, MIDB_SMEM);
  cudaFuncSetAttribute(k_proj, cudaFuncAttributeMaxDynamicSharedMemorySize, MIDB_SMEM);
  cudaFuncSetAttribute(k_ffn1, cudaFuncAttributeMaxDynamicSharedMemorySize, FFN1_SMEM);
  cudaFuncSetAttribute(k_ffn2, cudaFuncAttributeMaxDynamicSharedMemorySize, FFN2_SMEM);

  float *p_st1, *p_f2p, *p_st2;
  cudaGetSymbolAddress((void**)&p_st1, g_st1);
  cudaGetSymbolAddress((void**)&p_f2p, g_f2p);
  cudaGetSymbolAddress((void**)&p_st2, g_st2);

  k_assign_pool<<<dim3(KAB, BB), 512, smem_ka>>>(x, sq_w, sq_b);
  k_reduce_st<<<64, 256>>>();
  k_gate<<<dim3(8, BB), 512, MIDB_SMEM>>>(eid_gw, eid_gb, eid_state);
  k_qkv<<<dim3(24, BB), 512, MIDB_SMEM>>>(in_w, in_b);
  k_attn<<<32, 1024>>>();
  k_proj<<<dim3(8, BB), 512, MIDB_SMEM>>>(out_w, out_b);
  k_ffn1<<<dim3(32, BB), 512, FFN1_SMEM>>>(f1_w, f1_b, n1_g, n1_b);
  k_ffn2<<<dim3(8, BB, 4), 512, FFN2_SMEM>>>(f2_w, f2_b);
  k_ln<<<64, 256>>>(p_st1, p_f2p, 4, n2_g, n2_b, p_st2);
  k_decode<<<dim3(256, BB), 256, smem_kc>>>(x, out);
}